// round 1
// baseline (speedup 1.0000x reference)
#include <cuda_runtime.h>
#include <math.h>
#include <float.h>

// Problem constants (fixed by reference setup_inputs)
#define DIM   1024
#define HS    128
#define NKV   2
#define T_SEQ 2048
#define BT_MAX 8192   // B*T = 4*2048

// ---------------- scratch (static device allocations; no cudaMalloc) -------
__device__ float g_qkv [BT_MAX * 512];   // [BT, 512] : q(h0)128 | q(h1)128 | k128 | v128
__device__ float g_attn[BT_MAX * 256];   // [BT, 256] : attention output, heads concat
__device__ float g_wcat[512 * DIM];      // concat(Wq0,Wq1,Wk,Wv) rows x 1024

// ---------------------------------------------------------------------------
// Weight concat: Wcat rows 0..255 = Wq (2*128 rows), 256..383 = Wk, 384..511 = Wv
// ---------------------------------------------------------------------------
__global__ void concat_w_kernel(const float* __restrict__ Wq,
                                const float* __restrict__ Wk,
                                const float* __restrict__ Wv)
{
    int i = blockIdx.x * blockDim.x + threadIdx.x;       // float4 index
    const int TOT = 512 * DIM / 4;                       // 131072
    if (i >= TOT) return;
    int row = i >> 8;                                    // 256 float4 per 1024-float row
    float4 v;
    if (row < 256)       v = ((const float4*)Wq)[i];
    else if (row < 384)  v = ((const float4*)Wk)[i - 256 * 256];
    else                 v = ((const float4*)Wv)[i - 384 * 256];
    ((float4*)g_wcat)[i] = v;
}

// ---------------------------------------------------------------------------
// SGEMM NT: C[M,N] = A[M,K] * B[N,K]^T   (A,B row-major, K contiguous)
// 128x128 block, BK=16, 256 threads, 8x8 register tile.
// ---------------------------------------------------------------------------
#define GBM 128
#define GBN 128
#define GBK 16
#define GPAD 4

__global__ __launch_bounds__(256, 2)
void sgemm_nt_kernel(const float* __restrict__ A, const float* __restrict__ B,
                     float* __restrict__ C, int M, int N, int K, int ldc)
{
    __shared__ float As[GBK][GBM + GPAD];
    __shared__ float Bs[GBK][GBN + GPAD];

    const int tid = threadIdx.x;
    const int tx = tid & 15;
    const int ty = tid >> 4;
    const int m0 = blockIdx.x * GBM;
    const int n0 = blockIdx.y * GBN;

    float acc[8][8];
#pragma unroll
    for (int i = 0; i < 8; i++)
#pragma unroll
        for (int j = 0; j < 8; j++) acc[i][j] = 0.f;

    for (int k0 = 0; k0 < K; k0 += GBK) {
        // Load A/B tiles (128 rows x 16 k each), transposed into smem
#pragma unroll
        for (int ld = 0; ld < 2; ld++) {
            int v   = tid + ld * 256;        // 0..511
            int row = v >> 2;                // 0..127
            int kq  = (v & 3) << 2;          // 0,4,8,12
            float4 a = *(const float4*)(A + (size_t)(m0 + row) * K + k0 + kq);
            As[kq + 0][row] = a.x; As[kq + 1][row] = a.y;
            As[kq + 2][row] = a.z; As[kq + 3][row] = a.w;
            float4 b = *(const float4*)(B + (size_t)(n0 + row) * K + k0 + kq);
            Bs[kq + 0][row] = b.x; Bs[kq + 1][row] = b.y;
            Bs[kq + 2][row] = b.z; Bs[kq + 3][row] = b.w;
        }
        __syncthreads();

#pragma unroll
        for (int kk = 0; kk < GBK; kk++) {
            float a[8], b[8];
            *(float4*)(a)     = *(const float4*)&As[kk][ty * 8];
            *(float4*)(a + 4) = *(const float4*)&As[kk][ty * 8 + 4];
            *(float4*)(b)     = *(const float4*)&Bs[kk][tx * 8];
            *(float4*)(b + 4) = *(const float4*)&Bs[kk][tx * 8 + 4];
#pragma unroll
            for (int i = 0; i < 8; i++)
#pragma unroll
                for (int j = 0; j < 8; j++)
                    acc[i][j] += a[i] * b[j];
        }
        __syncthreads();
    }

#pragma unroll
    for (int i = 0; i < 8; i++) {
        float* cp = C + (size_t)(m0 + ty * 8 + i) * ldc + n0 + tx * 8;
        *(float4*)(cp)     = make_float4(acc[i][0], acc[i][1], acc[i][2], acc[i][3]);
        *(float4*)(cp + 4) = make_float4(acc[i][4], acc[i][5], acc[i][6], acc[i][7]);
    }
}

// ---------------------------------------------------------------------------
// RoPE in-place on g_qkv: q (cols 0..255, two heads of 128) and k (cols 256..383).
// pair i (elements 2i,2i+1 within a 128-dim head): theta_i = 10000^(-i/32)
// ---------------------------------------------------------------------------
__global__ void rope_kernel(float* __restrict__ qkv, int BT, int T)
{
    int idx = blockIdx.x * blockDim.x + threadIdx.x;
    const int PAIRS = 192;                 // 128 q pairs (2 heads) + 64 k pairs
    int row = idx / PAIRS;
    if (row >= BT) return;
    int p = idx - row * PAIRS;
    int t = row % T;

    int i, col;
    if (p < 128) { int h = p >> 6; i = p & 63; col = h * 128 + 2 * i; }
    else         { i = p - 128;               col = 256 + 2 * i;      }

    float theta = powf(10000.0f, -(float)i / 32.0f);
    float ang = (float)t * theta;
    float s, c;
    sincosf(ang, &s, &c);

    float* ptr = qkv + (size_t)row * 512 + col;
    float x0 = ptr[0], x1 = ptr[1];
    ptr[0] = x0 * c - x1 * s;
    ptr[1] = x1 * c + x0 * s;
}

// ---------------------------------------------------------------------------
// Flash attention, fp32. BLOCK_M=64 queries, BLOCK_N=64 keys, HS=128.
// 256 threads (16x16). Score stage: 4x4 register tile. PV stage: 4 rows x 8 cols.
// Q pre-scaled by HS^-0.5 on smem load. Causal mask on diagonal tile.
// ---------------------------------------------------------------------------
#define ABM 64
#define ABN 64

__global__ __launch_bounds__(256, 2)
void attn_kernel(const float* __restrict__ qkv, float* __restrict__ O, int T)
{
    extern __shared__ float sm[];
    float* Qs = sm;                  // 64*128
    float* Ks = sm + 64 * 128;       // 64*128
    float* Vs = sm + 2 * 64 * 128;   // 64*128
    float* Ps = sm + 3 * 64 * 128;   // 64*64

    const int bh = blockIdx.y;
    const int b  = bh >> 1;
    const int h  = bh & 1;
    const int mt = blockIdx.x;
    const int m0 = mt * ABM;

    const int tid = threadIdx.x;
    const int tx = tid & 15;
    const int ty = tid >> 4;

    const float scale = 0.08838834764831845f;  // 128^-0.5

    const float* qbase = qkv + (size_t)b * T * 512 + h * 128;
    const float* kbase = qkv + (size_t)b * T * 512 + 256;
    const float* vbase = qkv + (size_t)b * T * 512 + 384;

    // Load + pre-scale Q tile
    for (int v = tid; v < 64 * 32; v += 256) {
        int row = v >> 5;
        int c4  = (v & 31) << 2;
        float4 q = *(const float4*)(qbase + (size_t)(m0 + row) * 512 + c4);
        q.x *= scale; q.y *= scale; q.z *= scale; q.w *= scale;
        *(float4*)(Qs + row * 128 + c4) = q;
    }

    float m_i[4], l_i[4], acc[4][8];
#pragma unroll
    for (int r = 0; r < 4; r++) {
        m_i[r] = -1e30f; l_i[r] = 0.f;
#pragma unroll
        for (int c = 0; c < 8; c++) acc[r][c] = 0.f;
    }

    for (int j = 0; j <= mt; j++) {
        const int n0v = j * ABN;
        __syncthreads();   // previous PV done reading Ks/Vs/Ps
        for (int v = tid; v < 64 * 32; v += 256) {
            int row = v >> 5;
            int c4  = (v & 31) << 2;
            *(float4*)(Ks + row * 128 + c4) =
                *(const float4*)(kbase + (size_t)(n0v + row) * 512 + c4);
            *(float4*)(Vs + row * 128 + c4) =
                *(const float4*)(vbase + (size_t)(n0v + row) * 512 + c4);
        }
        __syncthreads();

        // S = Q K^T (this thread: rows ty*4+r, cols tx*4+c)
        float s[4][4];
#pragma unroll
        for (int r = 0; r < 4; r++)
#pragma unroll
            for (int c = 0; c < 4; c++) s[r][c] = 0.f;

        for (int k4 = 0; k4 < 128; k4 += 4) {
            float4 qr[4], kc[4];
#pragma unroll
            for (int r = 0; r < 4; r++)
                qr[r] = *(const float4*)(Qs + (ty * 4 + r) * 128 + k4);
#pragma unroll
            for (int c = 0; c < 4; c++)
                kc[c] = *(const float4*)(Ks + (tx * 4 + c) * 128 + k4);
#pragma unroll
            for (int r = 0; r < 4; r++)
#pragma unroll
                for (int c = 0; c < 4; c++) {
                    s[r][c] += qr[r].x * kc[c].x;
                    s[r][c] += qr[r].y * kc[c].y;
                    s[r][c] += qr[r].z * kc[c].z;
                    s[r][c] += qr[r].w * kc[c].w;
                }
        }

        // Causal mask (only the diagonal tile needs it)
        if (j == mt) {
#pragma unroll
            for (int r = 0; r < 4; r++)
#pragma unroll
                for (int c = 0; c < 4; c++)
                    if (n0v + tx * 4 + c > m0 + ty * 4 + r) s[r][c] = -1e30f;
        }

        // Online softmax update
#pragma unroll
        for (int r = 0; r < 4; r++) {
            float mx = fmaxf(fmaxf(s[r][0], s[r][1]), fmaxf(s[r][2], s[r][3]));
#pragma unroll
            for (int o = 8; o >= 1; o >>= 1)
                mx = fmaxf(mx, __shfl_xor_sync(0xffffffffu, mx, o));
            float mnew = fmaxf(m_i[r], mx);
            float corr = __expf(m_i[r] - mnew);
            m_i[r] = mnew;
            float rs = 0.f;
#pragma unroll
            for (int c = 0; c < 4; c++) {
                float p = __expf(s[r][c] - mnew);
                s[r][c] = p;
                rs += p;
            }
#pragma unroll
            for (int o = 8; o >= 1; o >>= 1)
                rs += __shfl_xor_sync(0xffffffffu, rs, o);
            l_i[r] = l_i[r] * corr + rs;
#pragma unroll
            for (int c = 0; c < 8; c++) acc[r][c] *= corr;
            *(float4*)(Ps + (ty * 4 + r) * 64 + tx * 4) =
                make_float4(s[r][0], s[r][1], s[r][2], s[r][3]);
        }
        __syncthreads();

        // O += P V  (this thread: rows ty*4+r, cols tx*8..tx*8+7)
        for (int n = 0; n < 64; n++) {
            float4 v0 = *(const float4*)(Vs + n * 128 + tx * 8);
            float4 v1 = *(const float4*)(Vs + n * 128 + tx * 8 + 4);
#pragma unroll
            for (int r = 0; r < 4; r++) {
                float p = Ps[(ty * 4 + r) * 64 + n];
                acc[r][0] += p * v0.x; acc[r][1] += p * v0.y;
                acc[r][2] += p * v0.z; acc[r][3] += p * v0.w;
                acc[r][4] += p * v1.x; acc[r][5] += p * v1.y;
                acc[r][6] += p * v1.z; acc[r][7] += p * v1.w;
            }
        }
    }

    // Epilogue: normalize and store into [BT, 256] concat-head layout
#pragma unroll
    for (int r = 0; r < 4; r++) {
        float inv = 1.0f / l_i[r];
        float* op = O + ((size_t)b * T + m0 + ty * 4 + r) * 256 + h * 128 + tx * 8;
        *(float4*)(op) = make_float4(acc[r][0] * inv, acc[r][1] * inv,
                                     acc[r][2] * inv, acc[r][3] * inv);
        *(float4*)(op + 4) = make_float4(acc[r][4] * inv, acc[r][5] * inv,
                                         acc[r][6] * inv, acc[r][7] * inv);
    }
}

// ---------------------------------------------------------------------------
extern "C" void kernel_launch(void* const* d_in, const int* in_sizes, int n_in,
                              void* d_out, int out_size)
{
    const float* x  = (const float*)d_in[0];  // [B,T,1024]
    const float* Wq = (const float*)d_in[1];  // [2,128,1024]
    const float* Wk = (const float*)d_in[2];  // [128,1024]
    const float* Wv = (const float*)d_in[3];  // [128,1024]
    const float* Wo = (const float*)d_in[4];  // [1024,256]

    const int BT = in_sizes[0] / DIM;  // 8192
    const int T  = T_SEQ;
    const int B  = BT / T;

    float *qkv, *attn, *wcat;
    cudaGetSymbolAddress((void**)&qkv,  g_qkv);
    cudaGetSymbolAddress((void**)&attn, g_attn);
    cudaGetSymbolAddress((void**)&wcat, g_wcat);

    // 1) concat weights
    {
        int tot = 512 * DIM / 4;
        concat_w_kernel<<<(tot + 255) / 256, 256>>>(Wq, Wk, Wv);
    }

    // 2) fused QKV projection: [BT,512] = x[BT,1024] * Wcat[512,1024]^T
    {
        dim3 grid(BT / GBM, 512 / GBN);
        sgemm_nt_kernel<<<grid, 256>>>(x, wcat, qkv, BT, 512, DIM, 512);
    }

    // 3) RoPE on q (both heads) and k
    {
        long total = (long)BT * 192;
        rope_kernel<<<(int)((total + 255) / 256), 256>>>(qkv, BT, T);
    }

    // 4) flash attention
    {
        size_t smem = (3 * 64 * 128 + 64 * 64) * sizeof(float);  // 112 KB
        cudaFuncSetAttribute(attn_kernel,
                             cudaFuncAttributeMaxDynamicSharedMemorySize,
                             (int)smem);
        dim3 grid(T / ABM, B * NKV);
        attn_kernel<<<grid, 256, smem>>>(qkv, attn, T);
    }

    // 5) output projection: out[BT,1024] = attn[BT,256] * Wo[1024,256]^T
    {
        dim3 grid(BT / GBM, DIM / GBN);
        sgemm_nt_kernel<<<grid, 256>>>(attn, Wo, (float*)d_out,
                                       BT, DIM, 256, DIM);
    }
}

// round 3
// speedup vs baseline: 5.8086x; 5.8086x over previous
#include <cuda_runtime.h>
#include <cuda_bf16.h>
#include <math.h>
#include <float.h>
#include <stdint.h>

// Problem constants (fixed by reference setup_inputs)
#define DIM   1024
#define HS    128
#define NKV   2
#define T_SEQ 2048
#define BT_MAX 8192   // B*T = 4*2048

// ---------------- scratch (static device allocations; no cudaMalloc) -------
__device__ float g_qkv [BT_MAX * 512];   // [BT, 512] : q(h0)128 | q(h1)128 | k128 | v128
__device__ float g_attn[BT_MAX * 256];   // [BT, 256] : attention output, heads concat
__device__ float g_wcat[512 * DIM];      // concat(Wq0,Wq1,Wk,Wv) rows x 1024

// ============================================================================
// mma.sync / ldmatrix helpers (base sm_103-compatible HMMA path)
// ============================================================================
__device__ __forceinline__ uint32_t smem_u32(const void* p) {
    uint32_t a;
    asm("{ .reg .u64 t; cvta.to.shared.u64 t, %1; cvt.u32.u64 %0, t; }"
        : "=r"(a) : "l"(p));
    return a;
}

__device__ __forceinline__ void mma_bf16(float c[4], const uint32_t a[4],
                                         const uint32_t b[2]) {
    asm volatile(
        "mma.sync.aligned.m16n8k16.row.col.f32.bf16.bf16.f32 "
        "{%0,%1,%2,%3}, {%4,%5,%6,%7}, {%8,%9}, {%0,%1,%2,%3};"
        : "+f"(c[0]), "+f"(c[1]), "+f"(c[2]), "+f"(c[3])
        : "r"(a[0]), "r"(a[1]), "r"(a[2]), "r"(a[3]), "r"(b[0]), "r"(b[1]));
}

__device__ __forceinline__ void ldsm_x4(uint32_t r[4], uint32_t addr) {
    asm volatile("ldmatrix.sync.aligned.m8n8.x4.shared.b16 {%0,%1,%2,%3}, [%4];"
                 : "=r"(r[0]), "=r"(r[1]), "=r"(r[2]), "=r"(r[3]) : "r"(addr));
}
__device__ __forceinline__ void ldsm_x4_t(uint32_t r[4], uint32_t addr) {
    asm volatile("ldmatrix.sync.aligned.m8n8.x4.trans.shared.b16 {%0,%1,%2,%3}, [%4];"
                 : "=r"(r[0]), "=r"(r[1]), "=r"(r[2]), "=r"(r[3]) : "r"(addr));
}

// Split float4 into bf16 hi/lo pairs (packed bf16x2 words)
__device__ __forceinline__ void split_f4(float4 v, uint2& hi, uint2& lo) {
    __nv_bfloat162 h0 = __float22bfloat162_rn(make_float2(v.x, v.y));
    __nv_bfloat162 h1 = __float22bfloat162_rn(make_float2(v.z, v.w));
    __nv_bfloat162 l0 = __float22bfloat162_rn(
        make_float2(v.x - __low2float(h0), v.y - __high2float(h0)));
    __nv_bfloat162 l1 = __float22bfloat162_rn(
        make_float2(v.z - __low2float(h1), v.w - __high2float(h1)));
    hi.x = *(uint32_t*)&h0; hi.y = *(uint32_t*)&h1;
    lo.x = *(uint32_t*)&l0; lo.y = *(uint32_t*)&l1;
}

// Swizzled byte offsets for bf16 tiles (conflict-free ldmatrix)
// 256B rows (128 bf16 cols), 16 chunks of 16B, chunk ^= row&7
__device__ __forceinline__ uint32_t sw256(int row, int col) {
    int chunk = col >> 3;
    return (uint32_t)(row * 256 + (((chunk ^ (row & 7)) << 4) | ((col & 7) << 1)));
}
// 128B rows (64 bf16 cols), 8 chunks of 16B
__device__ __forceinline__ uint32_t sw128o(int row, int col) {
    int chunk = col >> 3;
    return (uint32_t)(row * 128 + (((chunk ^ (row & 7)) << 4) | ((col & 7) << 1)));
}

// ---------------------------------------------------------------------------
// Weight concat
// ---------------------------------------------------------------------------
__global__ void concat_w_kernel(const float* __restrict__ Wq,
                                const float* __restrict__ Wk,
                                const float* __restrict__ Wv)
{
    int i = blockIdx.x * blockDim.x + threadIdx.x;
    const int TOT = 512 * DIM / 4;
    if (i >= TOT) return;
    int row = i >> 8;
    float4 v;
    if (row < 256)       v = ((const float4*)Wq)[i];
    else if (row < 384)  v = ((const float4*)Wk)[i - 256 * 256];
    else                 v = ((const float4*)Wv)[i - 384 * 256];
    ((float4*)g_wcat)[i] = v;
}

// ---------------------------------------------------------------------------
// HMMA GEMM NT (3xBF16 compensated): C[M,N] = A[M,K] * B[N,K]^T
// 128x128 CTA tile, BK=32, 256 threads (8 warps, 32x64 warp tiles),
// double-buffered smem. Rows padded to 80B for conflict-free ldmatrix.
// smem per buffer: Ah(10240) Al(10240) Bh(10240) Bl(10240) = 40960; x2 = 81920
// ---------------------------------------------------------------------------
#define GEMM_SMEM 81920

__global__ __launch_bounds__(256)
void gemm_mma_kernel(const float* __restrict__ A, const float* __restrict__ B,
                     float* __restrict__ C, int M, int N, int K, int ldc)
{
    extern __shared__ __align__(16) char smp[];
    const uint32_t sb = smem_u32(smp);

    const int tid = threadIdx.x;
    const int wid = tid >> 5;
    const int lane = tid & 31;
    const int m0 = blockIdx.x * 128;
    const int n0 = blockIdx.y * 128;
    const int wm = wid & 3;      // 4 warps over M (32 rows each)
    const int wn = wid >> 2;     // 2 warps over N (64 cols each)

    float acc[2][8][4];
#pragma unroll
    for (int mf = 0; mf < 2; mf++)
#pragma unroll
        for (int nf = 0; nf < 8; nf++)
#pragma unroll
            for (int q = 0; q < 4; q++) acc[mf][nf][q] = 0.f;

    const int KT = K >> 5;
    float4 ar[4], br[4];

    // ---- stage 0 ----
    {
        const float* Ab = A + (size_t)m0 * K;
        const float* Bb = B + (size_t)n0 * K;
#pragma unroll
        for (int i = 0; i < 4; i++) {
            int u = tid + i * 256, row = u >> 3, g = u & 7;
            ar[i] = *(const float4*)(Ab + (size_t)row * K + g * 4);
            br[i] = *(const float4*)(Bb + (size_t)row * K + g * 4);
        }
#pragma unroll
        for (int i = 0; i < 4; i++) {
            int u = tid + i * 256, row = u >> 3, g = u & 7;
            uint32_t off = row * 80 + (g >> 1) * 16 + (g & 1) * 8;
            uint2 hi, lo;
            split_f4(ar[i], hi, lo);
            *(uint2*)(smp + off)         = hi;
            *(uint2*)(smp + 10240 + off) = lo;
            split_f4(br[i], hi, lo);
            *(uint2*)(smp + 20480 + off) = hi;
            *(uint2*)(smp + 30720 + off) = lo;
        }
    }
    __syncthreads();

    for (int kt = 0; kt < KT; kt++) {
        const int buf = kt & 1;
        // prefetch next tile into registers
        if (kt + 1 < KT) {
            const float* Ab = A + (size_t)m0 * K + (kt + 1) * 32;
            const float* Bb = B + (size_t)n0 * K + (kt + 1) * 32;
#pragma unroll
            for (int i = 0; i < 4; i++) {
                int u = tid + i * 256, row = u >> 3, g = u & 7;
                ar[i] = *(const float4*)(Ab + (size_t)row * K + g * 4);
                br[i] = *(const float4*)(Bb + (size_t)row * K + g * 4);
            }
        }

        // compute current buffer
        const uint32_t ab = sb + buf * 40960;
        const uint32_t bb = ab + 20480;
#pragma unroll
        for (int ks = 0; ks < 2; ks++) {
            uint32_t ah[2][4], al[2][4];
#pragma unroll
            for (int mf = 0; mf < 2; mf++) {
                int row = wm * 32 + mf * 16 + (lane & 15);
                int chunk = ks * 2 + (lane >> 4);
                uint32_t ad = ab + row * 80 + chunk * 16;
                ldsm_x4(ah[mf], ad);
                ldsm_x4(al[mf], ad + 10240);
            }
            uint32_t bh[8][2], bl[8][2];
#pragma unroll
            for (int np = 0; np < 4; np++) {
                int row = wn * 64 + np * 16 + ((lane >> 4) << 3) + (lane & 7);
                int chunk = ks * 2 + ((lane >> 3) & 1);
                uint32_t bd = bb + row * 80 + chunk * 16;
                uint32_t t[4];
                ldsm_x4(t, bd);
                bh[np * 2][0] = t[0]; bh[np * 2][1] = t[1];
                bh[np * 2 + 1][0] = t[2]; bh[np * 2 + 1][1] = t[3];
                ldsm_x4(t, bd + 10240);
                bl[np * 2][0] = t[0]; bl[np * 2][1] = t[1];
                bl[np * 2 + 1][0] = t[2]; bl[np * 2 + 1][1] = t[3];
            }
#pragma unroll
            for (int mf = 0; mf < 2; mf++)
#pragma unroll
                for (int nf = 0; nf < 8; nf++) {
                    mma_bf16(acc[mf][nf], ah[mf], bh[nf]);
                    mma_bf16(acc[mf][nf], ah[mf], bl[nf]);
                    mma_bf16(acc[mf][nf], al[mf], bh[nf]);
                }
        }

        // store prefetched tile to the other buffer
        if (kt + 1 < KT) {
            char* dst = smp + ((kt + 1) & 1) * 40960;
#pragma unroll
            for (int i = 0; i < 4; i++) {
                int u = tid + i * 256, row = u >> 3, g = u & 7;
                uint32_t off = row * 80 + (g >> 1) * 16 + (g & 1) * 8;
                uint2 hi, lo;
                split_f4(ar[i], hi, lo);
                *(uint2*)(dst + off)         = hi;
                *(uint2*)(dst + 10240 + off) = lo;
                split_f4(br[i], hi, lo);
                *(uint2*)(dst + 20480 + off) = hi;
                *(uint2*)(dst + 30720 + off) = lo;
            }
        }
        __syncthreads();
    }

    // epilogue
#pragma unroll
    for (int mf = 0; mf < 2; mf++)
#pragma unroll
        for (int nf = 0; nf < 8; nf++) {
            int row = m0 + wm * 32 + mf * 16 + (lane >> 2);
            int col = n0 + wn * 64 + nf * 8 + (lane & 3) * 2;
            *(float2*)(C + (size_t)row * ldc + col) =
                make_float2(acc[mf][nf][0], acc[mf][nf][1]);
            *(float2*)(C + (size_t)(row + 8) * ldc + col) =
                make_float2(acc[mf][nf][2], acc[mf][nf][3]);
        }
}

// ---------------------------------------------------------------------------
// RoPE in-place on g_qkv (fp32)
// ---------------------------------------------------------------------------
__global__ void rope_kernel(float* __restrict__ qkv, int BT, int T)
{
    int idx = blockIdx.x * blockDim.x + threadIdx.x;
    const int PAIRS = 192;
    int row = idx / PAIRS;
    if (row >= BT) return;
    int p = idx - row * PAIRS;
    int t = row % T;

    int i, col;
    if (p < 128) { int h = p >> 6; i = p & 63; col = h * 128 + 2 * i; }
    else         { i = p - 128;               col = 256 + 2 * i;      }

    float theta = powf(10000.0f, -(float)i / 32.0f);
    float ang = (float)t * theta;
    float s, c;
    sincosf(ang, &s, &c);

    float* ptr = qkv + (size_t)row * 512 + col;
    float x0 = ptr[0], x1 = ptr[1];
    ptr[0] = x0 * c - x1 * s;
    ptr[1] = x1 * c + x0 * s;
}

// ---------------------------------------------------------------------------
// Flash attention, HMMA 3xBF16. 64 q-rows per CTA, 64 kv per iter, HS=128.
// 256 threads (8 warps). S-phase warp tile 32x16; PV-phase warp tile 32x32.
// smem offsets (bytes):
//   QH 0, QL 16384, KH 32768, KL 49152, VH 65536, VL 81920   (bf16, sw256)
//   SS 98304 (fp32 64 x 68 padded)                            (17408)
//   PH 115712, PL 123904 (bf16, sw128o)                       (8192 ea)
//   MM 132096, LL 132352, CC 132608 (fp32[64] each)
#define ATT_SMEM 132864
#define OFF_QH 0
#define OFF_QL 16384
#define OFF_KH 32768
#define OFF_KL 49152
#define OFF_VH 65536
#define OFF_VL 81920
#define OFF_SS 98304
#define OFF_PH 115712
#define OFF_PL 123904
#define OFF_MM 132096
#define OFF_LL 132352
#define OFF_CC 132608

__global__ __launch_bounds__(256)
void attn_mma_kernel(const float* __restrict__ qkv, float* __restrict__ O, int T)
{
    extern __shared__ __align__(16) char smp[];
    const uint32_t sb = smem_u32(smp);

    const int tid = threadIdx.x;
    const int wid = tid >> 5;
    const int lane = tid & 31;
    const int bh = blockIdx.y;
    const int b  = bh >> 1;
    const int h  = bh & 1;
    const int mt = gridDim.x - 1 - blockIdx.x;   // heavy tiles scheduled first
    const int m0 = mt * 64;
    const int wm = wid & 1;     // 2 warps over 64 q rows (32 each)
    const int wn = wid >> 1;    // 4 warps over cols

    const float scale = 0.08838834764831845f;  // 128^-0.5

    const float* qb = qkv + (size_t)b * T * 512 + h * 128;
    const float* kb = qkv + (size_t)b * T * 512 + 256;
    const float* vb = qkv + (size_t)b * T * 512 + 384;

    float* mArr = (float*)(smp + OFF_MM);
    float* lArr = (float*)(smp + OFF_LL);
    float* cArr = (float*)(smp + OFF_CC);

    // ---- load + split Q (pre-scaled) ----
#pragma unroll
    for (int i = 0; i < 8; i++) {
        int u = tid + i * 256;       // float4 units: 64 rows * 32 groups
        int row = u >> 5, g = u & 31;
        float4 v = *(const float4*)(qb + (size_t)(m0 + row) * 512 + g * 4);
        v.x *= scale; v.y *= scale; v.z *= scale; v.w *= scale;
        uint2 hi, lo;
        split_f4(v, hi, lo);
        uint32_t off = sw256(row, g * 4);
        *(uint2*)(smp + OFF_QH + off) = hi;
        *(uint2*)(smp + OFF_QL + off) = lo;
    }
    if (tid < 64) { mArr[tid] = -1e30f; lArr[tid] = 0.f; }

    float acc[2][4][4];
#pragma unroll
    for (int mf = 0; mf < 2; mf++)
#pragma unroll
        for (int nf = 0; nf < 4; nf++)
#pragma unroll
            for (int q = 0; q < 4; q++) acc[mf][nf][q] = 0.f;

    __syncthreads();

    for (int j = 0; j <= mt; j++) {
        const int n0v = j * 64;

        // ---- load + split K, V ----
#pragma unroll
        for (int i = 0; i < 8; i++) {
            int u = tid + i * 256;
            int row = u >> 5, g = u & 31;
            uint32_t off = sw256(row, g * 4);
            float4 kv = *(const float4*)(kb + (size_t)(n0v + row) * 512 + g * 4);
            uint2 hi, lo;
            split_f4(kv, hi, lo);
            *(uint2*)(smp + OFF_KH + off) = hi;
            *(uint2*)(smp + OFF_KL + off) = lo;
            float4 vv = *(const float4*)(vb + (size_t)(n0v + row) * 512 + g * 4);
            split_f4(vv, hi, lo);
            *(uint2*)(smp + OFF_VH + off) = hi;
            *(uint2*)(smp + OFF_VL + off) = lo;
        }
        __syncthreads();

        // ---- S = Q K^T  (warp: rows wm*32..+31, cols wn*16..+15) ----
        float sacc[2][2][4];
#pragma unroll
        for (int mf = 0; mf < 2; mf++)
#pragma unroll
            for (int nf = 0; nf < 2; nf++)
#pragma unroll
                for (int q = 0; q < 4; q++) sacc[mf][nf][q] = 0.f;

#pragma unroll
        for (int ks = 0; ks < 8; ks++) {
            uint32_t qh[2][4], ql[2][4];
#pragma unroll
            for (int mf = 0; mf < 2; mf++) {
                int row = wm * 32 + mf * 16 + (lane & 15);
                int chunk = ks * 2 + (lane >> 4);
                uint32_t off = sw256(row, chunk * 8);
                ldsm_x4(qh[mf], sb + OFF_QH + off);
                ldsm_x4(ql[mf], sb + OFF_QL + off);
            }
            uint32_t kh[2][2], kl[2][2];
            {
                int row = wn * 16 + ((lane >> 4) << 3) + (lane & 7);
                int chunk = ks * 2 + ((lane >> 3) & 1);
                uint32_t off = sw256(row, chunk * 8);
                uint32_t t[4];
                ldsm_x4(t, sb + OFF_KH + off);
                kh[0][0] = t[0]; kh[0][1] = t[1]; kh[1][0] = t[2]; kh[1][1] = t[3];
                ldsm_x4(t, sb + OFF_KL + off);
                kl[0][0] = t[0]; kl[0][1] = t[1]; kl[1][0] = t[2]; kl[1][1] = t[3];
            }
#pragma unroll
            for (int mf = 0; mf < 2; mf++)
#pragma unroll
                for (int nf = 0; nf < 2; nf++) {
                    mma_bf16(sacc[mf][nf], qh[mf], kh[nf]);
                    mma_bf16(sacc[mf][nf], qh[mf], kl[nf]);
                    mma_bf16(sacc[mf][nf], ql[mf], kh[nf]);
                }
        }

        // write S to smem (fp32, 68-float row stride)
        float* S = (float*)(smp + OFF_SS);
#pragma unroll
        for (int mf = 0; mf < 2; mf++)
#pragma unroll
            for (int nf = 0; nf < 2; nf++) {
                int row = wm * 32 + mf * 16 + (lane >> 2);
                int col = wn * 16 + nf * 8 + (lane & 3) * 2;
                *(float2*)(S + row * 68 + col) =
                    make_float2(sacc[mf][nf][0], sacc[mf][nf][1]);
                *(float2*)(S + (row + 8) * 68 + col) =
                    make_float2(sacc[mf][nf][2], sacc[mf][nf][3]);
            }
        __syncthreads();

        // ---- softmax (4 threads per row, 16 cols each) ----
        {
            int r = tid >> 2;
            int cg = (tid & 3) * 16;
            float* srow = S + r * 68 + cg;
            float vals[16];
#pragma unroll
            for (int q = 0; q < 4; q++) {
                float4 v = *(float4*)(srow + q * 4);
                vals[q * 4 + 0] = v.x; vals[q * 4 + 1] = v.y;
                vals[q * 4 + 2] = v.z; vals[q * 4 + 3] = v.w;
            }
            if (j == mt) {
#pragma unroll
                for (int q = 0; q < 16; q++)
                    if (n0v + cg + q > m0 + r) vals[q] = -1e30f;
            }
            float mx = -1e30f;
#pragma unroll
            for (int q = 0; q < 16; q++) mx = fmaxf(mx, vals[q]);
            mx = fmaxf(mx, __shfl_xor_sync(0xffffffffu, mx, 1));
            mx = fmaxf(mx, __shfl_xor_sync(0xffffffffu, mx, 2));
            float mold = mArr[r];
            float mnew = fmaxf(mold, mx);
            float corr = __expf(mold - mnew);
            float sum = 0.f;
#pragma unroll
            for (int q = 0; q < 16; q++) {
                vals[q] = __expf(vals[q] - mnew);
                sum += vals[q];
            }
            sum += __shfl_xor_sync(0xffffffffu, sum, 1);
            sum += __shfl_xor_sync(0xffffffffu, sum, 2);
            __syncthreads();   // everyone done reading mArr/lArr before update
            if ((tid & 3) == 0) {
                lArr[r] = lArr[r] * corr + sum;
                mArr[r] = mnew;
                cArr[r] = corr;
            }
            // write P hi/lo (bf16, sw128o)
#pragma unroll
            for (int q = 0; q < 4; q++) {
                int col = cg + q * 4;
                float4 v = make_float4(vals[q * 4 + 0], vals[q * 4 + 1],
                                       vals[q * 4 + 2], vals[q * 4 + 3]);
                uint2 hi, lo;
                split_f4(v, hi, lo);
                uint32_t off = sw128o(r, col);
                *(uint2*)(smp + OFF_PH + off) = hi;
                *(uint2*)(smp + OFF_PL + off) = lo;
            }
        }
        __syncthreads();

        // ---- rescale O accumulator ----
#pragma unroll
        for (int mf = 0; mf < 2; mf++) {
            int r0 = wm * 32 + mf * 16 + (lane >> 2);
            float c0 = cArr[r0], c1 = cArr[r0 + 8];
#pragma unroll
            for (int nf = 0; nf < 4; nf++) {
                acc[mf][nf][0] *= c0; acc[mf][nf][1] *= c0;
                acc[mf][nf][2] *= c1; acc[mf][nf][3] *= c1;
            }
        }

        // ---- O += P V  (warp: rows wm*32..+31, cols wn*32..+31) ----
#pragma unroll
        for (int ks = 0; ks < 4; ks++) {
            uint32_t ph[2][4], pl[2][4];
#pragma unroll
            for (int mf = 0; mf < 2; mf++) {
                int row = wm * 32 + mf * 16 + (lane & 15);
                int chunk = ks * 2 + (lane >> 4);
                uint32_t off = sw128o(row, chunk * 8);
                ldsm_x4(ph[mf], sb + OFF_PH + off);
                ldsm_x4(pl[mf], sb + OFF_PL + off);
            }
            uint32_t vh[4][2], vl[4][2];
#pragma unroll
            for (int np = 0; np < 2; np++) {
                int row = ks * 16 + (lane & 15);
                int chunk = ((wn * 32 + np * 16) >> 3) + (lane >> 4);
                uint32_t off = sw256(row, chunk * 8);
                uint32_t t[4];
                ldsm_x4_t(t, sb + OFF_VH + off);
                vh[np * 2][0] = t[0]; vh[np * 2][1] = t[1];
                vh[np * 2 + 1][0] = t[2]; vh[np * 2 + 1][1] = t[3];
                ldsm_x4_t(t, sb + OFF_VL + off);
                vl[np * 2][0] = t[0]; vl[np * 2][1] = t[1];
                vl[np * 2 + 1][0] = t[2]; vl[np * 2 + 1][1] = t[3];
            }
#pragma unroll
            for (int mf = 0; mf < 2; mf++)
#pragma unroll
                for (int nf = 0; nf < 4; nf++) {
                    mma_bf16(acc[mf][nf], ph[mf], vh[nf]);
                    mma_bf16(acc[mf][nf], ph[mf], vl[nf]);
                    mma_bf16(acc[mf][nf], pl[mf], vh[nf]);
                }
        }
        __syncthreads();
    }

    // ---- epilogue: normalize + store ----
#pragma unroll
    for (int mf = 0; mf < 2; mf++) {
        int rloc = wm * 32 + mf * 16 + (lane >> 2);
        float inv0 = 1.0f / lArr[rloc];
        float inv1 = 1.0f / lArr[rloc + 8];
#pragma unroll
        for (int nf = 0; nf < 4; nf++) {
            int col = h * 128 + wn * 32 + nf * 8 + (lane & 3) * 2;
            size_t r0 = (size_t)b * T + m0 + rloc;
            *(float2*)(O + r0 * 256 + col) =
                make_float2(acc[mf][nf][0] * inv0, acc[mf][nf][1] * inv0);
            *(float2*)(O + (r0 + 8) * 256 + col) =
                make_float2(acc[mf][nf][2] * inv1, acc[mf][nf][3] * inv1);
        }
    }
}

// ---------------------------------------------------------------------------
extern "C" void kernel_launch(void* const* d_in, const int* in_sizes, int n_in,
                              void* d_out, int out_size)
{
    const float* x  = (const float*)d_in[0];  // [B,T,1024]
    const float* Wq = (const float*)d_in[1];  // [2,128,1024]
    const float* Wk = (const float*)d_in[2];  // [128,1024]
    const float* Wv = (const float*)d_in[3];  // [128,1024]
    const float* Wo = (const float*)d_in[4];  // [1024,256]

    const int BT = in_sizes[0] / DIM;  // 8192
    const int T  = T_SEQ;
    const int B  = BT / T;

    float *qkv, *attn, *wcat;
    cudaGetSymbolAddress((void**)&qkv,  g_qkv);
    cudaGetSymbolAddress((void**)&attn, g_attn);
    cudaGetSymbolAddress((void**)&wcat, g_wcat);

    static int attr_done = 0;
    if (!attr_done) {
        cudaFuncSetAttribute(gemm_mma_kernel,
                             cudaFuncAttributeMaxDynamicSharedMemorySize,
                             GEMM_SMEM);
        cudaFuncSetAttribute(attn_mma_kernel,
                             cudaFuncAttributeMaxDynamicSharedMemorySize,
                             ATT_SMEM);
        attr_done = 1;
    }

    // 1) concat weights
    {
        int tot = 512 * DIM / 4;
        concat_w_kernel<<<(tot + 255) / 256, 256>>>(Wq, Wk, Wv);
    }

    // 2) fused QKV projection: qkv[BT,512] = x * Wcat^T
    {
        dim3 grid(BT / 128, 512 / 128);
        gemm_mma_kernel<<<grid, 256, GEMM_SMEM>>>(x, wcat, qkv, BT, 512, DIM, 512);
    }

    // 3) RoPE
    {
        long total = (long)BT * 192;
        rope_kernel<<<(int)((total + 255) / 256), 256>>>(qkv, BT, T);
    }

    // 4) flash attention (HMMA)
    {
        dim3 grid(T / 64, B * NKV);
        attn_mma_kernel<<<grid, 256, ATT_SMEM>>>(qkv, attn, T);
    }

    // 5) output projection: out[BT,1024] = attn * Wo^T
    {
        dim3 grid(BT / 128, DIM / 128);
        gemm_mma_kernel<<<grid, 256, GEMM_SMEM>>>(attn, Wo, (float*)d_out,
                                                  BT, DIM, 256, DIM);
    }
}

// round 4
// speedup vs baseline: 5.8571x; 1.0083x over previous
#include <cuda_runtime.h>
#include <cuda_bf16.h>
#include <math.h>
#include <float.h>
#include <stdint.h>

// Problem constants (fixed by reference setup_inputs)
#define DIM   1024
#define HS    128
#define NKV   2
#define T_SEQ 2048
#define BT_MAX 8192   // B*T = 4*2048

// ---------------- scratch (static device allocations; no cudaMalloc) -------
__device__ float g_qkv [BT_MAX * 512];   // [BT, 512] : q(h0)128 | q(h1)128 | k128 | v128
__device__ float g_attn[BT_MAX * 256];   // [BT, 256] : attention output, heads concat
__device__ float g_wcat[512 * DIM];      // concat(Wq0,Wq1,Wk,Wv) rows x 1024

// ============================================================================
// mma.sync / ldmatrix helpers (base sm_103-compatible HMMA path)
// ============================================================================
__device__ __forceinline__ uint32_t smem_u32(const void* p) {
    uint32_t a;
    asm("{ .reg .u64 t; cvta.to.shared.u64 t, %1; cvt.u32.u64 %0, t; }"
        : "=r"(a) : "l"(p));
    return a;
}

__device__ __forceinline__ void mma_bf16(float c[4], const uint32_t a[4],
                                         const uint32_t b[2]) {
    asm volatile(
        "mma.sync.aligned.m16n8k16.row.col.f32.bf16.bf16.f32 "
        "{%0,%1,%2,%3}, {%4,%5,%6,%7}, {%8,%9}, {%0,%1,%2,%3};"
        : "+f"(c[0]), "+f"(c[1]), "+f"(c[2]), "+f"(c[3])
        : "r"(a[0]), "r"(a[1]), "r"(a[2]), "r"(a[3]), "r"(b[0]), "r"(b[1]));
}

__device__ __forceinline__ void ldsm_x4(uint32_t r[4], uint32_t addr) {
    asm volatile("ldmatrix.sync.aligned.m8n8.x4.shared.b16 {%0,%1,%2,%3}, [%4];"
                 : "=r"(r[0]), "=r"(r[1]), "=r"(r[2]), "=r"(r[3]) : "r"(addr));
}
__device__ __forceinline__ void ldsm_x4_t(uint32_t r[4], uint32_t addr) {
    asm volatile("ldmatrix.sync.aligned.m8n8.x4.trans.shared.b16 {%0,%1,%2,%3}, [%4];"
                 : "=r"(r[0]), "=r"(r[1]), "=r"(r[2]), "=r"(r[3]) : "r"(addr));
}

// Split float4 into bf16 hi/lo pairs (packed bf16x2 words)
__device__ __forceinline__ void split_f4(float4 v, uint2& hi, uint2& lo) {
    __nv_bfloat162 h0 = __float22bfloat162_rn(make_float2(v.x, v.y));
    __nv_bfloat162 h1 = __float22bfloat162_rn(make_float2(v.z, v.w));
    __nv_bfloat162 l0 = __float22bfloat162_rn(
        make_float2(v.x - __low2float(h0), v.y - __high2float(h0)));
    __nv_bfloat162 l1 = __float22bfloat162_rn(
        make_float2(v.z - __low2float(h1), v.w - __high2float(h1)));
    hi.x = *(uint32_t*)&h0; hi.y = *(uint32_t*)&h1;
    lo.x = *(uint32_t*)&l0; lo.y = *(uint32_t*)&l1;
}

// Pack scalar pair into bf16x2 hi + lo-residual words
__device__ __forceinline__ void pack2(float x, float y, uint32_t& hi, uint32_t& lo) {
    __nv_bfloat162 h = __float22bfloat162_rn(make_float2(x, y));
    __nv_bfloat162 l = __float22bfloat162_rn(
        make_float2(x - __low2float(h), y - __high2float(h)));
    hi = *(uint32_t*)&h; lo = *(uint32_t*)&l;
}

// Fast exp2 on the FMA pipe (y <= 0 expected; clamped). ~8 ops, rel err ~3e-6.
__device__ __forceinline__ float exp2p(float y) {
    y = fmaxf(y, -125.0f);
    float t = y + 12582912.0f;           // magic round-to-nearest-int
    float k = t - 12582912.0f;
    float f = y - k;                     // f in [-0.5, 0.5]
    float p = 0.0013333558f;
    p = fmaf(p, f, 0.0096181291f);
    p = fmaf(p, f, 0.055504109f);
    p = fmaf(p, f, 0.24022651f);
    p = fmaf(p, f, 0.69314718f);
    p = fmaf(p, f, 1.0f);
    return __int_as_float(__float_as_int(p) + (__float_as_int(t) << 23));
}

// Swizzled byte offsets for bf16 tiles (conflict-free ldmatrix)
// 256B rows (128 bf16 cols), 16 chunks of 16B, chunk ^= row&7
__device__ __forceinline__ uint32_t sw256(int row, int col) {
    int chunk = col >> 3;
    return (uint32_t)(row * 256 + (((chunk ^ (row & 7)) << 4) | ((col & 7) << 1)));
}

// ---------------------------------------------------------------------------
// Weight concat
// ---------------------------------------------------------------------------
__global__ void concat_w_kernel(const float* __restrict__ Wq,
                                const float* __restrict__ Wk,
                                const float* __restrict__ Wv)
{
    int i = blockIdx.x * blockDim.x + threadIdx.x;
    const int TOT = 512 * DIM / 4;
    if (i >= TOT) return;
    int row = i >> 8;
    float4 v;
    if (row < 256)       v = ((const float4*)Wq)[i];
    else if (row < 384)  v = ((const float4*)Wk)[i - 256 * 256];
    else                 v = ((const float4*)Wv)[i - 384 * 256];
    ((float4*)g_wcat)[i] = v;
}

// ---------------------------------------------------------------------------
// HMMA GEMM NT (3xBF16 compensated): C[M,N] = A[M,K] * B[N,K]^T
// 128x128 CTA tile, BK=32, 256 threads (8 warps, 32x64 warp tiles),
// double-buffered smem. Rows padded to 80B for conflict-free ldmatrix.
// ---------------------------------------------------------------------------
#define GEMM_SMEM 81920

__global__ __launch_bounds__(256)
void gemm_mma_kernel(const float* __restrict__ A, const float* __restrict__ B,
                     float* __restrict__ C, int M, int N, int K, int ldc)
{
    extern __shared__ __align__(16) char smp[];
    const uint32_t sb = smem_u32(smp);

    const int tid = threadIdx.x;
    const int wid = tid >> 5;
    const int lane = tid & 31;
    const int m0 = blockIdx.x * 128;
    const int n0 = blockIdx.y * 128;
    const int wm = wid & 3;
    const int wn = wid >> 2;

    float acc[2][8][4];
#pragma unroll
    for (int mf = 0; mf < 2; mf++)
#pragma unroll
        for (int nf = 0; nf < 8; nf++)
#pragma unroll
            for (int q = 0; q < 4; q++) acc[mf][nf][q] = 0.f;

    const int KT = K >> 5;
    float4 ar[4], br[4];

    {
        const float* Ab = A + (size_t)m0 * K;
        const float* Bb = B + (size_t)n0 * K;
#pragma unroll
        for (int i = 0; i < 4; i++) {
            int u = tid + i * 256, row = u >> 3, g = u & 7;
            ar[i] = *(const float4*)(Ab + (size_t)row * K + g * 4);
            br[i] = *(const float4*)(Bb + (size_t)row * K + g * 4);
        }
#pragma unroll
        for (int i = 0; i < 4; i++) {
            int u = tid + i * 256, row = u >> 3, g = u & 7;
            uint32_t off = row * 80 + (g >> 1) * 16 + (g & 1) * 8;
            uint2 hi, lo;
            split_f4(ar[i], hi, lo);
            *(uint2*)(smp + off)         = hi;
            *(uint2*)(smp + 10240 + off) = lo;
            split_f4(br[i], hi, lo);
            *(uint2*)(smp + 20480 + off) = hi;
            *(uint2*)(smp + 30720 + off) = lo;
        }
    }
    __syncthreads();

    for (int kt = 0; kt < KT; kt++) {
        const int buf = kt & 1;
        if (kt + 1 < KT) {
            const float* Ab = A + (size_t)m0 * K + (kt + 1) * 32;
            const float* Bb = B + (size_t)n0 * K + (kt + 1) * 32;
#pragma unroll
            for (int i = 0; i < 4; i++) {
                int u = tid + i * 256, row = u >> 3, g = u & 7;
                ar[i] = *(const float4*)(Ab + (size_t)row * K + g * 4);
                br[i] = *(const float4*)(Bb + (size_t)row * K + g * 4);
            }
        }

        const uint32_t ab = sb + buf * 40960;
        const uint32_t bb = ab + 20480;
#pragma unroll
        for (int ks = 0; ks < 2; ks++) {
            uint32_t ah[2][4], al[2][4];
#pragma unroll
            for (int mf = 0; mf < 2; mf++) {
                int row = wm * 32 + mf * 16 + (lane & 15);
                int chunk = ks * 2 + (lane >> 4);
                uint32_t ad = ab + row * 80 + chunk * 16;
                ldsm_x4(ah[mf], ad);
                ldsm_x4(al[mf], ad + 10240);
            }
            uint32_t bh[8][2], bl[8][2];
#pragma unroll
            for (int np = 0; np < 4; np++) {
                int row = wn * 64 + np * 16 + ((lane >> 4) << 3) + (lane & 7);
                int chunk = ks * 2 + ((lane >> 3) & 1);
                uint32_t bd = bb + row * 80 + chunk * 16;
                uint32_t t[4];
                ldsm_x4(t, bd);
                bh[np * 2][0] = t[0]; bh[np * 2][1] = t[1];
                bh[np * 2 + 1][0] = t[2]; bh[np * 2 + 1][1] = t[3];
                ldsm_x4(t, bd + 10240);
                bl[np * 2][0] = t[0]; bl[np * 2][1] = t[1];
                bl[np * 2 + 1][0] = t[2]; bl[np * 2 + 1][1] = t[3];
            }
#pragma unroll
            for (int mf = 0; mf < 2; mf++)
#pragma unroll
                for (int nf = 0; nf < 8; nf++) {
                    mma_bf16(acc[mf][nf], ah[mf], bh[nf]);
                    mma_bf16(acc[mf][nf], ah[mf], bl[nf]);
                    mma_bf16(acc[mf][nf], al[mf], bh[nf]);
                }
        }

        if (kt + 1 < KT) {
            char* dst = smp + ((kt + 1) & 1) * 40960;
#pragma unroll
            for (int i = 0; i < 4; i++) {
                int u = tid + i * 256, row = u >> 3, g = u & 7;
                uint32_t off = row * 80 + (g >> 1) * 16 + (g & 1) * 8;
                uint2 hi, lo;
                split_f4(ar[i], hi, lo);
                *(uint2*)(dst + off)         = hi;
                *(uint2*)(dst + 10240 + off) = lo;
                split_f4(br[i], hi, lo);
                *(uint2*)(dst + 20480 + off) = hi;
                *(uint2*)(dst + 30720 + off) = lo;
            }
        }
        __syncthreads();
    }

#pragma unroll
    for (int mf = 0; mf < 2; mf++)
#pragma unroll
        for (int nf = 0; nf < 8; nf++) {
            int row = m0 + wm * 32 + mf * 16 + (lane >> 2);
            int col = n0 + wn * 64 + nf * 8 + (lane & 3) * 2;
            *(float2*)(C + (size_t)row * ldc + col) =
                make_float2(acc[mf][nf][0], acc[mf][nf][1]);
            *(float2*)(C + (size_t)(row + 8) * ldc + col) =
                make_float2(acc[mf][nf][2], acc[mf][nf][3]);
        }
}

// ---------------------------------------------------------------------------
// RoPE in-place on g_qkv (fp32)
// ---------------------------------------------------------------------------
__global__ void rope_kernel(float* __restrict__ qkv, int BT, int T)
{
    int idx = blockIdx.x * blockDim.x + threadIdx.x;
    const int PAIRS = 192;
    int row = idx / PAIRS;
    if (row >= BT) return;
    int p = idx - row * PAIRS;
    int t = row % T;

    int i, col;
    if (p < 128) { int h = p >> 6; i = p & 63; col = h * 128 + 2 * i; }
    else         { i = p - 128;               col = 256 + 2 * i;      }

    float theta = powf(10000.0f, -(float)i / 32.0f);
    float ang = (float)t * theta;
    float s, c;
    sincosf(ang, &s, &c);

    float* ptr = qkv + (size_t)row * 512 + col;
    float x0 = ptr[0], x1 = ptr[1];
    ptr[0] = x0 * c - x1 * s;
    ptr[1] = x1 * c + x0 * s;
}

// ---------------------------------------------------------------------------
// Flash attention, FA2-register style. 3xBF16 HMMA, polynomial exp2 softmax.
// BM=64 q-rows/CTA, BN=64 kv/iter, 128 threads (4 warps), warp = 16 q-rows.
// S accumulator frags reused directly as P A-operand frags (no S/P smem).
// smem: QH QL KH KL VH VL, each 64x128 bf16 sw256 = 16KB -> 96KB, 2 CTAs/SM.
// ---------------------------------------------------------------------------
#define ATT2_SMEM 98304
#define AQH 0
#define AQL 16384
#define AKH 32768
#define AKL 49152
#define AVH 65536
#define AVL 81920

__global__ __launch_bounds__(128, 2)
void attn_reg_kernel(const float* __restrict__ qkv, float* __restrict__ O, int T)
{
    extern __shared__ __align__(16) char smp[];
    const uint32_t sb = smem_u32(smp);

    const int tid = threadIdx.x;
    const int wid = tid >> 5;
    const int lane = tid & 31;
    const int bh = blockIdx.y;
    const int b  = bh >> 1;
    const int h  = bh & 1;

    // Orbit-balanced mt map: co-resident pair (bid, bid+148) -> mt sums ~31.
    {
    }
    const int bx = blockIdx.x;
    const int oo = bx & 3;
    const int qq = bx >> 2;
    const int pp = (qq & 1) ? (qq ^ 4) : qq;
    const int mt = (pp & 1) ? (4 * oo + (pp >> 1)) : (31 - 4 * oo - (pp >> 1));
    const int m0 = mt * 64;

    // scale * log2(e): scores land directly in exp2 domain
    const float qscale = 0.08838834764831845f * 1.4426950408889634f;

    const float* qb = qkv + (size_t)b * T * 512 + h * 128;
    const float* kb = qkv + (size_t)b * T * 512 + 256;
    const float* vb = qkv + (size_t)b * T * 512 + 384;

    // ---- load + split Q (pre-scaled) ----
#pragma unroll
    for (int i = 0; i < 16; i++) {
        int u = tid + i * 128;
        int row = u >> 5, g = u & 31;
        float4 v = *(const float4*)(qb + (size_t)(m0 + row) * 512 + g * 4);
        v.x *= qscale; v.y *= qscale; v.z *= qscale; v.w *= qscale;
        uint2 hi, lo;
        split_f4(v, hi, lo);
        uint32_t off = sw256(row, g * 4);
        *(uint2*)(smp + AQH + off) = hi;
        *(uint2*)(smp + AQL + off) = lo;
    }

    float mr0 = -1e30f, mr1 = -1e30f, lr0 = 0.f, lr1 = 0.f;
    float oacc[16][4];
#pragma unroll
    for (int nf = 0; nf < 16; nf++)
#pragma unroll
        for (int q = 0; q < 4; q++) oacc[nf][q] = 0.f;

    for (int j = 0; j <= mt; j++) {
        const int n0v = j * 64;
        __syncthreads();   // previous tile's MMA reads done

        // ---- load + split K, V ----
#pragma unroll
        for (int i = 0; i < 16; i++) {
            int u = tid + i * 128;
            int row = u >> 5, g = u & 31;
            uint32_t off = sw256(row, g * 4);
            float4 kv = *(const float4*)(kb + (size_t)(n0v + row) * 512 + g * 4);
            uint2 hi, lo;
            split_f4(kv, hi, lo);
            *(uint2*)(smp + AKH + off) = hi;
            *(uint2*)(smp + AKL + off) = lo;
            float4 vv = *(const float4*)(vb + (size_t)(n0v + row) * 512 + g * 4);
            split_f4(vv, hi, lo);
            *(uint2*)(smp + AVH + off) = hi;
            *(uint2*)(smp + AVL + off) = lo;
        }
        __syncthreads();

        // ---- S = Q K^T : warp tile 16 rows x 64 cols ----
        float sacc[8][4];
#pragma unroll
        for (int nf = 0; nf < 8; nf++)
#pragma unroll
            for (int q = 0; q < 4; q++) sacc[nf][q] = 0.f;

#pragma unroll
        for (int ks = 0; ks < 8; ks++) {
            uint32_t qh[4], ql[4];
            {
                int row = wid * 16 + (lane & 15);
                int chunk = ks * 2 + (lane >> 4);
                uint32_t off = sw256(row, chunk * 8);
                ldsm_x4(qh, sb + AQH + off);
                ldsm_x4(ql, sb + AQL + off);
            }
#pragma unroll
            for (int ng = 0; ng < 4; ng++) {
                int row = ng * 16 + ((lane >> 4) << 3) + (lane & 7);
                int chunk = ks * 2 + ((lane >> 3) & 1);
                uint32_t off = sw256(row, chunk * 8);
                uint32_t th[4], tl[4];
                ldsm_x4(th, sb + AKH + off);
                ldsm_x4(tl, sb + AKL + off);
                uint32_t bh0[2] = {th[0], th[1]}, bh1[2] = {th[2], th[3]};
                uint32_t bl0[2] = {tl[0], tl[1]}, bl1[2] = {tl[2], tl[3]};
                mma_bf16(sacc[ng * 2],     qh, bh0);
                mma_bf16(sacc[ng * 2],     qh, bl0);
                mma_bf16(sacc[ng * 2],     ql, bh0);
                mma_bf16(sacc[ng * 2 + 1], qh, bh1);
                mma_bf16(sacc[ng * 2 + 1], qh, bl1);
                mma_bf16(sacc[ng * 2 + 1], ql, bh1);
            }
        }

        // ---- causal mask (diagonal tile only) ----
        if (j == mt) {
            int grow0 = m0 + wid * 16 + (lane >> 2);
            int grow1 = grow0 + 8;
            int cbase = n0v + (lane & 3) * 2;
#pragma unroll
            for (int nf = 0; nf < 8; nf++) {
                int c = cbase + nf * 8;
                if (c     > grow0) sacc[nf][0] = -1e30f;
                if (c + 1 > grow0) sacc[nf][1] = -1e30f;
                if (c     > grow1) sacc[nf][2] = -1e30f;
                if (c + 1 > grow1) sacc[nf][3] = -1e30f;
            }
        }

        // ---- register softmax (exp2 domain) ----
        float mx0 = -1e30f, mx1 = -1e30f;
#pragma unroll
        for (int nf = 0; nf < 8; nf++) {
            mx0 = fmaxf(mx0, fmaxf(sacc[nf][0], sacc[nf][1]));
            mx1 = fmaxf(mx1, fmaxf(sacc[nf][2], sacc[nf][3]));
        }
        mx0 = fmaxf(mx0, __shfl_xor_sync(0xffffffffu, mx0, 1));
        mx0 = fmaxf(mx0, __shfl_xor_sync(0xffffffffu, mx0, 2));
        mx1 = fmaxf(mx1, __shfl_xor_sync(0xffffffffu, mx1, 1));
        mx1 = fmaxf(mx1, __shfl_xor_sync(0xffffffffu, mx1, 2));

        float mn0 = fmaxf(mr0, mx0), mn1 = fmaxf(mr1, mx1);
        float corr0 = exp2p(mr0 - mn0), corr1 = exp2p(mr1 - mn1);
        mr0 = mn0; mr1 = mn1;

        float sum0 = 0.f, sum1 = 0.f;
#pragma unroll
        for (int nf = 0; nf < 8; nf++) {
            sacc[nf][0] = exp2p(sacc[nf][0] - mn0);
            sacc[nf][1] = exp2p(sacc[nf][1] - mn0);
            sacc[nf][2] = exp2p(sacc[nf][2] - mn1);
            sacc[nf][3] = exp2p(sacc[nf][3] - mn1);
            sum0 += sacc[nf][0] + sacc[nf][1];
            sum1 += sacc[nf][2] + sacc[nf][3];
        }
        sum0 += __shfl_xor_sync(0xffffffffu, sum0, 1);
        sum0 += __shfl_xor_sync(0xffffffffu, sum0, 2);
        sum1 += __shfl_xor_sync(0xffffffffu, sum1, 1);
        sum1 += __shfl_xor_sync(0xffffffffu, sum1, 2);
        lr0 = lr0 * corr0 + sum0;
        lr1 = lr1 * corr1 + sum1;

        // rescale O accumulator
#pragma unroll
        for (int nf = 0; nf < 16; nf++) {
            oacc[nf][0] *= corr0; oacc[nf][1] *= corr0;
            oacc[nf][2] *= corr1; oacc[nf][3] *= corr1;
        }

        // pack P into A-operand frags (hi/lo) — C-frag layout IS A-frag layout
        uint32_t ph[4][4], pl[4][4];
#pragma unroll
        for (int kc = 0; kc < 4; kc++) {
            pack2(sacc[2 * kc][0],     sacc[2 * kc][1],     ph[kc][0], pl[kc][0]);
            pack2(sacc[2 * kc][2],     sacc[2 * kc][3],     ph[kc][1], pl[kc][1]);
            pack2(sacc[2 * kc + 1][0], sacc[2 * kc + 1][1], ph[kc][2], pl[kc][2]);
            pack2(sacc[2 * kc + 1][2], sacc[2 * kc + 1][3], ph[kc][3], pl[kc][3]);
        }

        // ---- O += P V : warp tile 16 rows x 128 cols ----
#pragma unroll
        for (int ks2 = 0; ks2 < 4; ks2++) {
            int vrow = ks2 * 16 + (lane & 15);
#pragma unroll
            for (int g = 0; g < 8; g++) {
                int chunk = g * 2 + (lane >> 4);
                uint32_t off = sw256(vrow, chunk * 8);
                uint32_t vh[4], vl[4];
                ldsm_x4_t(vh, sb + AVH + off);
                ldsm_x4_t(vl, sb + AVL + off);
                uint32_t vh0[2] = {vh[0], vh[1]}, vh1[2] = {vh[2], vh[3]};
                uint32_t vl0[2] = {vl[0], vl[1]}, vl1[2] = {vl[2], vl[3]};
                mma_bf16(oacc[g * 2],     ph[ks2], vh0);
                mma_bf16(oacc[g * 2],     ph[ks2], vl0);
                mma_bf16(oacc[g * 2],     pl[ks2], vh0);
                mma_bf16(oacc[g * 2 + 1], ph[ks2], vh1);
                mma_bf16(oacc[g * 2 + 1], ph[ks2], vl1);
                mma_bf16(oacc[g * 2 + 1], pl[ks2], vh1);
            }
        }
    }

    // ---- epilogue: normalize + store ----
    float inv0 = 1.0f / lr0;
    float inv1 = 1.0f / lr1;
    size_t row0 = (size_t)b * T + m0 + wid * 16 + (lane >> 2);
#pragma unroll
    for (int nf = 0; nf < 16; nf++) {
        int col = h * 128 + nf * 8 + (lane & 3) * 2;
        *(float2*)(O + row0 * 256 + col) =
            make_float2(oacc[nf][0] * inv0, oacc[nf][1] * inv0);
        *(float2*)(O + (row0 + 8) * 256 + col) =
            make_float2(oacc[nf][2] * inv1, oacc[nf][3] * inv1);
    }
}

// ---------------------------------------------------------------------------
extern "C" void kernel_launch(void* const* d_in, const int* in_sizes, int n_in,
                              void* d_out, int out_size)
{
    const float* x  = (const float*)d_in[0];  // [B,T,1024]
    const float* Wq = (const float*)d_in[1];  // [2,128,1024]
    const float* Wk = (const float*)d_in[2];  // [128,1024]
    const float* Wv = (const float*)d_in[3];  // [128,1024]
    const float* Wo = (const float*)d_in[4];  // [1024,256]

    const int BT = in_sizes[0] / DIM;  // 8192
    const int T  = T_SEQ;
    const int B  = BT / T;

    float *qkv, *attn, *wcat;
    cudaGetSymbolAddress((void**)&qkv,  g_qkv);
    cudaGetSymbolAddress((void**)&attn, g_attn);
    cudaGetSymbolAddress((void**)&wcat, g_wcat);

    cudaFuncSetAttribute(gemm_mma_kernel,
                         cudaFuncAttributeMaxDynamicSharedMemorySize, GEMM_SMEM);
    cudaFuncSetAttribute(attn_reg_kernel,
                         cudaFuncAttributeMaxDynamicSharedMemorySize, ATT2_SMEM);

    // 1) concat weights
    {
        int tot = 512 * DIM / 4;
        concat_w_kernel<<<(tot + 255) / 256, 256>>>(Wq, Wk, Wv);
    }

    // 2) fused QKV projection: qkv[BT,512] = x * Wcat^T
    {
        dim3 grid(BT / 128, 512 / 128);
        gemm_mma_kernel<<<grid, 256, GEMM_SMEM>>>(x, wcat, qkv, BT, 512, DIM, 512);
    }

    // 3) RoPE
    {
        long total = (long)BT * 192;
        rope_kernel<<<(int)((total + 255) / 256), 256>>>(qkv, BT, T);
    }

    // 4) flash attention (FA2-register HMMA)
    {
        dim3 grid(T / 64, B * NKV);
        attn_reg_kernel<<<grid, 128, ATT2_SMEM>>>(qkv, attn, T);
    }

    // 5) output projection: out[BT,1024] = attn * Wo^T
    {
        dim3 grid(BT / 128, DIM / 128);
        gemm_mma_kernel<<<grid, 256, GEMM_SMEM>>>(attn, Wo, (float*)d_out,
                                                  BT, DIM, 256, DIM);
    }
}

// round 5
// speedup vs baseline: 6.1889x; 1.0567x over previous
#include <cuda_runtime.h>
#include <cuda_bf16.h>
#include <math.h>
#include <float.h>
#include <stdint.h>

// Problem constants (fixed by reference setup_inputs)
#define DIM   1024
#define HS    128
#define NKV   2
#define T_SEQ 2048
#define BT_MAX 8192   // B*T = 4*2048

// ---------------- scratch (static device allocations; no cudaMalloc) -------
__device__ float         g_qkv  [BT_MAX * 512];  // fp32 QKV (GEMM1 out, pre-rope)
__device__ __nv_bfloat16 g_xh   [BT_MAX * DIM];  // x split hi
__device__ __nv_bfloat16 g_xl   [BT_MAX * DIM];  // x split lo
__device__ __nv_bfloat16 g_qkvh [BT_MAX * 512];  // rope'd qkv hi (q pre-scaled)
__device__ __nv_bfloat16 g_qkvl [BT_MAX * 512];  // rope'd qkv lo
__device__ __nv_bfloat16 g_attnh[BT_MAX * 256];  // attention out hi
__device__ __nv_bfloat16 g_attnl[BT_MAX * 256];  // attention out lo
__device__ __nv_bfloat16 g_wh   [512 * DIM];     // Wcat hi
__device__ __nv_bfloat16 g_wl   [512 * DIM];     // Wcat lo
__device__ __nv_bfloat16 g_woh  [DIM * 256];     // Wo hi
__device__ __nv_bfloat16 g_wol  [DIM * 256];     // Wo lo

// ============================================================================
// helpers
// ============================================================================
__device__ __forceinline__ uint32_t smem_u32(const void* p) {
    uint32_t a;
    asm("{ .reg .u64 t; cvta.to.shared.u64 t, %1; cvt.u32.u64 %0, t; }"
        : "=r"(a) : "l"(p));
    return a;
}

__device__ __forceinline__ void mma_bf16(float c[4], const uint32_t a[4],
                                         const uint32_t b[2]) {
    asm volatile(
        "mma.sync.aligned.m16n8k16.row.col.f32.bf16.bf16.f32 "
        "{%0,%1,%2,%3}, {%4,%5,%6,%7}, {%8,%9}, {%0,%1,%2,%3};"
        : "+f"(c[0]), "+f"(c[1]), "+f"(c[2]), "+f"(c[3])
        : "r"(a[0]), "r"(a[1]), "r"(a[2]), "r"(a[3]), "r"(b[0]), "r"(b[1]));
}

__device__ __forceinline__ void ldsm_x4(uint32_t r[4], uint32_t addr) {
    asm volatile("ldmatrix.sync.aligned.m8n8.x4.shared.b16 {%0,%1,%2,%3}, [%4];"
                 : "=r"(r[0]), "=r"(r[1]), "=r"(r[2]), "=r"(r[3]) : "r"(addr));
}
__device__ __forceinline__ void ldsm_x4_t(uint32_t r[4], uint32_t addr) {
    asm volatile("ldmatrix.sync.aligned.m8n8.x4.trans.shared.b16 {%0,%1,%2,%3}, [%4];"
                 : "=r"(r[0]), "=r"(r[1]), "=r"(r[2]), "=r"(r[3]) : "r"(addr));
}

#define CP_A16(dst, src) \
    asm volatile("cp.async.cg.shared.global [%0], [%1], 16;" \
                 :: "r"(dst), "l"(src) : "memory")
#define CP_COMMIT() asm volatile("cp.async.commit_group;" ::: "memory")
#define CP_WAIT0()  asm volatile("cp.async.wait_group 0;" ::: "memory")
#define CP_WAIT1()  asm volatile("cp.async.wait_group 1;" ::: "memory")

// Split float4 into bf16 hi/lo pairs (packed bf16x2 words)
__device__ __forceinline__ void split_f4(float4 v, uint2& hi, uint2& lo) {
    __nv_bfloat162 h0 = __float22bfloat162_rn(make_float2(v.x, v.y));
    __nv_bfloat162 h1 = __float22bfloat162_rn(make_float2(v.z, v.w));
    __nv_bfloat162 l0 = __float22bfloat162_rn(
        make_float2(v.x - __low2float(h0), v.y - __high2float(h0)));
    __nv_bfloat162 l1 = __float22bfloat162_rn(
        make_float2(v.z - __low2float(h1), v.w - __high2float(h1)));
    hi.x = *(uint32_t*)&h0; hi.y = *(uint32_t*)&h1;
    lo.x = *(uint32_t*)&l0; lo.y = *(uint32_t*)&l1;
}

__device__ __forceinline__ void pack2(float x, float y, uint32_t& hi, uint32_t& lo) {
    __nv_bfloat162 h = __float22bfloat162_rn(make_float2(x, y));
    __nv_bfloat162 l = __float22bfloat162_rn(
        make_float2(x - __low2float(h), y - __high2float(h)));
    hi = *(uint32_t*)&h; lo = *(uint32_t*)&l;
}

// Fast exp2 on the FMA pipe (y <= 0 expected; clamped).
__device__ __forceinline__ float exp2p(float y) {
    y = fmaxf(y, -125.0f);
    float t = y + 12582912.0f;
    float f = y - (t - 12582912.0f);
    float p = 0.0013333558f;
    p = fmaf(p, f, 0.0096181291f);
    p = fmaf(p, f, 0.055504109f);
    p = fmaf(p, f, 0.24022651f);
    p = fmaf(p, f, 0.69314718f);
    p = fmaf(p, f, 1.0f);
    return __int_as_float(__float_as_int(p) + (__float_as_int(t) << 23));
}

// Swizzle for 128-col bf16 tiles (256B payload rows), 16B chunks
__device__ __forceinline__ uint32_t sw256(int row, int col) {
    int chunk = col >> 3;
    return (uint32_t)(row * 256 + (((chunk ^ (row & 7)) << 4) | ((col & 7) << 1)));
}

// ---------------------------------------------------------------------------
// split_x: x fp32 -> bf16 hi/lo
// ---------------------------------------------------------------------------
__global__ void split_x_kernel(const float* __restrict__ x)
{
    int i = blockIdx.x * blockDim.x + threadIdx.x;   // float4 index
    const int TOT = BT_MAX * DIM / 4;
    if (i >= TOT) return;
    float4 v = ((const float4*)x)[i];
    uint2 hi, lo;
    split_f4(v, hi, lo);
    *(uint2*)(g_xh + i * 4) = hi;
    *(uint2*)(g_xl + i * 4) = lo;
}

// ---------------------------------------------------------------------------
// Weight concat + split: Wcat hi/lo and Wo hi/lo
// ---------------------------------------------------------------------------
__global__ void concat_w_kernel(const float* __restrict__ Wq,
                                const float* __restrict__ Wk,
                                const float* __restrict__ Wv,
                                const float* __restrict__ Wo)
{
    int i = blockIdx.x * blockDim.x + threadIdx.x;
    const int WCAT4 = 512 * DIM / 4;       // 131072
    const int WO4   = DIM * 256 / 4;       // 65536
    if (i < WCAT4) {
        int row = i >> 8;
        float4 v;
        if (row < 256)       v = ((const float4*)Wq)[i];
        else if (row < 384)  v = ((const float4*)Wk)[i - 256 * 256];
        else                 v = ((const float4*)Wv)[i - 384 * 256];
        uint2 hi, lo;
        split_f4(v, hi, lo);
        *(uint2*)(g_wh + i * 4) = hi;
        *(uint2*)(g_wl + i * 4) = lo;
    } else if (i < WCAT4 + WO4) {
        int j = i - WCAT4;
        float4 v = ((const float4*)Wo)[j];
        uint2 hi, lo;
        split_f4(v, hi, lo);
        *(uint2*)(g_woh + j * 4) = hi;
        *(uint2*)(g_wol + j * 4) = lo;
    }
}

// ---------------------------------------------------------------------------
// HMMA GEMM NT (3xBF16): C[M,N] = (Ah+Al)[M,K] * (Bh+Bl)[N,K]^T, bf16 inputs.
// 128x128 CTA tile, BK=32, 256 threads, cp.async double-buffered smem.
// Buffer: Ah(10240) Al(10240) Bh(10240) Bl(10240) = 40960; x2 = 81920 bytes.
// Rows: 32 bf16 = 64B payload, 80B pitch, 4 chunks of 16B.
// ---------------------------------------------------------------------------
#define GEMM_SMEM 81920

__global__ __launch_bounds__(256)
void gemm_bf16_kernel(const __nv_bfloat16* __restrict__ Ah,
                      const __nv_bfloat16* __restrict__ Al,
                      const __nv_bfloat16* __restrict__ Bh,
                      const __nv_bfloat16* __restrict__ Bl,
                      float* __restrict__ C, int M, int N, int K, int ldc)
{
    extern __shared__ __align__(16) char smp[];
    const uint32_t sb = smem_u32(smp);

    const int tid = threadIdx.x;
    const int wid = tid >> 5;
    const int lane = tid & 31;
    const int m0 = blockIdx.x * 128;
    const int n0 = blockIdx.y * 128;
    const int wm = wid & 3;
    const int wn = wid >> 2;

    float acc[2][8][4];
#pragma unroll
    for (int mf = 0; mf < 2; mf++)
#pragma unroll
        for (int nf = 0; nf < 8; nf++)
#pragma unroll
            for (int q = 0; q < 4; q++) acc[mf][nf][q] = 0.f;

    const int KT = K >> 5;

    // fill helper (macro-ish lambda)
    auto fill = [&](int buf, int kt) {
        const uint32_t base = sb + buf * 40960;
#pragma unroll
        for (int i = 0; i < 2; i++) {
            int u = tid + i * 256;           // 0..511
            int row = u >> 2, ch = u & 3;
            uint32_t off = row * 80 + ch * 16;
            const __nv_bfloat16* sA = Ah + (size_t)(m0 + row) * K + kt * 32 + ch * 8;
            const __nv_bfloat16* sAl = Al + (size_t)(m0 + row) * K + kt * 32 + ch * 8;
            const __nv_bfloat16* sB = Bh + (size_t)(n0 + row) * K + kt * 32 + ch * 8;
            const __nv_bfloat16* sBl = Bl + (size_t)(n0 + row) * K + kt * 32 + ch * 8;
            CP_A16(base + off, sA);
            CP_A16(base + 10240 + off, sAl);
            CP_A16(base + 20480 + off, sB);
            CP_A16(base + 30720 + off, sBl);
        }
        CP_COMMIT();
    };

    fill(0, 0);

    for (int kt = 0; kt < KT; kt++) {
        const int buf = kt & 1;
        if (kt + 1 < KT) {
            fill(buf ^ 1, kt + 1);
            CP_WAIT1();
        } else {
            CP_WAIT0();
        }
        __syncthreads();

        const uint32_t ab = sb + buf * 40960;
        const uint32_t bb = ab + 20480;
#pragma unroll
        for (int ks = 0; ks < 2; ks++) {
            uint32_t ah[2][4], al[2][4];
#pragma unroll
            for (int mf = 0; mf < 2; mf++) {
                int row = wm * 32 + mf * 16 + (lane & 15);
                int chunk = ks * 2 + (lane >> 4);
                uint32_t ad = ab + row * 80 + chunk * 16;
                ldsm_x4(ah[mf], ad);
                ldsm_x4(al[mf], ad + 10240);
            }
            uint32_t bh[8][2], bl[8][2];
#pragma unroll
            for (int np = 0; np < 4; np++) {
                int row = wn * 64 + np * 16 + ((lane >> 4) << 3) + (lane & 7);
                int chunk = ks * 2 + ((lane >> 3) & 1);
                uint32_t bd = bb + row * 80 + chunk * 16;
                uint32_t t[4];
                ldsm_x4(t, bd);
                bh[np * 2][0] = t[0]; bh[np * 2][1] = t[1];
                bh[np * 2 + 1][0] = t[2]; bh[np * 2 + 1][1] = t[3];
                ldsm_x4(t, bd + 10240);
                bl[np * 2][0] = t[0]; bl[np * 2][1] = t[1];
                bl[np * 2 + 1][0] = t[2]; bl[np * 2 + 1][1] = t[3];
            }
#pragma unroll
            for (int mf = 0; mf < 2; mf++)
#pragma unroll
                for (int nf = 0; nf < 8; nf++) {
                    mma_bf16(acc[mf][nf], ah[mf], bh[nf]);
                    mma_bf16(acc[mf][nf], ah[mf], bl[nf]);
                    mma_bf16(acc[mf][nf], al[mf], bh[nf]);
                }
        }
        __syncthreads();   // all warps done with buf before next fill overwrites
    }

#pragma unroll
    for (int mf = 0; mf < 2; mf++)
#pragma unroll
        for (int nf = 0; nf < 8; nf++) {
            int row = m0 + wm * 32 + mf * 16 + (lane >> 2);
            int col = n0 + wn * 64 + nf * 8 + (lane & 3) * 2;
            *(float2*)(C + (size_t)row * ldc + col) =
                make_float2(acc[mf][nf][0], acc[mf][nf][1]);
            *(float2*)(C + (size_t)(row + 8) * ldc + col) =
                make_float2(acc[mf][nf][2], acc[mf][nf][3]);
        }
}

// ---------------------------------------------------------------------------
// Fused RoPE + bf16 hi/lo split. Reads g_qkv fp32, writes g_qkvh/g_qkvl.
// Q (cols 0..255) additionally scaled by 128^-0.5 * log2(e).
// Thread handles one row x 8 cols (4 adjacent pairs).
// ---------------------------------------------------------------------------
__global__ void rope_split_kernel(const float* __restrict__ qkv, int BT, int T)
{
    int idx = blockIdx.x * blockDim.x + threadIdx.x;
    if (idx >= BT * 64) return;
    int row = idx >> 6;
    int col0 = (idx & 63) * 8;
    int t = row & (T - 1);

    const float qscale = 0.08838834764831845f * 1.4426950408889634f;

    float4 v0 = *(const float4*)(qkv + (size_t)row * 512 + col0);
    float4 v1 = *(const float4*)(qkv + (size_t)row * 512 + col0 + 4);
    float vals[8] = {v0.x, v0.y, v0.z, v0.w, v1.x, v1.y, v1.z, v1.w};

    if (col0 < 384) {
        // rope on 4 pairs
#pragma unroll
        for (int p = 0; p < 4; p++) {
            int col = col0 + 2 * p;
            int i = (col & 127) >> 1;                 // pair index in head
            float theta = exp2f(-(float)i * (13.287712379549449f / 32.0f));
            float ang = (float)t * theta;
            float s, c;
            sincosf(ang, &s, &c);
            float x0 = vals[2 * p], x1 = vals[2 * p + 1];
            vals[2 * p]     = x0 * c - x1 * s;
            vals[2 * p + 1] = x1 * c + x0 * s;
        }
        if (col0 < 256) {
#pragma unroll
            for (int q = 0; q < 8; q++) vals[q] *= qscale;
        }
    }

    uint2 hi0, lo0, hi1, lo1;
    split_f4(make_float4(vals[0], vals[1], vals[2], vals[3]), hi0, lo0);
    split_f4(make_float4(vals[4], vals[5], vals[6], vals[7]), hi1, lo1);
    __nv_bfloat16* ph = g_qkvh + (size_t)row * 512 + col0;
    __nv_bfloat16* pl = g_qkvl + (size_t)row * 512 + col0;
    *(uint2*)(ph)     = hi0; *(uint2*)(ph + 4) = hi1;
    *(uint2*)(pl)     = lo0; *(uint2*)(pl + 4) = lo1;
}

// ---------------------------------------------------------------------------
// Flash attention, FA2-register style, bf16 pre-split inputs, cp.async fills.
// BM=64, BN=64, 128 threads (4 warps x 16 q-rows). Output: bf16 hi/lo.
// smem: QH QL KH KL VH VL, each 64x128 bf16 sw256 = 16KB -> 96KB, 2 CTAs/SM.
// ---------------------------------------------------------------------------
#define ATT2_SMEM 98304
#define AQH 0
#define AQL 16384
#define AKH 32768
#define AKL 49152
#define AVH 65536
#define AVL 81920

__global__ __launch_bounds__(128, 2)
void attn_reg_kernel(const __nv_bfloat16* __restrict__ qh_g,
                     const __nv_bfloat16* __restrict__ ql_g, int T)
{
    extern __shared__ __align__(16) char smp[];
    const uint32_t sb = smem_u32(smp);

    const int tid = threadIdx.x;
    const int wid = tid >> 5;
    const int lane = tid & 31;
    const int bh = blockIdx.y;
    const int b  = bh >> 1;
    const int h  = bh & 1;

    // Orbit-balanced mt map: co-resident pair (bid, bid+148) -> balanced work
    const int bx = blockIdx.x;
    const int oo = bx & 3;
    const int qq = bx >> 2;
    const int pp = (qq & 1) ? (qq ^ 4) : qq;
    const int mt = (pp & 1) ? (4 * oo + (pp >> 1)) : (31 - 4 * oo - (pp >> 1));
    const int m0 = mt * 64;

    const size_t rb = (size_t)b * T;

    // ---- Q loads (cp.async, swizzled) ----
#pragma unroll
    for (int i = 0; i < 8; i++) {
        int u = tid + i * 128;               // 0..1023
        int row = u >> 4, ch = u & 15;
        uint32_t off = sw256(row, ch * 8);
        size_t src = (rb + m0 + row) * 512 + h * 128 + ch * 8;
        CP_A16(sb + AQH + off, qh_g + src);
        CP_A16(sb + AQL + off, ql_g + src);
    }
    CP_COMMIT();

    float mr0 = -1e30f, mr1 = -1e30f, lr0 = 0.f, lr1 = 0.f;
    float oacc[16][4];
#pragma unroll
    for (int nf = 0; nf < 16; nf++)
#pragma unroll
        for (int q = 0; q < 4; q++) oacc[nf][q] = 0.f;

    for (int j = 0; j <= mt; j++) {
        const int n0v = j * 64;
        __syncthreads();   // previous tile's smem reads done

        // ---- K,V loads (cp.async) ----
#pragma unroll
        for (int i = 0; i < 8; i++) {
            int u = tid + i * 128;
            int row = u >> 4, ch = u & 15;
            uint32_t off = sw256(row, ch * 8);
            size_t srcK = (rb + n0v + row) * 512 + 256 + ch * 8;
            size_t srcV = (rb + n0v + row) * 512 + 384 + ch * 8;
            CP_A16(sb + AKH + off, qh_g + srcK);
            CP_A16(sb + AKL + off, ql_g + srcK);
            CP_A16(sb + AVH + off, qh_g + srcV);
            CP_A16(sb + AVL + off, ql_g + srcV);
        }
        CP_COMMIT();
        CP_WAIT0();
        __syncthreads();

        // ---- S = Q K^T : warp tile 16 rows x 64 cols ----
        float sacc[8][4];
#pragma unroll
        for (int nf = 0; nf < 8; nf++)
#pragma unroll
            for (int q = 0; q < 4; q++) sacc[nf][q] = 0.f;

#pragma unroll
        for (int ks = 0; ks < 8; ks++) {
            uint32_t qh[4], ql[4];
            {
                int row = wid * 16 + (lane & 15);
                int chunk = ks * 2 + (lane >> 4);
                uint32_t off = sw256(row, chunk * 8);
                ldsm_x4(qh, sb + AQH + off);
                ldsm_x4(ql, sb + AQL + off);
            }
#pragma unroll
            for (int ng = 0; ng < 4; ng++) {
                int row = ng * 16 + ((lane >> 4) << 3) + (lane & 7);
                int chunk = ks * 2 + ((lane >> 3) & 1);
                uint32_t off = sw256(row, chunk * 8);
                uint32_t th[4], tl[4];
                ldsm_x4(th, sb + AKH + off);
                ldsm_x4(tl, sb + AKL + off);
                uint32_t bh0[2] = {th[0], th[1]}, bh1[2] = {th[2], th[3]};
                uint32_t bl0[2] = {tl[0], tl[1]}, bl1[2] = {tl[2], tl[3]};
                mma_bf16(sacc[ng * 2],     qh, bh0);
                mma_bf16(sacc[ng * 2],     qh, bl0);
                mma_bf16(sacc[ng * 2],     ql, bh0);
                mma_bf16(sacc[ng * 2 + 1], qh, bh1);
                mma_bf16(sacc[ng * 2 + 1], qh, bl1);
                mma_bf16(sacc[ng * 2 + 1], ql, bh1);
            }
        }

        // ---- causal mask (diagonal tile only) ----
        if (j == mt) {
            int grow0 = m0 + wid * 16 + (lane >> 2);
            int grow1 = grow0 + 8;
            int cbase = n0v + (lane & 3) * 2;
#pragma unroll
            for (int nf = 0; nf < 8; nf++) {
                int c = cbase + nf * 8;
                if (c     > grow0) sacc[nf][0] = -1e30f;
                if (c + 1 > grow0) sacc[nf][1] = -1e30f;
                if (c     > grow1) sacc[nf][2] = -1e30f;
                if (c + 1 > grow1) sacc[nf][3] = -1e30f;
            }
        }

        // ---- register softmax (exp2 domain) ----
        float mx0 = -1e30f, mx1 = -1e30f;
#pragma unroll
        for (int nf = 0; nf < 8; nf++) {
            mx0 = fmaxf(mx0, fmaxf(sacc[nf][0], sacc[nf][1]));
            mx1 = fmaxf(mx1, fmaxf(sacc[nf][2], sacc[nf][3]));
        }
        mx0 = fmaxf(mx0, __shfl_xor_sync(0xffffffffu, mx0, 1));
        mx0 = fmaxf(mx0, __shfl_xor_sync(0xffffffffu, mx0, 2));
        mx1 = fmaxf(mx1, __shfl_xor_sync(0xffffffffu, mx1, 1));
        mx1 = fmaxf(mx1, __shfl_xor_sync(0xffffffffu, mx1, 2));

        float mn0 = fmaxf(mr0, mx0), mn1 = fmaxf(mr1, mx1);
        float corr0 = exp2p(mr0 - mn0), corr1 = exp2p(mr1 - mn1);
        mr0 = mn0; mr1 = mn1;

        float sum0 = 0.f, sum1 = 0.f;
#pragma unroll
        for (int nf = 0; nf < 8; nf++) {
            sacc[nf][0] = exp2p(sacc[nf][0] - mn0);
            sacc[nf][1] = exp2p(sacc[nf][1] - mn0);
            sacc[nf][2] = exp2p(sacc[nf][2] - mn1);
            sacc[nf][3] = exp2p(sacc[nf][3] - mn1);
            sum0 += sacc[nf][0] + sacc[nf][1];
            sum1 += sacc[nf][2] + sacc[nf][3];
        }
        sum0 += __shfl_xor_sync(0xffffffffu, sum0, 1);
        sum0 += __shfl_xor_sync(0xffffffffu, sum0, 2);
        sum1 += __shfl_xor_sync(0xffffffffu, sum1, 1);
        sum1 += __shfl_xor_sync(0xffffffffu, sum1, 2);
        lr0 = lr0 * corr0 + sum0;
        lr1 = lr1 * corr1 + sum1;

#pragma unroll
        for (int nf = 0; nf < 16; nf++) {
            oacc[nf][0] *= corr0; oacc[nf][1] *= corr0;
            oacc[nf][2] *= corr1; oacc[nf][3] *= corr1;
        }

        // pack P into A-operand frags (hi/lo)
        uint32_t ph[4][4], pl[4][4];
#pragma unroll
        for (int kc = 0; kc < 4; kc++) {
            pack2(sacc[2 * kc][0],     sacc[2 * kc][1],     ph[kc][0], pl[kc][0]);
            pack2(sacc[2 * kc][2],     sacc[2 * kc][3],     ph[kc][1], pl[kc][1]);
            pack2(sacc[2 * kc + 1][0], sacc[2 * kc + 1][1], ph[kc][2], pl[kc][2]);
            pack2(sacc[2 * kc + 1][2], sacc[2 * kc + 1][3], ph[kc][3], pl[kc][3]);
        }

        // ---- O += P V : warp tile 16 rows x 128 cols ----
#pragma unroll
        for (int ks2 = 0; ks2 < 4; ks2++) {
            int vrow = ks2 * 16 + (lane & 15);
#pragma unroll
            for (int g = 0; g < 8; g++) {
                int chunk = g * 2 + (lane >> 4);
                uint32_t off = sw256(vrow, chunk * 8);
                uint32_t vh[4], vl[4];
                ldsm_x4_t(vh, sb + AVH + off);
                ldsm_x4_t(vl, sb + AVL + off);
                uint32_t vh0[2] = {vh[0], vh[1]}, vh1[2] = {vh[2], vh[3]};
                uint32_t vl0[2] = {vl[0], vl[1]}, vl1[2] = {vl[2], vl[3]};
                mma_bf16(oacc[g * 2],     ph[ks2], vh0);
                mma_bf16(oacc[g * 2],     ph[ks2], vl0);
                mma_bf16(oacc[g * 2],     pl[ks2], vh0);
                mma_bf16(oacc[g * 2 + 1], ph[ks2], vh1);
                mma_bf16(oacc[g * 2 + 1], ph[ks2], vl1);
                mma_bf16(oacc[g * 2 + 1], pl[ks2], vh1);
            }
        }
    }

    // ---- epilogue: normalize + split-store bf16 hi/lo ----
    float inv0 = 1.0f / lr0;
    float inv1 = 1.0f / lr1;
    size_t row0 = rb + m0 + wid * 16 + (lane >> 2);
#pragma unroll
    for (int nf = 0; nf < 16; nf++) {
        int col = h * 128 + nf * 8 + (lane & 3) * 2;
        uint32_t hi, lo;
        pack2(oacc[nf][0] * inv0, oacc[nf][1] * inv0, hi, lo);
        *(uint32_t*)(g_attnh + row0 * 256 + col) = hi;
        *(uint32_t*)(g_attnl + row0 * 256 + col) = lo;
        pack2(oacc[nf][2] * inv1, oacc[nf][3] * inv1, hi, lo);
        *(uint32_t*)(g_attnh + (row0 + 8) * 256 + col) = hi;
        *(uint32_t*)(g_attnl + (row0 + 8) * 256 + col) = lo;
    }
}

// ---------------------------------------------------------------------------
extern "C" void kernel_launch(void* const* d_in, const int* in_sizes, int n_in,
                              void* d_out, int out_size)
{
    const float* x  = (const float*)d_in[0];  // [B,T,1024]
    const float* Wq = (const float*)d_in[1];  // [2,128,1024]
    const float* Wk = (const float*)d_in[2];  // [128,1024]
    const float* Wv = (const float*)d_in[3];  // [128,1024]
    const float* Wo = (const float*)d_in[4];  // [1024,256]

    const int BT = in_sizes[0] / DIM;  // 8192
    const int T  = T_SEQ;
    const int B  = BT / T;

    float* qkv;
    __nv_bfloat16 *xh, *xl, *qkvh, *qkvl, *attnh, *attnl, *wh, *wl, *woh, *wol;
    cudaGetSymbolAddress((void**)&qkv,   g_qkv);
    cudaGetSymbolAddress((void**)&xh,    g_xh);
    cudaGetSymbolAddress((void**)&xl,    g_xl);
    cudaGetSymbolAddress((void**)&qkvh,  g_qkvh);
    cudaGetSymbolAddress((void**)&qkvl,  g_qkvl);
    cudaGetSymbolAddress((void**)&attnh, g_attnh);
    cudaGetSymbolAddress((void**)&attnl, g_attnl);
    cudaGetSymbolAddress((void**)&wh,    g_wh);
    cudaGetSymbolAddress((void**)&wl,    g_wl);
    cudaGetSymbolAddress((void**)&woh,   g_woh);
    cudaGetSymbolAddress((void**)&wol,   g_wol);

    cudaFuncSetAttribute(gemm_bf16_kernel,
                         cudaFuncAttributeMaxDynamicSharedMemorySize, GEMM_SMEM);
    cudaFuncSetAttribute(attn_reg_kernel,
                         cudaFuncAttributeMaxDynamicSharedMemorySize, ATT2_SMEM);

    // 1) split x; concat+split weights
    {
        int tot = BT * DIM / 4;
        split_x_kernel<<<(tot + 255) / 256, 256>>>(x);
        int wt = 512 * DIM / 4 + DIM * 256 / 4;
        concat_w_kernel<<<(wt + 255) / 256, 256>>>(Wq, Wk, Wv, Wo);
    }

    // 2) fused QKV projection: qkv[BT,512] = x * Wcat^T (fp32 out)
    {
        dim3 grid(BT / 128, 512 / 128);
        gemm_bf16_kernel<<<grid, 256, GEMM_SMEM>>>(xh, xl, wh, wl, qkv,
                                                   BT, 512, DIM, 512);
    }

    // 3) fused RoPE + bf16 split
    {
        int tot = BT * 64;
        rope_split_kernel<<<(tot + 255) / 256, 256>>>(qkv, BT, T);
    }

    // 4) flash attention
    {
        dim3 grid(T / 64, B * NKV);
        attn_reg_kernel<<<grid, 128, ATT2_SMEM>>>(qkvh, qkvl, T);
    }

    // 5) output projection: out[BT,1024] = attn * Wo^T
    {
        dim3 grid(BT / 128, DIM / 128);
        gemm_bf16_kernel<<<grid, 256, GEMM_SMEM>>>(attnh, attnl, woh, wol,
                                                   (float*)d_out, BT, DIM, 256, DIM);
    }
}

// round 6
// speedup vs baseline: 6.5453x; 1.0576x over previous
#include <cuda_runtime.h>
#include <cuda_bf16.h>
#include <cuda_fp16.h>
#include <math.h>
#include <float.h>
#include <stdint.h>

// Problem constants (fixed by reference setup_inputs)
#define DIM   1024
#define HS    128
#define NKV   2
#define T_SEQ 2048
#define BT_MAX 8192   // B*T = 4*2048

// ---------------- scratch (static device allocations; no cudaMalloc) -------
__device__ float         g_qkv  [BT_MAX * 512];  // fp32 QKV (GEMM1 out, pre-rope)
__device__ __nv_bfloat16 g_xh   [BT_MAX * DIM];
__device__ __nv_bfloat16 g_xl   [BT_MAX * DIM];
__device__ __nv_bfloat16 g_qkvh [BT_MAX * 512];  // rope'd q,k hi (q pre-scaled)
__device__ __nv_bfloat16 g_qkvl [BT_MAX * 512];  // rope'd q,k lo
__device__ __half        g_v16  [BT_MAX * 128];  // V as single fp16
__device__ __nv_bfloat16 g_attnh[BT_MAX * 256];
__device__ __nv_bfloat16 g_attnl[BT_MAX * 256];
__device__ __nv_bfloat16 g_wh   [512 * DIM];
__device__ __nv_bfloat16 g_wl   [512 * DIM];
__device__ __nv_bfloat16 g_woh  [DIM * 256];
__device__ __nv_bfloat16 g_wol  [DIM * 256];

// ============================================================================
// helpers
// ============================================================================
__device__ __forceinline__ uint32_t smem_u32(const void* p) {
    uint32_t a;
    asm("{ .reg .u64 t; cvta.to.shared.u64 t, %1; cvt.u32.u64 %0, t; }"
        : "=r"(a) : "l"(p));
    return a;
}

__device__ __forceinline__ void mma_bf16(float c[4], const uint32_t a[4],
                                         const uint32_t b[2]) {
    asm volatile(
        "mma.sync.aligned.m16n8k16.row.col.f32.bf16.bf16.f32 "
        "{%0,%1,%2,%3}, {%4,%5,%6,%7}, {%8,%9}, {%0,%1,%2,%3};"
        : "+f"(c[0]), "+f"(c[1]), "+f"(c[2]), "+f"(c[3])
        : "r"(a[0]), "r"(a[1]), "r"(a[2]), "r"(a[3]), "r"(b[0]), "r"(b[1]));
}
__device__ __forceinline__ void mma_f16(float c[4], const uint32_t a[4],
                                        const uint32_t b[2]) {
    asm volatile(
        "mma.sync.aligned.m16n8k16.row.col.f32.f16.f16.f32 "
        "{%0,%1,%2,%3}, {%4,%5,%6,%7}, {%8,%9}, {%0,%1,%2,%3};"
        : "+f"(c[0]), "+f"(c[1]), "+f"(c[2]), "+f"(c[3])
        : "r"(a[0]), "r"(a[1]), "r"(a[2]), "r"(a[3]), "r"(b[0]), "r"(b[1]));
}

__device__ __forceinline__ void ldsm_x4(uint32_t r[4], uint32_t addr) {
    asm volatile("ldmatrix.sync.aligned.m8n8.x4.shared.b16 {%0,%1,%2,%3}, [%4];"
                 : "=r"(r[0]), "=r"(r[1]), "=r"(r[2]), "=r"(r[3]) : "r"(addr));
}
__device__ __forceinline__ void ldsm_x4_t(uint32_t r[4], uint32_t addr) {
    asm volatile("ldmatrix.sync.aligned.m8n8.x4.trans.shared.b16 {%0,%1,%2,%3}, [%4];"
                 : "=r"(r[0]), "=r"(r[1]), "=r"(r[2]), "=r"(r[3]) : "r"(addr));
}

#define CP_A16(dst, src) \
    asm volatile("cp.async.cg.shared.global [%0], [%1], 16;" \
                 :: "r"(dst), "l"(src) : "memory")
#define CP_COMMIT() asm volatile("cp.async.commit_group;" ::: "memory")
#define CP_WAIT0()  asm volatile("cp.async.wait_group 0;" ::: "memory")
#define CP_WAIT1()  asm volatile("cp.async.wait_group 1;" ::: "memory")

// Split float4 into bf16 hi/lo pairs (packed bf16x2 words)
__device__ __forceinline__ void split_f4(float4 v, uint2& hi, uint2& lo) {
    __nv_bfloat162 h0 = __float22bfloat162_rn(make_float2(v.x, v.y));
    __nv_bfloat162 h1 = __float22bfloat162_rn(make_float2(v.z, v.w));
    __nv_bfloat162 l0 = __float22bfloat162_rn(
        make_float2(v.x - __low2float(h0), v.y - __high2float(h0)));
    __nv_bfloat162 l1 = __float22bfloat162_rn(
        make_float2(v.z - __low2float(h1), v.w - __high2float(h1)));
    hi.x = *(uint32_t*)&h0; hi.y = *(uint32_t*)&h1;
    lo.x = *(uint32_t*)&l0; lo.y = *(uint32_t*)&l1;
}

__device__ __forceinline__ void pack2(float x, float y, uint32_t& hi, uint32_t& lo) {
    __nv_bfloat162 h = __float22bfloat162_rn(make_float2(x, y));
    __nv_bfloat162 l = __float22bfloat162_rn(
        make_float2(x - __low2float(h), y - __high2float(h)));
    hi = *(uint32_t*)&h; lo = *(uint32_t*)&l;
}
// fp16 variant (P is in [0,1]; hi/lo exact to ~2^-22)
__device__ __forceinline__ void pack2h(float x, float y, uint32_t& hi, uint32_t& lo) {
    __half2 h = __float22half2_rn(make_float2(x, y));
    __half2 l = __float22half2_rn(
        make_float2(x - __low2float(h), y - __high2float(h)));
    hi = *(uint32_t*)&h; lo = *(uint32_t*)&l;
}

// Fast exp2 on the FMA pipe (y <= 0 expected; clamped).
__device__ __forceinline__ float exp2p(float y) {
    y = fmaxf(y, -125.0f);
    float t = y + 12582912.0f;
    float f = y - (t - 12582912.0f);
    float p = 0.0013333558f;
    p = fmaf(p, f, 0.0096181291f);
    p = fmaf(p, f, 0.055504109f);
    p = fmaf(p, f, 0.24022651f);
    p = fmaf(p, f, 0.69314718f);
    p = fmaf(p, f, 1.0f);
    return __int_as_float(__float_as_int(p) + (__float_as_int(t) << 23));
}

// Swizzle for 128-col 16-bit tiles (256B rows), 16B chunks
__device__ __forceinline__ uint32_t sw256(int row, int col) {
    int chunk = col >> 3;
    return (uint32_t)(row * 256 + (((chunk ^ (row & 7)) << 4) | ((col & 7) << 1)));
}

// ---------------------------------------------------------------------------
// split_x: x fp32 -> bf16 hi/lo
// ---------------------------------------------------------------------------
__global__ void split_x_kernel(const float* __restrict__ x)
{
    int i = blockIdx.x * blockDim.x + threadIdx.x;
    const int TOT = BT_MAX * DIM / 4;
    if (i >= TOT) return;
    float4 v = ((const float4*)x)[i];
    uint2 hi, lo;
    split_f4(v, hi, lo);
    *(uint2*)(g_xh + i * 4) = hi;
    *(uint2*)(g_xl + i * 4) = lo;
}

// ---------------------------------------------------------------------------
// Weight concat + split: Wcat hi/lo and Wo hi/lo
// ---------------------------------------------------------------------------
__global__ void concat_w_kernel(const float* __restrict__ Wq,
                                const float* __restrict__ Wk,
                                const float* __restrict__ Wv,
                                const float* __restrict__ Wo)
{
    int i = blockIdx.x * blockDim.x + threadIdx.x;
    const int WCAT4 = 512 * DIM / 4;
    const int WO4   = DIM * 256 / 4;
    if (i < WCAT4) {
        int row = i >> 8;
        float4 v;
        if (row < 256)       v = ((const float4*)Wq)[i];
        else if (row < 384)  v = ((const float4*)Wk)[i - 256 * 256];
        else                 v = ((const float4*)Wv)[i - 384 * 256];
        uint2 hi, lo;
        split_f4(v, hi, lo);
        *(uint2*)(g_wh + i * 4) = hi;
        *(uint2*)(g_wl + i * 4) = lo;
    } else if (i < WCAT4 + WO4) {
        int j = i - WCAT4;
        float4 v = ((const float4*)Wo)[j];
        uint2 hi, lo;
        split_f4(v, hi, lo);
        *(uint2*)(g_woh + j * 4) = hi;
        *(uint2*)(g_wol + j * 4) = lo;
    }
}

// ---------------------------------------------------------------------------
// HMMA GEMM NT (3xBF16): C[M,N] = (Ah+Al)[M,K] * (Bh+Bl)[N,K]^T, bf16 inputs.
// 128x128 CTA tile, BK=32, 256 threads, cp.async double-buffered smem.
// ---------------------------------------------------------------------------
#define GEMM_SMEM 81920

__global__ __launch_bounds__(256)
void gemm_bf16_kernel(const __nv_bfloat16* __restrict__ Ah,
                      const __nv_bfloat16* __restrict__ Al,
                      const __nv_bfloat16* __restrict__ Bh,
                      const __nv_bfloat16* __restrict__ Bl,
                      float* __restrict__ C, int M, int N, int K, int ldc)
{
    extern __shared__ __align__(16) char smp[];
    const uint32_t sb = smem_u32(smp);

    const int tid = threadIdx.x;
    const int wid = tid >> 5;
    const int lane = tid & 31;
    const int m0 = blockIdx.x * 128;
    const int n0 = blockIdx.y * 128;
    const int wm = wid & 3;
    const int wn = wid >> 2;

    float acc[2][8][4];
#pragma unroll
    for (int mf = 0; mf < 2; mf++)
#pragma unroll
        for (int nf = 0; nf < 8; nf++)
#pragma unroll
            for (int q = 0; q < 4; q++) acc[mf][nf][q] = 0.f;

    const int KT = K >> 5;

    auto fill = [&](int buf, int kt) {
        const uint32_t base = sb + buf * 40960;
#pragma unroll
        for (int i = 0; i < 2; i++) {
            int u = tid + i * 256;
            int row = u >> 2, ch = u & 3;
            uint32_t off = row * 80 + ch * 16;
            size_t sA = (size_t)(m0 + row) * K + kt * 32 + ch * 8;
            size_t sB = (size_t)(n0 + row) * K + kt * 32 + ch * 8;
            CP_A16(base + off,         Ah + sA);
            CP_A16(base + 10240 + off, Al + sA);
            CP_A16(base + 20480 + off, Bh + sB);
            CP_A16(base + 30720 + off, Bl + sB);
        }
        CP_COMMIT();
    };

    fill(0, 0);

    for (int kt = 0; kt < KT; kt++) {
        const int buf = kt & 1;
        if (kt + 1 < KT) {
            fill(buf ^ 1, kt + 1);
            CP_WAIT1();
        } else {
            CP_WAIT0();
        }
        __syncthreads();

        const uint32_t ab = sb + buf * 40960;
        const uint32_t bb = ab + 20480;
#pragma unroll
        for (int ks = 0; ks < 2; ks++) {
            uint32_t ah[2][4], al[2][4];
#pragma unroll
            for (int mf = 0; mf < 2; mf++) {
                int row = wm * 32 + mf * 16 + (lane & 15);
                int chunk = ks * 2 + (lane >> 4);
                uint32_t ad = ab + row * 80 + chunk * 16;
                ldsm_x4(ah[mf], ad);
                ldsm_x4(al[mf], ad + 10240);
            }
            uint32_t bh[8][2], bl[8][2];
#pragma unroll
            for (int np = 0; np < 4; np++) {
                int row = wn * 64 + np * 16 + ((lane >> 4) << 3) + (lane & 7);
                int chunk = ks * 2 + ((lane >> 3) & 1);
                uint32_t bd = bb + row * 80 + chunk * 16;
                uint32_t t[4];
                ldsm_x4(t, bd);
                bh[np * 2][0] = t[0]; bh[np * 2][1] = t[1];
                bh[np * 2 + 1][0] = t[2]; bh[np * 2 + 1][1] = t[3];
                ldsm_x4(t, bd + 10240);
                bl[np * 2][0] = t[0]; bl[np * 2][1] = t[1];
                bl[np * 2 + 1][0] = t[2]; bl[np * 2 + 1][1] = t[3];
            }
#pragma unroll
            for (int mf = 0; mf < 2; mf++)
#pragma unroll
                for (int nf = 0; nf < 8; nf++) {
                    mma_bf16(acc[mf][nf], ah[mf], bh[nf]);
                    mma_bf16(acc[mf][nf], ah[mf], bl[nf]);
                    mma_bf16(acc[mf][nf], al[mf], bh[nf]);
                }
        }
        __syncthreads();
    }

#pragma unroll
    for (int mf = 0; mf < 2; mf++)
#pragma unroll
        for (int nf = 0; nf < 8; nf++) {
            int row = m0 + wm * 32 + mf * 16 + (lane >> 2);
            int col = n0 + wn * 64 + nf * 8 + (lane & 3) * 2;
            *(float2*)(C + (size_t)row * ldc + col) =
                make_float2(acc[mf][nf][0], acc[mf][nf][1]);
            *(float2*)(C + (size_t)(row + 8) * ldc + col) =
                make_float2(acc[mf][nf][2], acc[mf][nf][3]);
        }
}

// ---------------------------------------------------------------------------
// Fused RoPE + split. Q,K (cols 0..383): rope, bf16 hi/lo (Q pre-scaled).
// V (cols 384..511): single fp16 into g_v16.
// ---------------------------------------------------------------------------
__global__ void rope_split_kernel(const float* __restrict__ qkv, int BT, int T)
{
    int idx = blockIdx.x * blockDim.x + threadIdx.x;
    if (idx >= BT * 64) return;
    int row = idx >> 6;
    int col0 = (idx & 63) * 8;
    int t = row & (T - 1);

    const float qscale = 0.08838834764831845f * 1.4426950408889634f;

    float4 v0 = *(const float4*)(qkv + (size_t)row * 512 + col0);
    float4 v1 = *(const float4*)(qkv + (size_t)row * 512 + col0 + 4);
    float vals[8] = {v0.x, v0.y, v0.z, v0.w, v1.x, v1.y, v1.z, v1.w};

    if (col0 < 384) {
#pragma unroll
        for (int p = 0; p < 4; p++) {
            int col = col0 + 2 * p;
            int i = (col & 127) >> 1;
            float theta = exp2f(-(float)i * (13.287712379549449f / 32.0f));
            float ang = (float)t * theta;
            float s, c;
            sincosf(ang, &s, &c);
            float x0 = vals[2 * p], x1 = vals[2 * p + 1];
            vals[2 * p]     = x0 * c - x1 * s;
            vals[2 * p + 1] = x1 * c + x0 * s;
        }
        if (col0 < 256) {
#pragma unroll
            for (int q = 0; q < 8; q++) vals[q] *= qscale;
        }
        uint2 hi0, lo0, hi1, lo1;
        split_f4(make_float4(vals[0], vals[1], vals[2], vals[3]), hi0, lo0);
        split_f4(make_float4(vals[4], vals[5], vals[6], vals[7]), hi1, lo1);
        __nv_bfloat16* ph = g_qkvh + (size_t)row * 512 + col0;
        __nv_bfloat16* pl = g_qkvl + (size_t)row * 512 + col0;
        *(uint2*)(ph)     = hi0; *(uint2*)(ph + 4) = hi1;
        *(uint2*)(pl)     = lo0; *(uint2*)(pl + 4) = lo1;
    } else {
        // V: single fp16
        __half2 a = __float22half2_rn(make_float2(vals[0], vals[1]));
        __half2 b = __float22half2_rn(make_float2(vals[2], vals[3]));
        __half2 c = __float22half2_rn(make_float2(vals[4], vals[5]));
        __half2 d = __float22half2_rn(make_float2(vals[6], vals[7]));
        uint2 w0, w1;
        w0.x = *(uint32_t*)&a; w0.y = *(uint32_t*)&b;
        w1.x = *(uint32_t*)&c; w1.y = *(uint32_t*)&d;
        __half* pv = g_v16 + (size_t)row * 128 + (col0 - 384);
        *(uint2*)(pv) = w0; *(uint2*)(pv + 4) = w1;
    }
}

// ---------------------------------------------------------------------------
// Flash attention. Q frags in registers; K (bf16 hi/lo) + V (fp16) tiles
// double-buffered with cp.async prefetch. BM=64, BN=64, 128 threads.
// S: 3xbf16 (192 MMA/tile/warp). PV: P fp16 hi/lo x V fp16 (128 MMA).
// smem: K buf b at b*32768 (KH +0, KL +16384); V buf b at 65536 + b*16384.
// ---------------------------------------------------------------------------
#define ATT2_SMEM 98304

__global__ __launch_bounds__(128, 2)
void attn_reg_kernel(const __nv_bfloat16* __restrict__ qh_g,
                     const __nv_bfloat16* __restrict__ ql_g,
                     const __half* __restrict__ v_g, int T)
{
    extern __shared__ __align__(16) char smp[];
    const uint32_t sb = smem_u32(smp);

    const int tid = threadIdx.x;
    const int wid = tid >> 5;
    const int lane = tid & 31;
    const int bh = blockIdx.y;
    const int b  = bh >> 1;
    const int h  = bh & 1;

    // Orbit-balanced mt map
    const int bx = blockIdx.x;
    const int oo = bx & 3;
    const int qq = bx >> 2;
    const int pp = (qq & 1) ? (qq ^ 4) : qq;
    const int mt = (pp & 1) ? (4 * oo + (pp >> 1)) : (31 - 4 * oo - (pp >> 1));
    const int m0 = mt * 64;

    const size_t rb = (size_t)b * T;

    // ---- stage Q into smem (reuses K-buffer 0 region), frag to registers ----
#pragma unroll
    for (int i = 0; i < 8; i++) {
        int u = tid + i * 128;
        int row = u >> 4, ch = u & 15;
        uint32_t off = sw256(row, ch * 8);
        size_t src = (rb + m0 + row) * 512 + h * 128 + ch * 8;
        CP_A16(sb + off,         qh_g + src);
        CP_A16(sb + 16384 + off, ql_g + src);
    }
    CP_COMMIT();
    CP_WAIT0();
    __syncthreads();

    uint32_t qfh[8][4], qfl[8][4];
#pragma unroll
    for (int ks = 0; ks < 8; ks++) {
        int row = wid * 16 + (lane & 15);
        int chunk = ks * 2 + (lane >> 4);
        uint32_t off = sw256(row, chunk * 8);
        ldsm_x4(qfh[ks], sb + off);
        ldsm_x4(qfl[ks], sb + 16384 + off);
    }
    __syncthreads();   // Q reads done before K0 overwrites the buffer

    // ---- KV fill helper ----
    auto fillKV = [&](int buf, int j) {
        const uint32_t kb = sb + buf * 32768;
        const uint32_t vb = sb + 65536 + buf * 16384;
        const int n0v = j * 64;
#pragma unroll
        for (int i = 0; i < 8; i++) {
            int u = tid + i * 128;
            int row = u >> 4, ch = u & 15;
            uint32_t off = sw256(row, ch * 8);
            size_t srcK = (rb + n0v + row) * 512 + 256 + ch * 8;
            CP_A16(kb + off,         qh_g + srcK);
            CP_A16(kb + 16384 + off, ql_g + srcK);
            if (i < 4) {   // V: 64 rows x 128 fp16 = 16KB = 1024 x 16B
                int u2 = tid + i * 128;      // reuse first 512 iterations
                (void)u2;
            }
        }
        // V: 1024 16B chunks over 128 threads = 8 per thread
#pragma unroll
        for (int i = 0; i < 8; i++) {
            int u = tid + i * 128;
            int row = u >> 4, ch = u & 15;
            uint32_t off = sw256(row, ch * 8);
            size_t srcV = (size_t)(rb + n0v + row) * 128 + ch * 8;
            CP_A16(vb + off, v_g + srcV);
        }
        CP_COMMIT();
    };

    fillKV(0, 0);

    float mr0 = -1e30f, mr1 = -1e30f, lr0 = 0.f, lr1 = 0.f;
    float oacc[16][4];
#pragma unroll
    for (int nf = 0; nf < 16; nf++)
#pragma unroll
        for (int q = 0; q < 4; q++) oacc[nf][q] = 0.f;

    for (int j = 0; j <= mt; j++) {
        const int cur = j & 1;
        const int n0v = j * 64;

        __syncthreads();   // buffer cur^1 fully consumed (iter j-1)
        if (j < mt) {
            fillKV(cur ^ 1, j + 1);
            CP_WAIT1();
        } else {
            CP_WAIT0();
        }
        __syncthreads();

        const uint32_t kh_b = sb + cur * 32768;
        const uint32_t kl_b = kh_b + 16384;
        const uint32_t v_b  = sb + 65536 + cur * 16384;

        // ---- S = Q K^T ----
        float sacc[8][4];
#pragma unroll
        for (int nf = 0; nf < 8; nf++)
#pragma unroll
            for (int q = 0; q < 4; q++) sacc[nf][q] = 0.f;

#pragma unroll
        for (int ks = 0; ks < 8; ks++) {
#pragma unroll
            for (int ng = 0; ng < 4; ng++) {
                int row = ng * 16 + ((lane >> 4) << 3) + (lane & 7);
                int chunk = ks * 2 + ((lane >> 3) & 1);
                uint32_t off = sw256(row, chunk * 8);
                uint32_t th[4], tl[4];
                ldsm_x4(th, kh_b + off);
                ldsm_x4(tl, kl_b + off);
                uint32_t bh0[2] = {th[0], th[1]}, bh1[2] = {th[2], th[3]};
                uint32_t bl0[2] = {tl[0], tl[1]}, bl1[2] = {tl[2], tl[3]};
                mma_bf16(sacc[ng * 2],     qfh[ks], bh0);
                mma_bf16(sacc[ng * 2],     qfh[ks], bl0);
                mma_bf16(sacc[ng * 2],     qfl[ks], bh0);
                mma_bf16(sacc[ng * 2 + 1], qfh[ks], bh1);
                mma_bf16(sacc[ng * 2 + 1], qfh[ks], bl1);
                mma_bf16(sacc[ng * 2 + 1], qfl[ks], bh1);
            }
        }

        // ---- causal mask (diagonal tile only) ----
        if (j == mt) {
            int grow0 = m0 + wid * 16 + (lane >> 2);
            int grow1 = grow0 + 8;
            int cbase = n0v + (lane & 3) * 2;
#pragma unroll
            for (int nf = 0; nf < 8; nf++) {
                int c = cbase + nf * 8;
                if (c     > grow0) sacc[nf][0] = -1e30f;
                if (c + 1 > grow0) sacc[nf][1] = -1e30f;
                if (c     > grow1) sacc[nf][2] = -1e30f;
                if (c + 1 > grow1) sacc[nf][3] = -1e30f;
            }
        }

        // ---- register softmax (exp2 domain) ----
        float mx0 = -1e30f, mx1 = -1e30f;
#pragma unroll
        for (int nf = 0; nf < 8; nf++) {
            mx0 = fmaxf(mx0, fmaxf(sacc[nf][0], sacc[nf][1]));
            mx1 = fmaxf(mx1, fmaxf(sacc[nf][2], sacc[nf][3]));
        }
        mx0 = fmaxf(mx0, __shfl_xor_sync(0xffffffffu, mx0, 1));
        mx0 = fmaxf(mx0, __shfl_xor_sync(0xffffffffu, mx0, 2));
        mx1 = fmaxf(mx1, __shfl_xor_sync(0xffffffffu, mx1, 1));
        mx1 = fmaxf(mx1, __shfl_xor_sync(0xffffffffu, mx1, 2));

        float mn0 = fmaxf(mr0, mx0), mn1 = fmaxf(mr1, mx1);
        float corr0 = exp2p(mr0 - mn0), corr1 = exp2p(mr1 - mn1);
        mr0 = mn0; mr1 = mn1;

        float sum0 = 0.f, sum1 = 0.f;
#pragma unroll
        for (int nf = 0; nf < 8; nf++) {
            sacc[nf][0] = exp2p(sacc[nf][0] - mn0);
            sacc[nf][1] = exp2p(sacc[nf][1] - mn0);
            sacc[nf][2] = exp2p(sacc[nf][2] - mn1);
            sacc[nf][3] = exp2p(sacc[nf][3] - mn1);
            sum0 += sacc[nf][0] + sacc[nf][1];
            sum1 += sacc[nf][2] + sacc[nf][3];
        }
        sum0 += __shfl_xor_sync(0xffffffffu, sum0, 1);
        sum0 += __shfl_xor_sync(0xffffffffu, sum0, 2);
        sum1 += __shfl_xor_sync(0xffffffffu, sum1, 1);
        sum1 += __shfl_xor_sync(0xffffffffu, sum1, 2);
        lr0 = lr0 * corr0 + sum0;
        lr1 = lr1 * corr1 + sum1;

#pragma unroll
        for (int nf = 0; nf < 16; nf++) {
            oacc[nf][0] *= corr0; oacc[nf][1] *= corr0;
            oacc[nf][2] *= corr1; oacc[nf][3] *= corr1;
        }

        // ---- pack P into fp16 A-frags (hi/lo; exact to ~2^-22) ----
        uint32_t ph[4][4], pl[4][4];
#pragma unroll
        for (int kc = 0; kc < 4; kc++) {
            pack2h(sacc[2 * kc][0],     sacc[2 * kc][1],     ph[kc][0], pl[kc][0]);
            pack2h(sacc[2 * kc][2],     sacc[2 * kc][3],     ph[kc][1], pl[kc][1]);
            pack2h(sacc[2 * kc + 1][0], sacc[2 * kc + 1][1], ph[kc][2], pl[kc][2]);
            pack2h(sacc[2 * kc + 1][2], sacc[2 * kc + 1][3], ph[kc][3], pl[kc][3]);
        }

        // ---- O += P V (V single fp16) ----
#pragma unroll
        for (int ks2 = 0; ks2 < 4; ks2++) {
            int vrow = ks2 * 16 + (lane & 15);
#pragma unroll
            for (int g = 0; g < 8; g++) {
                int chunk = g * 2 + (lane >> 4);
                uint32_t off = sw256(vrow, chunk * 8);
                uint32_t vh[4];
                ldsm_x4_t(vh, v_b + off);
                uint32_t vh0[2] = {vh[0], vh[1]}, vh1[2] = {vh[2], vh[3]};
                mma_f16(oacc[g * 2],     ph[ks2], vh0);
                mma_f16(oacc[g * 2],     pl[ks2], vh0);
                mma_f16(oacc[g * 2 + 1], ph[ks2], vh1);
                mma_f16(oacc[g * 2 + 1], pl[ks2], vh1);
            }
        }
    }

    // ---- epilogue: normalize + split-store bf16 hi/lo ----
    float inv0 = 1.0f / lr0;
    float inv1 = 1.0f / lr1;
    size_t row0 = rb + m0 + wid * 16 + (lane >> 2);
#pragma unroll
    for (int nf = 0; nf < 16; nf++) {
        int col = h * 128 + nf * 8 + (lane & 3) * 2;
        uint32_t hi, lo;
        pack2(oacc[nf][0] * inv0, oacc[nf][1] * inv0, hi, lo);
        *(uint32_t*)(g_attnh + row0 * 256 + col) = hi;
        *(uint32_t*)(g_attnl + row0 * 256 + col) = lo;
        pack2(oacc[nf][2] * inv1, oacc[nf][3] * inv1, hi, lo);
        *(uint32_t*)(g_attnh + (row0 + 8) * 256 + col) = hi;
        *(uint32_t*)(g_attnl + (row0 + 8) * 256 + col) = lo;
    }
}

// ---------------------------------------------------------------------------
extern "C" void kernel_launch(void* const* d_in, const int* in_sizes, int n_in,
                              void* d_out, int out_size)
{
    const float* x  = (const float*)d_in[0];
    const float* Wq = (const float*)d_in[1];
    const float* Wk = (const float*)d_in[2];
    const float* Wv = (const float*)d_in[3];
    const float* Wo = (const float*)d_in[4];

    const int BT = in_sizes[0] / DIM;  // 8192
    const int T  = T_SEQ;
    const int B  = BT / T;

    float* qkv;
    __nv_bfloat16 *xh, *xl, *qkvh, *qkvl, *attnh, *attnl, *wh, *wl, *woh, *wol;
    __half* v16;
    cudaGetSymbolAddress((void**)&qkv,   g_qkv);
    cudaGetSymbolAddress((void**)&xh,    g_xh);
    cudaGetSymbolAddress((void**)&xl,    g_xl);
    cudaGetSymbolAddress((void**)&qkvh,  g_qkvh);
    cudaGetSymbolAddress((void**)&qkvl,  g_qkvl);
    cudaGetSymbolAddress((void**)&v16,   g_v16);
    cudaGetSymbolAddress((void**)&attnh, g_attnh);
    cudaGetSymbolAddress((void**)&attnl, g_attnl);
    cudaGetSymbolAddress((void**)&wh,    g_wh);
    cudaGetSymbolAddress((void**)&wl,    g_wl);
    cudaGetSymbolAddress((void**)&woh,   g_woh);
    cudaGetSymbolAddress((void**)&wol,   g_wol);

    cudaFuncSetAttribute(gemm_bf16_kernel,
                         cudaFuncAttributeMaxDynamicSharedMemorySize, GEMM_SMEM);
    cudaFuncSetAttribute(attn_reg_kernel,
                         cudaFuncAttributeMaxDynamicSharedMemorySize, ATT2_SMEM);

    // 1) split x; concat+split weights
    {
        int tot = BT * DIM / 4;
        split_x_kernel<<<(tot + 255) / 256, 256>>>(x);
        int wt = 512 * DIM / 4 + DIM * 256 / 4;
        concat_w_kernel<<<(wt + 255) / 256, 256>>>(Wq, Wk, Wv, Wo);
    }

    // 2) fused QKV projection
    {
        dim3 grid(BT / 128, 512 / 128);
        gemm_bf16_kernel<<<grid, 256, GEMM_SMEM>>>(xh, xl, wh, wl, qkv,
                                                   BT, 512, DIM, 512);
    }

    // 3) fused RoPE + split (V -> fp16)
    {
        int tot = BT * 64;
        rope_split_kernel<<<(tot + 255) / 256, 256>>>(qkv, BT, T);
    }

    // 4) flash attention
    {
        dim3 grid(T / 64, B * NKV);
        attn_reg_kernel<<<grid, 128, ATT2_SMEM>>>(qkvh, qkvl, v16, T);
    }

    // 5) output projection
    {
        dim3 grid(BT / 128, DIM / 128);
        gemm_bf16_kernel<<<grid, 256, GEMM_SMEM>>>(attnh, attnl, woh, wol,
                                                   (float*)d_out, BT, DIM, 256, DIM);
    }
}

// round 7
// speedup vs baseline: 6.8421x; 1.0453x over previous
#include <cuda_runtime.h>
#include <cuda_bf16.h>
#include <cuda_fp16.h>
#include <math.h>
#include <float.h>
#include <stdint.h>

// Problem constants (fixed by reference setup_inputs)
#define DIM   1024
#define HS    128
#define NKV   2
#define T_SEQ 2048
#define BT_MAX 8192   // B*T = 4*2048

// ---------------- scratch (static device allocations; no cudaMalloc) -------
__device__ __nv_bfloat16 g_xh   [BT_MAX * DIM];
__device__ __nv_bfloat16 g_xl   [BT_MAX * DIM];
__device__ __half        g_q16h [BT_MAX * 256];  // rope'd+scaled Q, fp16 hi
__device__ __half        g_q16l [BT_MAX * 256];  // fp16 lo residual
__device__ __half        g_k16  [BT_MAX * 128];  // rope'd K, single fp16
__device__ __half        g_v16  [BT_MAX * 128];  // V, single fp16
__device__ __nv_bfloat16 g_attnh[BT_MAX * 256];
__device__ __nv_bfloat16 g_attnl[BT_MAX * 256];
__device__ __nv_bfloat16 g_wh   [512 * DIM];
__device__ __nv_bfloat16 g_wl   [512 * DIM];
__device__ __nv_bfloat16 g_woh  [DIM * 256];
__device__ __nv_bfloat16 g_wol  [DIM * 256];
__device__ float2        g_trig [T_SEQ * 64];    // (cos, sin) per (t, pair)

// ============================================================================
// helpers
// ============================================================================
__device__ __forceinline__ uint32_t smem_u32(const void* p) {
    uint32_t a;
    asm("{ .reg .u64 t; cvta.to.shared.u64 t, %1; cvt.u32.u64 %0, t; }"
        : "=r"(a) : "l"(p));
    return a;
}

__device__ __forceinline__ void mma_bf16(float c[4], const uint32_t a[4],
                                         const uint32_t b[2]) {
    asm volatile(
        "mma.sync.aligned.m16n8k16.row.col.f32.bf16.bf16.f32 "
        "{%0,%1,%2,%3}, {%4,%5,%6,%7}, {%8,%9}, {%0,%1,%2,%3};"
        : "+f"(c[0]), "+f"(c[1]), "+f"(c[2]), "+f"(c[3])
        : "r"(a[0]), "r"(a[1]), "r"(a[2]), "r"(a[3]), "r"(b[0]), "r"(b[1]));
}
__device__ __forceinline__ void mma_f16(float c[4], const uint32_t a[4],
                                        const uint32_t b[2]) {
    asm volatile(
        "mma.sync.aligned.m16n8k16.row.col.f32.f16.f16.f32 "
        "{%0,%1,%2,%3}, {%4,%5,%6,%7}, {%8,%9}, {%0,%1,%2,%3};"
        : "+f"(c[0]), "+f"(c[1]), "+f"(c[2]), "+f"(c[3])
        : "r"(a[0]), "r"(a[1]), "r"(a[2]), "r"(a[3]), "r"(b[0]), "r"(b[1]));
}

__device__ __forceinline__ void ldsm_x4(uint32_t r[4], uint32_t addr) {
    asm volatile("ldmatrix.sync.aligned.m8n8.x4.shared.b16 {%0,%1,%2,%3}, [%4];"
                 : "=r"(r[0]), "=r"(r[1]), "=r"(r[2]), "=r"(r[3]) : "r"(addr));
}
__device__ __forceinline__ void ldsm_x4_t(uint32_t r[4], uint32_t addr) {
    asm volatile("ldmatrix.sync.aligned.m8n8.x4.trans.shared.b16 {%0,%1,%2,%3}, [%4];"
                 : "=r"(r[0]), "=r"(r[1]), "=r"(r[2]), "=r"(r[3]) : "r"(addr));
}

#define CP_A16(dst, src) \
    asm volatile("cp.async.cg.shared.global [%0], [%1], 16;" \
                 :: "r"(dst), "l"(src) : "memory")
#define CP_COMMIT() asm volatile("cp.async.commit_group;" ::: "memory")
#define CP_WAIT0()  asm volatile("cp.async.wait_group 0;" ::: "memory")
#define CP_WAIT1()  asm volatile("cp.async.wait_group 1;" ::: "memory")

__device__ __forceinline__ void split_f4(float4 v, uint2& hi, uint2& lo) {
    __nv_bfloat162 h0 = __float22bfloat162_rn(make_float2(v.x, v.y));
    __nv_bfloat162 h1 = __float22bfloat162_rn(make_float2(v.z, v.w));
    __nv_bfloat162 l0 = __float22bfloat162_rn(
        make_float2(v.x - __low2float(h0), v.y - __high2float(h0)));
    __nv_bfloat162 l1 = __float22bfloat162_rn(
        make_float2(v.z - __low2float(h1), v.w - __high2float(h1)));
    hi.x = *(uint32_t*)&h0; hi.y = *(uint32_t*)&h1;
    lo.x = *(uint32_t*)&l0; lo.y = *(uint32_t*)&l1;
}

__device__ __forceinline__ void pack2(float x, float y, uint32_t& hi, uint32_t& lo) {
    __nv_bfloat162 h = __float22bfloat162_rn(make_float2(x, y));
    __nv_bfloat162 l = __float22bfloat162_rn(
        make_float2(x - __low2float(h), y - __high2float(h)));
    hi = *(uint32_t*)&h; lo = *(uint32_t*)&l;
}
__device__ __forceinline__ void pack2h(float x, float y, uint32_t& hi, uint32_t& lo) {
    __half2 h = __float22half2_rn(make_float2(x, y));
    __half2 l = __float22half2_rn(
        make_float2(x - __low2float(h), y - __high2float(h)));
    hi = *(uint32_t*)&h; lo = *(uint32_t*)&l;
}

__device__ __forceinline__ float exp2p(float y) {
    y = fmaxf(y, -125.0f);
    float t = y + 12582912.0f;
    float f = y - (t - 12582912.0f);
    float p = 0.0013333558f;
    p = fmaf(p, f, 0.0096181291f);
    p = fmaf(p, f, 0.055504109f);
    p = fmaf(p, f, 0.24022651f);
    p = fmaf(p, f, 0.69314718f);
    p = fmaf(p, f, 1.0f);
    return __int_as_float(__float_as_int(p) + (__float_as_int(t) << 23));
}

// Swizzle for 128-col 16-bit tiles (256B rows), 16B chunks
__device__ __forceinline__ uint32_t sw256(int row, int col) {
    int chunk = col >> 3;
    return (uint32_t)(row * 256 + (((chunk ^ (row & 7)) << 4) | ((col & 7) << 1)));
}

// ---------------------------------------------------------------------------
// trig table: g_trig[t*64+i] = (cos(t*theta_i), sin(t*theta_i))
// ---------------------------------------------------------------------------
__global__ void trig_kernel()
{
    int idx = blockIdx.x * blockDim.x + threadIdx.x;
    if (idx >= T_SEQ * 64) return;
    int t = idx >> 6, i = idx & 63;
    float theta = exp2f(-(float)i * (13.287712379549449f / 32.0f));
    float s, c;
    sincosf((float)t * theta, &s, &c);
    g_trig[idx] = make_float2(c, s);
}

// ---------------------------------------------------------------------------
// split_x: x fp32 -> bf16 hi/lo
// ---------------------------------------------------------------------------
__global__ void split_x_kernel(const float* __restrict__ x)
{
    int i = blockIdx.x * blockDim.x + threadIdx.x;
    const int TOT = BT_MAX * DIM / 4;
    if (i >= TOT) return;
    float4 v = ((const float4*)x)[i];
    uint2 hi, lo;
    split_f4(v, hi, lo);
    *(uint2*)(g_xh + i * 4) = hi;
    *(uint2*)(g_xl + i * 4) = lo;
}

// ---------------------------------------------------------------------------
// Weight concat + split
// ---------------------------------------------------------------------------
__global__ void concat_w_kernel(const float* __restrict__ Wq,
                                const float* __restrict__ Wk,
                                const float* __restrict__ Wv,
                                const float* __restrict__ Wo)
{
    int i = blockIdx.x * blockDim.x + threadIdx.x;
    const int WCAT4 = 512 * DIM / 4;
    const int WO4   = DIM * 256 / 4;
    if (i < WCAT4) {
        int row = i >> 8;
        float4 v;
        if (row < 256)       v = ((const float4*)Wq)[i];
        else if (row < 384)  v = ((const float4*)Wk)[i - 256 * 256];
        else                 v = ((const float4*)Wv)[i - 384 * 256];
        uint2 hi, lo;
        split_f4(v, hi, lo);
        *(uint2*)(g_wh + i * 4) = hi;
        *(uint2*)(g_wl + i * 4) = lo;
    } else if (i < WCAT4 + WO4) {
        int j = i - WCAT4;
        float4 v = ((const float4*)Wo)[j];
        uint2 hi, lo;
        split_f4(v, hi, lo);
        *(uint2*)(g_woh + j * 4) = hi;
        *(uint2*)(g_wol + j * 4) = lo;
    }
}

// ---------------------------------------------------------------------------
// HMMA GEMM NT (3xBF16). epi=0: fp32 C. epi=1: fused rope+split epilogue
// writing g_q16h/l (Q, scaled), g_k16, g_v16.
// ---------------------------------------------------------------------------
#define GEMM_SMEM 81920

__device__ __forceinline__ void rope_epi_store(int r, int c, float x0, float x1)
{
    const float qscale = 0.08838834764831845f * 1.4426950408889634f;
    int t = r & (T_SEQ - 1);
    if (c < 384) {
        int i = (c & 127) >> 1;
        float2 cs = g_trig[t * 64 + i];
        float y0 = x0 * cs.x - x1 * cs.y;
        float y1 = x1 * cs.x + x0 * cs.y;
        if (c < 256) {
            y0 *= qscale; y1 *= qscale;
            uint32_t hi, lo;
            pack2h(y0, y1, hi, lo);
            *(uint32_t*)(g_q16h + (size_t)r * 256 + c) = hi;
            *(uint32_t*)(g_q16l + (size_t)r * 256 + c) = lo;
        } else {
            __half2 hh = __float22half2_rn(make_float2(y0, y1));
            *(uint32_t*)(g_k16 + (size_t)r * 128 + (c - 256)) = *(uint32_t*)&hh;
        }
    } else {
        __half2 hh = __float22half2_rn(make_float2(x0, x1));
        *(uint32_t*)(g_v16 + (size_t)r * 128 + (c - 384)) = *(uint32_t*)&hh;
    }
}

__global__ __launch_bounds__(256)
void gemm_bf16_kernel(const __nv_bfloat16* __restrict__ Ah,
                      const __nv_bfloat16* __restrict__ Al,
                      const __nv_bfloat16* __restrict__ Bh,
                      const __nv_bfloat16* __restrict__ Bl,
                      float* __restrict__ C, int M, int N, int K, int ldc,
                      int epi)
{
    extern __shared__ __align__(16) char smp[];
    const uint32_t sb = smem_u32(smp);

    const int tid = threadIdx.x;
    const int wid = tid >> 5;
    const int lane = tid & 31;
    const int m0 = blockIdx.x * 128;
    const int n0 = blockIdx.y * 128;
    const int wm = wid & 3;
    const int wn = wid >> 2;

    float acc[2][8][4];
#pragma unroll
    for (int mf = 0; mf < 2; mf++)
#pragma unroll
        for (int nf = 0; nf < 8; nf++)
#pragma unroll
            for (int q = 0; q < 4; q++) acc[mf][nf][q] = 0.f;

    const int KT = K >> 5;

    auto fill = [&](int buf, int kt) {
        const uint32_t base = sb + buf * 40960;
#pragma unroll
        for (int i = 0; i < 2; i++) {
            int u = tid + i * 256;
            int row = u >> 2, ch = u & 3;
            uint32_t off = row * 80 + ch * 16;
            size_t sA = (size_t)(m0 + row) * K + kt * 32 + ch * 8;
            size_t sB = (size_t)(n0 + row) * K + kt * 32 + ch * 8;
            CP_A16(base + off,         Ah + sA);
            CP_A16(base + 10240 + off, Al + sA);
            CP_A16(base + 20480 + off, Bh + sB);
            CP_A16(base + 30720 + off, Bl + sB);
        }
        CP_COMMIT();
    };

    fill(0, 0);

    for (int kt = 0; kt < KT; kt++) {
        const int buf = kt & 1;
        if (kt + 1 < KT) {
            fill(buf ^ 1, kt + 1);
            CP_WAIT1();
        } else {
            CP_WAIT0();
        }
        __syncthreads();

        const uint32_t ab = sb + buf * 40960;
        const uint32_t bb = ab + 20480;
#pragma unroll
        for (int ks = 0; ks < 2; ks++) {
            uint32_t ah[2][4], al[2][4];
#pragma unroll
            for (int mf = 0; mf < 2; mf++) {
                int row = wm * 32 + mf * 16 + (lane & 15);
                int chunk = ks * 2 + (lane >> 4);
                uint32_t ad = ab + row * 80 + chunk * 16;
                ldsm_x4(ah[mf], ad);
                ldsm_x4(al[mf], ad + 10240);
            }
            uint32_t bh[8][2], bl[8][2];
#pragma unroll
            for (int np = 0; np < 4; np++) {
                int row = wn * 64 + np * 16 + ((lane >> 4) << 3) + (lane & 7);
                int chunk = ks * 2 + ((lane >> 3) & 1);
                uint32_t bd = bb + row * 80 + chunk * 16;
                uint32_t t[4];
                ldsm_x4(t, bd);
                bh[np * 2][0] = t[0]; bh[np * 2][1] = t[1];
                bh[np * 2 + 1][0] = t[2]; bh[np * 2 + 1][1] = t[3];
                ldsm_x4(t, bd + 10240);
                bl[np * 2][0] = t[0]; bl[np * 2][1] = t[1];
                bl[np * 2 + 1][0] = t[2]; bl[np * 2 + 1][1] = t[3];
            }
#pragma unroll
            for (int mf = 0; mf < 2; mf++)
#pragma unroll
                for (int nf = 0; nf < 8; nf++) {
                    mma_bf16(acc[mf][nf], ah[mf], bh[nf]);
                    mma_bf16(acc[mf][nf], ah[mf], bl[nf]);
                    mma_bf16(acc[mf][nf], al[mf], bh[nf]);
                }
        }
        __syncthreads();
    }

    if (epi == 0) {
#pragma unroll
        for (int mf = 0; mf < 2; mf++)
#pragma unroll
            for (int nf = 0; nf < 8; nf++) {
                int row = m0 + wm * 32 + mf * 16 + (lane >> 2);
                int col = n0 + wn * 64 + nf * 8 + (lane & 3) * 2;
                *(float2*)(C + (size_t)row * ldc + col) =
                    make_float2(acc[mf][nf][0], acc[mf][nf][1]);
                *(float2*)(C + (size_t)(row + 8) * ldc + col) =
                    make_float2(acc[mf][nf][2], acc[mf][nf][3]);
            }
    } else {
#pragma unroll
        for (int mf = 0; mf < 2; mf++)
#pragma unroll
            for (int nf = 0; nf < 8; nf++) {
                int row = m0 + wm * 32 + mf * 16 + (lane >> 2);
                int col = n0 + wn * 64 + nf * 8 + (lane & 3) * 2;
                rope_epi_store(row,     col, acc[mf][nf][0], acc[mf][nf][1]);
                rope_epi_store(row + 8, col, acc[mf][nf][2], acc[mf][nf][3]);
            }
    }
}

// ---------------------------------------------------------------------------
// Flash attention, all-fp16 MMA. Q fp16 hi/lo frags in registers.
// K single fp16, V single fp16, double-buffered cp.async.
// S: 128 mma/tile/warp. PV: 128. smem = 64KB.
//   K buf b at b*16384; V buf b at 32768 + b*16384. Q staged in 0..32767.
// ---------------------------------------------------------------------------
#define ATT2_SMEM 65536

__global__ __launch_bounds__(128, 2)
void attn_reg_kernel(const __half* __restrict__ qh_g,
                     const __half* __restrict__ ql_g,
                     const __half* __restrict__ k_g,
                     const __half* __restrict__ v_g, int T)
{
    extern __shared__ __align__(16) char smp[];
    const uint32_t sb = smem_u32(smp);

    const int tid = threadIdx.x;
    const int wid = tid >> 5;
    const int lane = tid & 31;
    const int bh = blockIdx.y;
    const int b  = bh >> 1;
    const int h  = bh & 1;

    // Orbit-balanced mt map
    const int bx = blockIdx.x;
    const int oo = bx & 3;
    const int qq = bx >> 2;
    const int pp = (qq & 1) ? (qq ^ 4) : qq;
    const int mt = (pp & 1) ? (4 * oo + (pp >> 1)) : (31 - 4 * oo - (pp >> 1));
    const int m0 = mt * 64;

    const size_t rb = (size_t)b * T;

    // ---- stage Q (hi at 0, lo at 16384), extract frags ----
#pragma unroll
    for (int i = 0; i < 8; i++) {
        int u = tid + i * 128;
        int row = u >> 4, ch = u & 15;
        uint32_t off = sw256(row, ch * 8);
        size_t src = (rb + m0 + row) * 256 + h * 128 + ch * 8;
        CP_A16(sb + off,         qh_g + src);
        CP_A16(sb + 16384 + off, ql_g + src);
    }
    CP_COMMIT();
    CP_WAIT0();
    __syncthreads();

    uint32_t qfh[8][4], qfl[8][4];
#pragma unroll
    for (int ks = 0; ks < 8; ks++) {
        int row = wid * 16 + (lane & 15);
        int chunk = ks * 2 + (lane >> 4);
        uint32_t off = sw256(row, chunk * 8);
        ldsm_x4(qfh[ks], sb + off);
        ldsm_x4(qfl[ks], sb + 16384 + off);
    }
    __syncthreads();   // Q reads done before K0 overwrites

    auto fillKV = [&](int buf, int j) {
        const uint32_t kb = sb + buf * 16384;
        const uint32_t vb = sb + 32768 + buf * 16384;
        const int n0v = j * 64;
#pragma unroll
        for (int i = 0; i < 8; i++) {
            int u = tid + i * 128;
            int row = u >> 4, ch = u & 15;
            uint32_t off = sw256(row, ch * 8);
            size_t src = (size_t)(rb + n0v + row) * 128 + ch * 8;
            CP_A16(kb + off, k_g + src);
            CP_A16(vb + off, v_g + src);
        }
        CP_COMMIT();
    };

    fillKV(0, 0);

    float mr0 = -1e30f, mr1 = -1e30f, lr0 = 0.f, lr1 = 0.f;
    float oacc[16][4];
#pragma unroll
    for (int nf = 0; nf < 16; nf++)
#pragma unroll
        for (int q = 0; q < 4; q++) oacc[nf][q] = 0.f;

    for (int j = 0; j <= mt; j++) {
        const int cur = j & 1;
        const int n0v = j * 64;

        __syncthreads();
        if (j < mt) {
            fillKV(cur ^ 1, j + 1);
            CP_WAIT1();
        } else {
            CP_WAIT0();
        }
        __syncthreads();

        const uint32_t kb = sb + cur * 16384;
        const uint32_t vb = sb + 32768 + cur * 16384;

        // ---- S = Q K^T (fp16) ----
        float sacc[8][4];
#pragma unroll
        for (int nf = 0; nf < 8; nf++)
#pragma unroll
            for (int q = 0; q < 4; q++) sacc[nf][q] = 0.f;

#pragma unroll
        for (int ks = 0; ks < 8; ks++) {
#pragma unroll
            for (int ng = 0; ng < 4; ng++) {
                int row = ng * 16 + ((lane >> 4) << 3) + (lane & 7);
                int chunk = ks * 2 + ((lane >> 3) & 1);
                uint32_t off = sw256(row, chunk * 8);
                uint32_t t[4];
                ldsm_x4(t, kb + off);
                uint32_t b0[2] = {t[0], t[1]}, b1[2] = {t[2], t[3]};
                mma_f16(sacc[ng * 2],     qfh[ks], b0);
                mma_f16(sacc[ng * 2],     qfl[ks], b0);
                mma_f16(sacc[ng * 2 + 1], qfh[ks], b1);
                mma_f16(sacc[ng * 2 + 1], qfl[ks], b1);
            }
        }

        // ---- causal mask (diagonal tile only) ----
        if (j == mt) {
            int grow0 = m0 + wid * 16 + (lane >> 2);
            int grow1 = grow0 + 8;
            int cbase = n0v + (lane & 3) * 2;
#pragma unroll
            for (int nf = 0; nf < 8; nf++) {
                int c = cbase + nf * 8;
                if (c     > grow0) sacc[nf][0] = -1e30f;
                if (c + 1 > grow0) sacc[nf][1] = -1e30f;
                if (c     > grow1) sacc[nf][2] = -1e30f;
                if (c + 1 > grow1) sacc[nf][3] = -1e30f;
            }
        }

        // ---- register softmax (exp2 domain) ----
        float mx0 = -1e30f, mx1 = -1e30f;
#pragma unroll
        for (int nf = 0; nf < 8; nf++) {
            mx0 = fmaxf(mx0, fmaxf(sacc[nf][0], sacc[nf][1]));
            mx1 = fmaxf(mx1, fmaxf(sacc[nf][2], sacc[nf][3]));
        }
        mx0 = fmaxf(mx0, __shfl_xor_sync(0xffffffffu, mx0, 1));
        mx0 = fmaxf(mx0, __shfl_xor_sync(0xffffffffu, mx0, 2));
        mx1 = fmaxf(mx1, __shfl_xor_sync(0xffffffffu, mx1, 1));
        mx1 = fmaxf(mx1, __shfl_xor_sync(0xffffffffu, mx1, 2));

        float mn0 = fmaxf(mr0, mx0), mn1 = fmaxf(mr1, mx1);
        float corr0 = exp2p(mr0 - mn0), corr1 = exp2p(mr1 - mn1);
        mr0 = mn0; mr1 = mn1;

        float sum0 = 0.f, sum1 = 0.f;
#pragma unroll
        for (int nf = 0; nf < 8; nf++) {
            sacc[nf][0] = exp2p(sacc[nf][0] - mn0);
            sacc[nf][1] = exp2p(sacc[nf][1] - mn0);
            sacc[nf][2] = exp2p(sacc[nf][2] - mn1);
            sacc[nf][3] = exp2p(sacc[nf][3] - mn1);
            sum0 += sacc[nf][0] + sacc[nf][1];
            sum1 += sacc[nf][2] + sacc[nf][3];
        }
        sum0 += __shfl_xor_sync(0xffffffffu, sum0, 1);
        sum0 += __shfl_xor_sync(0xffffffffu, sum0, 2);
        sum1 += __shfl_xor_sync(0xffffffffu, sum1, 1);
        sum1 += __shfl_xor_sync(0xffffffffu, sum1, 2);
        lr0 = lr0 * corr0 + sum0;
        lr1 = lr1 * corr1 + sum1;

#pragma unroll
        for (int nf = 0; nf < 16; nf++) {
            oacc[nf][0] *= corr0; oacc[nf][1] *= corr0;
            oacc[nf][2] *= corr1; oacc[nf][3] *= corr1;
        }

        // ---- pack P into fp16 hi/lo A-frags ----
        uint32_t ph[4][4], pl[4][4];
#pragma unroll
        for (int kc = 0; kc < 4; kc++) {
            pack2h(sacc[2 * kc][0],     sacc[2 * kc][1],     ph[kc][0], pl[kc][0]);
            pack2h(sacc[2 * kc][2],     sacc[2 * kc][3],     ph[kc][1], pl[kc][1]);
            pack2h(sacc[2 * kc + 1][0], sacc[2 * kc + 1][1], ph[kc][2], pl[kc][2]);
            pack2h(sacc[2 * kc + 1][2], sacc[2 * kc + 1][3], ph[kc][3], pl[kc][3]);
        }

        // ---- O += P V ----
#pragma unroll
        for (int ks2 = 0; ks2 < 4; ks2++) {
            int vrow = ks2 * 16 + (lane & 15);
#pragma unroll
            for (int g = 0; g < 8; g++) {
                int chunk = g * 2 + (lane >> 4);
                uint32_t off = sw256(vrow, chunk * 8);
                uint32_t vh[4];
                ldsm_x4_t(vh, vb + off);
                uint32_t vh0[2] = {vh[0], vh[1]}, vh1[2] = {vh[2], vh[3]};
                mma_f16(oacc[g * 2],     ph[ks2], vh0);
                mma_f16(oacc[g * 2],     pl[ks2], vh0);
                mma_f16(oacc[g * 2 + 1], ph[ks2], vh1);
                mma_f16(oacc[g * 2 + 1], pl[ks2], vh1);
            }
        }
    }

    // ---- epilogue: normalize + split-store bf16 hi/lo ----
    float inv0 = 1.0f / lr0;
    float inv1 = 1.0f / lr1;
    size_t row0 = rb + m0 + wid * 16 + (lane >> 2);
#pragma unroll
    for (int nf = 0; nf < 16; nf++) {
        int col = h * 128 + nf * 8 + (lane & 3) * 2;
        uint32_t hi, lo;
        pack2(oacc[nf][0] * inv0, oacc[nf][1] * inv0, hi, lo);
        *(uint32_t*)(g_attnh + row0 * 256 + col) = hi;
        *(uint32_t*)(g_attnl + row0 * 256 + col) = lo;
        pack2(oacc[nf][2] * inv1, oacc[nf][3] * inv1, hi, lo);
        *(uint32_t*)(g_attnh + (row0 + 8) * 256 + col) = hi;
        *(uint32_t*)(g_attnl + (row0 + 8) * 256 + col) = lo;
    }
}

// ---------------------------------------------------------------------------
extern "C" void kernel_launch(void* const* d_in, const int* in_sizes, int n_in,
                              void* d_out, int out_size)
{
    const float* x  = (const float*)d_in[0];
    const float* Wq = (const float*)d_in[1];
    const float* Wk = (const float*)d_in[2];
    const float* Wv = (const float*)d_in[3];
    const float* Wo = (const float*)d_in[4];

    const int BT = in_sizes[0] / DIM;  // 8192
    const int T  = T_SEQ;
    const int B  = BT / T;

    __nv_bfloat16 *xh, *xl, *attnh, *attnl, *wh, *wl, *woh, *wol;
    __half *q16h, *q16l, *k16, *v16;
    cudaGetSymbolAddress((void**)&xh,    g_xh);
    cudaGetSymbolAddress((void**)&xl,    g_xl);
    cudaGetSymbolAddress((void**)&q16h,  g_q16h);
    cudaGetSymbolAddress((void**)&q16l,  g_q16l);
    cudaGetSymbolAddress((void**)&k16,   g_k16);
    cudaGetSymbolAddress((void**)&v16,   g_v16);
    cudaGetSymbolAddress((void**)&attnh, g_attnh);
    cudaGetSymbolAddress((void**)&attnl, g_attnl);
    cudaGetSymbolAddress((void**)&wh,    g_wh);
    cudaGetSymbolAddress((void**)&wl,    g_wl);
    cudaGetSymbolAddress((void**)&woh,   g_woh);
    cudaGetSymbolAddress((void**)&wol,   g_wol);

    cudaFuncSetAttribute(gemm_bf16_kernel,
                         cudaFuncAttributeMaxDynamicSharedMemorySize, GEMM_SMEM);
    cudaFuncSetAttribute(attn_reg_kernel,
                         cudaFuncAttributeMaxDynamicSharedMemorySize, ATT2_SMEM);

    // 1) trig table + split x + concat/split weights
    {
        int tt = T_SEQ * 64;
        trig_kernel<<<(tt + 255) / 256, 256>>>();
        int tot = BT * DIM / 4;
        split_x_kernel<<<(tot + 255) / 256, 256>>>(x);
        int wt = 512 * DIM / 4 + DIM * 256 / 4;
        concat_w_kernel<<<(wt + 255) / 256, 256>>>(Wq, Wk, Wv, Wo);
    }

    // 2) fused QKV projection + rope + split epilogue
    {
        dim3 grid(BT / 128, 512 / 128);
        gemm_bf16_kernel<<<grid, 256, GEMM_SMEM>>>(xh, xl, wh, wl, nullptr,
                                                   BT, 512, DIM, 512, 1);
    }

    // 3) flash attention (all-fp16)
    {
        dim3 grid(T / 64, B * NKV);
        attn_reg_kernel<<<grid, 128, ATT2_SMEM>>>(q16h, q16l, k16, v16, T);
    }

    // 4) output projection
    {
        dim3 grid(BT / 128, DIM / 128);
        gemm_bf16_kernel<<<grid, 256, GEMM_SMEM>>>(attnh, attnl, woh, wol,
                                                   (float*)d_out, BT, DIM, 256,
                                                   DIM, 0);
    }
}

// round 8
// speedup vs baseline: 8.5095x; 1.2437x over previous
#include <cuda_runtime.h>
#include <cuda_bf16.h>
#include <cuda_fp16.h>
#include <math.h>
#include <float.h>
#include <stdint.h>

// Problem constants (fixed by reference setup_inputs)
#define DIM   1024
#define HS    128
#define NKV   2
#define T_SEQ 2048
#define BT_MAX 8192   // B*T = 4*2048

// ---------------- scratch (static device allocations; no cudaMalloc) -------
__device__ __half  g_xh   [BT_MAX * DIM];   // x fp16 hi
__device__ __half  g_xl   [BT_MAX * DIM];   // x fp16 lo residual
__device__ __half  g_q16h [BT_MAX * 256];   // rope'd+scaled Q, fp16 hi
__device__ __half  g_q16l [BT_MAX * 256];   // fp16 lo residual
__device__ __half  g_k16  [BT_MAX * 128];   // rope'd K, single fp16
__device__ __half  g_v16  [BT_MAX * 128];   // V, single fp16
__device__ __half  g_ath  [BT_MAX * 256];   // attention out fp16 hi
__device__ __half  g_atl  [BT_MAX * 256];   // attention out fp16 lo
__device__ __half  g_w16  [512 * DIM];      // Wcat single fp16
__device__ __half  g_wo16 [DIM * 256];      // Wo single fp16
__device__ float2  g_trig [T_SEQ * 64];     // (cos, sin) per (t, pair)

// ============================================================================
// helpers
// ============================================================================
__device__ __forceinline__ uint32_t smem_u32(const void* p) {
    uint32_t a;
    asm("{ .reg .u64 t; cvta.to.shared.u64 t, %1; cvt.u32.u64 %0, t; }"
        : "=r"(a) : "l"(p));
    return a;
}

__device__ __forceinline__ void mma_f16(float c[4], const uint32_t a[4],
                                        const uint32_t b[2]) {
    asm volatile(
        "mma.sync.aligned.m16n8k16.row.col.f32.f16.f16.f32 "
        "{%0,%1,%2,%3}, {%4,%5,%6,%7}, {%8,%9}, {%0,%1,%2,%3};"
        : "+f"(c[0]), "+f"(c[1]), "+f"(c[2]), "+f"(c[3])
        : "r"(a[0]), "r"(a[1]), "r"(a[2]), "r"(a[3]), "r"(b[0]), "r"(b[1]));
}

__device__ __forceinline__ void ldsm_x4(uint32_t r[4], uint32_t addr) {
    asm volatile("ldmatrix.sync.aligned.m8n8.x4.shared.b16 {%0,%1,%2,%3}, [%4];"
                 : "=r"(r[0]), "=r"(r[1]), "=r"(r[2]), "=r"(r[3]) : "r"(addr));
}
__device__ __forceinline__ void ldsm_x4_t(uint32_t r[4], uint32_t addr) {
    asm volatile("ldmatrix.sync.aligned.m8n8.x4.trans.shared.b16 {%0,%1,%2,%3}, [%4];"
                 : "=r"(r[0]), "=r"(r[1]), "=r"(r[2]), "=r"(r[3]) : "r"(addr));
}

#define CP_A16(dst, src) \
    asm volatile("cp.async.cg.shared.global [%0], [%1], 16;" \
                 :: "r"(dst), "l"(src) : "memory")
#define CP_COMMIT() asm volatile("cp.async.commit_group;" ::: "memory")
#define CP_WAIT0()  asm volatile("cp.async.wait_group 0;" ::: "memory")
#define CP_WAIT1()  asm volatile("cp.async.wait_group 1;" ::: "memory")

// fp16 hi/lo split of a scalar pair -> packed half2 words
__device__ __forceinline__ void pack2h(float x, float y, uint32_t& hi, uint32_t& lo) {
    __half2 h = __float22half2_rn(make_float2(x, y));
    __half2 l = __float22half2_rn(
        make_float2(x - __low2float(h), y - __high2float(h)));
    hi = *(uint32_t*)&h; lo = *(uint32_t*)&l;
}

__device__ __forceinline__ float exp2p(float y) {
    y = fmaxf(y, -125.0f);
    float t = y + 12582912.0f;
    float f = y - (t - 12582912.0f);
    float p = 0.0013333558f;
    p = fmaf(p, f, 0.0096181291f);
    p = fmaf(p, f, 0.055504109f);
    p = fmaf(p, f, 0.24022651f);
    p = fmaf(p, f, 0.69314718f);
    p = fmaf(p, f, 1.0f);
    return __int_as_float(__float_as_int(p) + (__float_as_int(t) << 23));
}

// Swizzle for 128-col 16-bit tiles (256B rows), 16B chunks (attention)
__device__ __forceinline__ uint32_t sw256(int row, int col) {
    int chunk = col >> 3;
    return (uint32_t)(row * 256 + (((chunk ^ (row & 7)) << 4) | ((col & 7) << 1)));
}
// Swizzle for 64-col fp16 tiles (128B rows), 8 chunks of 16B (GEMM)
__device__ __forceinline__ uint32_t sw128h(int row, int chunk) {
    return (uint32_t)(row * 128 + ((chunk ^ (row & 7)) << 4));
}

// ---------------------------------------------------------------------------
// trig table
// ---------------------------------------------------------------------------
__global__ void trig_kernel()
{
    int idx = blockIdx.x * blockDim.x + threadIdx.x;
    if (idx >= T_SEQ * 64) return;
    int t = idx >> 6, i = idx & 63;
    float theta = exp2f(-(float)i * (13.287712379549449f / 32.0f));
    float s, c;
    sincosf((float)t * theta, &s, &c);
    g_trig[idx] = make_float2(c, s);
}

// ---------------------------------------------------------------------------
// split_x: x fp32 -> fp16 hi/lo
// ---------------------------------------------------------------------------
__global__ void split_x_kernel(const float* __restrict__ x)
{
    int i = blockIdx.x * blockDim.x + threadIdx.x;
    const int TOT = BT_MAX * DIM / 4;
    if (i >= TOT) return;
    float4 v = ((const float4*)x)[i];
    uint2 hi, lo;
    pack2h(v.x, v.y, hi.x, lo.x);
    pack2h(v.z, v.w, hi.y, lo.y);
    *(uint2*)(g_xh + i * 4) = hi;
    *(uint2*)(g_xl + i * 4) = lo;
}

// ---------------------------------------------------------------------------
// Weight concat + fp16 convert
// ---------------------------------------------------------------------------
__global__ void concat_w_kernel(const float* __restrict__ Wq,
                                const float* __restrict__ Wk,
                                const float* __restrict__ Wv,
                                const float* __restrict__ Wo)
{
    int i = blockIdx.x * blockDim.x + threadIdx.x;
    const int WCAT4 = 512 * DIM / 4;
    const int WO4   = DIM * 256 / 4;
    if (i < WCAT4) {
        int row = i >> 8;
        float4 v;
        if (row < 256)       v = ((const float4*)Wq)[i];
        else if (row < 384)  v = ((const float4*)Wk)[i - 256 * 256];
        else                 v = ((const float4*)Wv)[i - 384 * 256];
        __half2 a = __float22half2_rn(make_float2(v.x, v.y));
        __half2 b = __float22half2_rn(make_float2(v.z, v.w));
        uint2 w; w.x = *(uint32_t*)&a; w.y = *(uint32_t*)&b;
        *(uint2*)(g_w16 + i * 4) = w;
    } else if (i < WCAT4 + WO4) {
        int j = i - WCAT4;
        float4 v = ((const float4*)Wo)[j];
        __half2 a = __float22half2_rn(make_float2(v.x, v.y));
        __half2 b = __float22half2_rn(make_float2(v.z, v.w));
        uint2 w; w.x = *(uint32_t*)&a; w.y = *(uint32_t*)&b;
        *(uint2*)(g_wo16 + j * 4) = w;
    }
}

// ---------------------------------------------------------------------------
// HMMA GEMM NT (2xFP16): C[M,N] = (Ah+Al)[M,K] * B16[N,K]^T.
// 128x128 CTA tile, BK=64, 256 threads (8 warps, 32x64 warp tiles),
// cp.async double-buffered. Stage s at s*49152: Ah +0, Al +16384, B +32768.
// 128B swizzled rows. epi=0: fp32 C. epi=1: fused rope+split epilogue.
// ---------------------------------------------------------------------------
#define GEMM_SMEM 98304

__device__ __forceinline__ void rope_epi_store(int r, int c, float x0, float x1)
{
    const float qscale = 0.08838834764831845f * 1.4426950408889634f;
    int t = r & (T_SEQ - 1);
    if (c < 384) {
        int i = (c & 127) >> 1;
        float2 cs = g_trig[t * 64 + i];
        float y0 = x0 * cs.x - x1 * cs.y;
        float y1 = x1 * cs.x + x0 * cs.y;
        if (c < 256) {
            y0 *= qscale; y1 *= qscale;
            uint32_t hi, lo;
            pack2h(y0, y1, hi, lo);
            *(uint32_t*)(g_q16h + (size_t)r * 256 + c) = hi;
            *(uint32_t*)(g_q16l + (size_t)r * 256 + c) = lo;
        } else {
            __half2 hh = __float22half2_rn(make_float2(y0, y1));
            *(uint32_t*)(g_k16 + (size_t)r * 128 + (c - 256)) = *(uint32_t*)&hh;
        }
    } else {
        __half2 hh = __float22half2_rn(make_float2(x0, x1));
        *(uint32_t*)(g_v16 + (size_t)r * 128 + (c - 384)) = *(uint32_t*)&hh;
    }
}

__global__ __launch_bounds__(256, 2)
void gemm_f16_kernel(const __half* __restrict__ Ah,
                     const __half* __restrict__ Al,
                     const __half* __restrict__ B16,
                     float* __restrict__ C, int M, int N, int K, int ldc,
                     int epi)
{
    extern __shared__ __align__(16) char smp[];
    const uint32_t sb = smem_u32(smp);

    const int tid = threadIdx.x;
    const int wid = tid >> 5;
    const int lane = tid & 31;
    const int m0 = blockIdx.x * 128;
    const int n0 = blockIdx.y * 128;
    const int wm = wid & 3;      // 4 warps over M (32 rows)
    const int wn = wid >> 2;     // 2 warps over N (64 cols)

    float acc[2][8][4];
#pragma unroll
    for (int mf = 0; mf < 2; mf++)
#pragma unroll
        for (int nf = 0; nf < 8; nf++)
#pragma unroll
            for (int q = 0; q < 4; q++) acc[mf][nf][q] = 0.f;

    const int KT = K >> 6;    // BK = 64

    auto fill = [&](int buf, int kt) {
        const uint32_t base = sb + buf * 49152;
#pragma unroll
        for (int i = 0; i < 4; i++) {
            int u = tid + i * 256;          // 0..1023
            int row = u >> 3, ch = u & 7;
            uint32_t off = sw128h(row, ch);
            size_t sA = (size_t)(m0 + row) * K + kt * 64 + ch * 8;
            size_t sB = (size_t)(n0 + row) * K + kt * 64 + ch * 8;
            CP_A16(base + off,         Ah  + sA);
            CP_A16(base + 16384 + off, Al  + sA);
            CP_A16(base + 32768 + off, B16 + sB);
        }
        CP_COMMIT();
    };

    fill(0, 0);

    for (int kt = 0; kt < KT; kt++) {
        const int buf = kt & 1;
        if (kt + 1 < KT) {
            fill(buf ^ 1, kt + 1);
            CP_WAIT1();
        } else {
            CP_WAIT0();
        }
        __syncthreads();

        const uint32_t ab = sb + buf * 49152;
        const uint32_t bb = ab + 32768;
#pragma unroll
        for (int ks = 0; ks < 4; ks++) {
            uint32_t ah[2][4], al[2][4];
#pragma unroll
            for (int mf = 0; mf < 2; mf++) {
                int row = wm * 32 + mf * 16 + (lane & 15);
                int chunk = ks * 2 + (lane >> 4);
                uint32_t ad = ab + sw128h(row, chunk);
                ldsm_x4(ah[mf], ad);
                ldsm_x4(al[mf], ad + 16384);
            }
            uint32_t bh[8][2];
#pragma unroll
            for (int np = 0; np < 4; np++) {
                int row = wn * 64 + np * 16 + ((lane >> 4) << 3) + (lane & 7);
                int chunk = ks * 2 + ((lane >> 3) & 1);
                uint32_t t[4];
                ldsm_x4(t, bb + sw128h(row, chunk));
                bh[np * 2][0] = t[0]; bh[np * 2][1] = t[1];
                bh[np * 2 + 1][0] = t[2]; bh[np * 2 + 1][1] = t[3];
            }
#pragma unroll
            for (int mf = 0; mf < 2; mf++)
#pragma unroll
                for (int nf = 0; nf < 8; nf++) {
                    mma_f16(acc[mf][nf], ah[mf], bh[nf]);
                    mma_f16(acc[mf][nf], al[mf], bh[nf]);
                }
        }
        __syncthreads();
    }

    if (epi == 0) {
#pragma unroll
        for (int mf = 0; mf < 2; mf++)
#pragma unroll
            for (int nf = 0; nf < 8; nf++) {
                int row = m0 + wm * 32 + mf * 16 + (lane >> 2);
                int col = n0 + wn * 64 + nf * 8 + (lane & 3) * 2;
                *(float2*)(C + (size_t)row * ldc + col) =
                    make_float2(acc[mf][nf][0], acc[mf][nf][1]);
                *(float2*)(C + (size_t)(row + 8) * ldc + col) =
                    make_float2(acc[mf][nf][2], acc[mf][nf][3]);
            }
    } else {
#pragma unroll
        for (int mf = 0; mf < 2; mf++)
#pragma unroll
            for (int nf = 0; nf < 8; nf++) {
                int row = m0 + wm * 32 + mf * 16 + (lane >> 2);
                int col = n0 + wn * 64 + nf * 8 + (lane & 3) * 2;
                rope_epi_store(row,     col, acc[mf][nf][0], acc[mf][nf][1]);
                rope_epi_store(row + 8, col, acc[mf][nf][2], acc[mf][nf][3]);
            }
    }
}

// ---------------------------------------------------------------------------
// Flash attention, all-fp16 MMA (unchanged core from R7). Output fp16 hi/lo.
// ---------------------------------------------------------------------------
#define ATT2_SMEM 65536

__global__ __launch_bounds__(128, 2)
void attn_reg_kernel(const __half* __restrict__ qh_g,
                     const __half* __restrict__ ql_g,
                     const __half* __restrict__ k_g,
                     const __half* __restrict__ v_g, int T)
{
    extern __shared__ __align__(16) char smp[];
    const uint32_t sb = smem_u32(smp);

    const int tid = threadIdx.x;
    const int wid = tid >> 5;
    const int lane = tid & 31;
    const int bh = blockIdx.y;
    const int b  = bh >> 1;
    const int h  = bh & 1;

    const int bx = blockIdx.x;
    const int oo = bx & 3;
    const int qq = bx >> 2;
    const int pp = (qq & 1) ? (qq ^ 4) : qq;
    const int mt = (pp & 1) ? (4 * oo + (pp >> 1)) : (31 - 4 * oo - (pp >> 1));
    const int m0 = mt * 64;

    const size_t rb = (size_t)b * T;

    // ---- stage Q (hi at 0, lo at 16384), extract frags ----
#pragma unroll
    for (int i = 0; i < 8; i++) {
        int u = tid + i * 128;
        int row = u >> 4, ch = u & 15;
        uint32_t off = sw256(row, ch * 8);
        size_t src = (rb + m0 + row) * 256 + h * 128 + ch * 8;
        CP_A16(sb + off,         qh_g + src);
        CP_A16(sb + 16384 + off, ql_g + src);
    }
    CP_COMMIT();
    CP_WAIT0();
    __syncthreads();

    uint32_t qfh[8][4], qfl[8][4];
#pragma unroll
    for (int ks = 0; ks < 8; ks++) {
        int row = wid * 16 + (lane & 15);
        int chunk = ks * 2 + (lane >> 4);
        uint32_t off = sw256(row, chunk * 8);
        ldsm_x4(qfh[ks], sb + off);
        ldsm_x4(qfl[ks], sb + 16384 + off);
    }
    __syncthreads();

    auto fillKV = [&](int buf, int j) {
        const uint32_t kb = sb + buf * 16384;
        const uint32_t vb = sb + 32768 + buf * 16384;
        const int n0v = j * 64;
#pragma unroll
        for (int i = 0; i < 8; i++) {
            int u = tid + i * 128;
            int row = u >> 4, ch = u & 15;
            uint32_t off = sw256(row, ch * 8);
            size_t src = (size_t)(rb + n0v + row) * 128 + ch * 8;
            CP_A16(kb + off, k_g + src);
            CP_A16(vb + off, v_g + src);
        }
        CP_COMMIT();
    };

    fillKV(0, 0);

    float mr0 = -1e30f, mr1 = -1e30f, lr0 = 0.f, lr1 = 0.f;
    float oacc[16][4];
#pragma unroll
    for (int nf = 0; nf < 16; nf++)
#pragma unroll
        for (int q = 0; q < 4; q++) oacc[nf][q] = 0.f;

    for (int j = 0; j <= mt; j++) {
        const int cur = j & 1;
        const int n0v = j * 64;

        __syncthreads();
        if (j < mt) {
            fillKV(cur ^ 1, j + 1);
            CP_WAIT1();
        } else {
            CP_WAIT0();
        }
        __syncthreads();

        const uint32_t kb = sb + cur * 16384;
        const uint32_t vb = sb + 32768 + cur * 16384;

        float sacc[8][4];
#pragma unroll
        for (int nf = 0; nf < 8; nf++)
#pragma unroll
            for (int q = 0; q < 4; q++) sacc[nf][q] = 0.f;

#pragma unroll
        for (int ks = 0; ks < 8; ks++) {
#pragma unroll
            for (int ng = 0; ng < 4; ng++) {
                int row = ng * 16 + ((lane >> 4) << 3) + (lane & 7);
                int chunk = ks * 2 + ((lane >> 3) & 1);
                uint32_t off = sw256(row, chunk * 8);
                uint32_t t[4];
                ldsm_x4(t, kb + off);
                uint32_t b0[2] = {t[0], t[1]}, b1[2] = {t[2], t[3]};
                mma_f16(sacc[ng * 2],     qfh[ks], b0);
                mma_f16(sacc[ng * 2],     qfl[ks], b0);
                mma_f16(sacc[ng * 2 + 1], qfh[ks], b1);
                mma_f16(sacc[ng * 2 + 1], qfl[ks], b1);
            }
        }

        if (j == mt) {
            int grow0 = m0 + wid * 16 + (lane >> 2);
            int grow1 = grow0 + 8;
            int cbase = n0v + (lane & 3) * 2;
#pragma unroll
            for (int nf = 0; nf < 8; nf++) {
                int c = cbase + nf * 8;
                if (c     > grow0) sacc[nf][0] = -1e30f;
                if (c + 1 > grow0) sacc[nf][1] = -1e30f;
                if (c     > grow1) sacc[nf][2] = -1e30f;
                if (c + 1 > grow1) sacc[nf][3] = -1e30f;
            }
        }

        float mx0 = -1e30f, mx1 = -1e30f;
#pragma unroll
        for (int nf = 0; nf < 8; nf++) {
            mx0 = fmaxf(mx0, fmaxf(sacc[nf][0], sacc[nf][1]));
            mx1 = fmaxf(mx1, fmaxf(sacc[nf][2], sacc[nf][3]));
        }
        mx0 = fmaxf(mx0, __shfl_xor_sync(0xffffffffu, mx0, 1));
        mx0 = fmaxf(mx0, __shfl_xor_sync(0xffffffffu, mx0, 2));
        mx1 = fmaxf(mx1, __shfl_xor_sync(0xffffffffu, mx1, 1));
        mx1 = fmaxf(mx1, __shfl_xor_sync(0xffffffffu, mx1, 2));

        float mn0 = fmaxf(mr0, mx0), mn1 = fmaxf(mr1, mx1);
        float corr0 = exp2p(mr0 - mn0), corr1 = exp2p(mr1 - mn1);
        mr0 = mn0; mr1 = mn1;

        float sum0 = 0.f, sum1 = 0.f;
#pragma unroll
        for (int nf = 0; nf < 8; nf++) {
            sacc[nf][0] = exp2p(sacc[nf][0] - mn0);
            sacc[nf][1] = exp2p(sacc[nf][1] - mn0);
            sacc[nf][2] = exp2p(sacc[nf][2] - mn1);
            sacc[nf][3] = exp2p(sacc[nf][3] - mn1);
            sum0 += sacc[nf][0] + sacc[nf][1];
            sum1 += sacc[nf][2] + sacc[nf][3];
        }
        sum0 += __shfl_xor_sync(0xffffffffu, sum0, 1);
        sum0 += __shfl_xor_sync(0xffffffffu, sum0, 2);
        sum1 += __shfl_xor_sync(0xffffffffu, sum1, 1);
        sum1 += __shfl_xor_sync(0xffffffffu, sum1, 2);
        lr0 = lr0 * corr0 + sum0;
        lr1 = lr1 * corr1 + sum1;

#pragma unroll
        for (int nf = 0; nf < 16; nf++) {
            oacc[nf][0] *= corr0; oacc[nf][1] *= corr0;
            oacc[nf][2] *= corr1; oacc[nf][3] *= corr1;
        }

        uint32_t ph[4][4], pl[4][4];
#pragma unroll
        for (int kc = 0; kc < 4; kc++) {
            pack2h(sacc[2 * kc][0],     sacc[2 * kc][1],     ph[kc][0], pl[kc][0]);
            pack2h(sacc[2 * kc][2],     sacc[2 * kc][3],     ph[kc][1], pl[kc][1]);
            pack2h(sacc[2 * kc + 1][0], sacc[2 * kc + 1][1], ph[kc][2], pl[kc][2]);
            pack2h(sacc[2 * kc + 1][2], sacc[2 * kc + 1][3], ph[kc][3], pl[kc][3]);
        }

#pragma unroll
        for (int ks2 = 0; ks2 < 4; ks2++) {
            int vrow = ks2 * 16 + (lane & 15);
#pragma unroll
            for (int g = 0; g < 8; g++) {
                int chunk = g * 2 + (lane >> 4);
                uint32_t off = sw256(vrow, chunk * 8);
                uint32_t vh[4];
                ldsm_x4_t(vh, vb + off);
                uint32_t vh0[2] = {vh[0], vh[1]}, vh1[2] = {vh[2], vh[3]};
                mma_f16(oacc[g * 2],     ph[ks2], vh0);
                mma_f16(oacc[g * 2],     pl[ks2], vh0);
                mma_f16(oacc[g * 2 + 1], ph[ks2], vh1);
                mma_f16(oacc[g * 2 + 1], pl[ks2], vh1);
            }
        }
    }

    // ---- epilogue: normalize + fp16 hi/lo store ----
    float inv0 = 1.0f / lr0;
    float inv1 = 1.0f / lr1;
    size_t row0 = rb + m0 + wid * 16 + (lane >> 2);
#pragma unroll
    for (int nf = 0; nf < 16; nf++) {
        int col = h * 128 + nf * 8 + (lane & 3) * 2;
        uint32_t hi, lo;
        pack2h(oacc[nf][0] * inv0, oacc[nf][1] * inv0, hi, lo);
        *(uint32_t*)(g_ath + row0 * 256 + col) = hi;
        *(uint32_t*)(g_atl + row0 * 256 + col) = lo;
        pack2h(oacc[nf][2] * inv1, oacc[nf][3] * inv1, hi, lo);
        *(uint32_t*)(g_ath + (row0 + 8) * 256 + col) = hi;
        *(uint32_t*)(g_atl + (row0 + 8) * 256 + col) = lo;
    }
}

// ---------------------------------------------------------------------------
extern "C" void kernel_launch(void* const* d_in, const int* in_sizes, int n_in,
                              void* d_out, int out_size)
{
    const float* x  = (const float*)d_in[0];
    const float* Wq = (const float*)d_in[1];
    const float* Wk = (const float*)d_in[2];
    const float* Wv = (const float*)d_in[3];
    const float* Wo = (const float*)d_in[4];

    const int BT = in_sizes[0] / DIM;  // 8192
    const int T  = T_SEQ;
    const int B  = BT / T;

    __half *xh, *xl, *q16h, *q16l, *k16, *v16, *ath, *atl, *w16, *wo16;
    cudaGetSymbolAddress((void**)&xh,   g_xh);
    cudaGetSymbolAddress((void**)&xl,   g_xl);
    cudaGetSymbolAddress((void**)&q16h, g_q16h);
    cudaGetSymbolAddress((void**)&q16l, g_q16l);
    cudaGetSymbolAddress((void**)&k16,  g_k16);
    cudaGetSymbolAddress((void**)&v16,  g_v16);
    cudaGetSymbolAddress((void**)&ath,  g_ath);
    cudaGetSymbolAddress((void**)&atl,  g_atl);
    cudaGetSymbolAddress((void**)&w16,  g_w16);
    cudaGetSymbolAddress((void**)&wo16, g_wo16);

    cudaFuncSetAttribute(gemm_f16_kernel,
                         cudaFuncAttributeMaxDynamicSharedMemorySize, GEMM_SMEM);
    cudaFuncSetAttribute(attn_reg_kernel,
                         cudaFuncAttributeMaxDynamicSharedMemorySize, ATT2_SMEM);

    // 1) trig table + split x + concat/convert weights
    {
        int tt = T_SEQ * 64;
        trig_kernel<<<(tt + 255) / 256, 256>>>();
        int tot = BT * DIM / 4;
        split_x_kernel<<<(tot + 255) / 256, 256>>>(x);
        int wt = 512 * DIM / 4 + DIM * 256 / 4;
        concat_w_kernel<<<(wt + 255) / 256, 256>>>(Wq, Wk, Wv, Wo);
    }

    // 2) fused QKV projection + rope + split epilogue
    {
        dim3 grid(BT / 128, 512 / 128);
        gemm_f16_kernel<<<grid, 256, GEMM_SMEM>>>(xh, xl, w16, nullptr,
                                                  BT, 512, DIM, 512, 1);
    }

    // 3) flash attention (all-fp16)
    {
        dim3 grid(T / 64, B * NKV);
        attn_reg_kernel<<<grid, 128, ATT2_SMEM>>>(q16h, q16l, k16, v16, T);
    }

    // 4) output projection
    {
        dim3 grid(BT / 128, DIM / 128);
        gemm_f16_kernel<<<grid, 256, GEMM_SMEM>>>(ath, atl, wo16,
                                                  (float*)d_out, BT, DIM, 256,
                                                  DIM, 0);
    }
}

// round 9
// speedup vs baseline: 9.0209x; 1.0601x over previous
#include <cuda_runtime.h>
#include <cuda_bf16.h>
#include <cuda_fp16.h>
#include <math.h>
#include <float.h>
#include <stdint.h>

// Problem constants (fixed by reference setup_inputs)
#define DIM   1024
#define HS    128
#define NKV   2
#define T_SEQ 2048
#define BT_MAX 8192   // B*T = 4*2048

// ---------------- scratch (static device allocations; no cudaMalloc) -------
__device__ __half  g_xh   [BT_MAX * DIM];   // x fp16 hi
__device__ __half  g_xl   [BT_MAX * DIM];   // x fp16 lo residual
__device__ __half  g_q16h [BT_MAX * 256];   // rope'd+scaled Q, fp16 hi
__device__ __half  g_q16l [BT_MAX * 256];   // fp16 lo residual
__device__ __half  g_k16  [BT_MAX * 128];   // rope'd K, single fp16
__device__ __half  g_v16  [BT_MAX * 128];   // V, single fp16
__device__ __half  g_ath  [BT_MAX * 256];   // attention out fp16 hi
__device__ __half  g_atl  [BT_MAX * 256];   // attention out fp16 lo
__device__ __half  g_w16  [512 * DIM];      // Wcat single fp16
__device__ __half  g_wo16 [DIM * 256];      // Wo single fp16
__device__ float2  g_trig [T_SEQ * 64];     // (cos, sin) per (t, pair)

// ============================================================================
// helpers
// ============================================================================
__device__ __forceinline__ uint32_t smem_u32(const void* p) {
    uint32_t a;
    asm("{ .reg .u64 t; cvta.to.shared.u64 t, %1; cvt.u32.u64 %0, t; }"
        : "=r"(a) : "l"(p));
    return a;
}

__device__ __forceinline__ void mma_f16(float c[4], const uint32_t a[4],
                                        const uint32_t b[2]) {
    asm volatile(
        "mma.sync.aligned.m16n8k16.row.col.f32.f16.f16.f32 "
        "{%0,%1,%2,%3}, {%4,%5,%6,%7}, {%8,%9}, {%0,%1,%2,%3};"
        : "+f"(c[0]), "+f"(c[1]), "+f"(c[2]), "+f"(c[3])
        : "r"(a[0]), "r"(a[1]), "r"(a[2]), "r"(a[3]), "r"(b[0]), "r"(b[1]));
}

__device__ __forceinline__ void ldsm_x4(uint32_t r[4], uint32_t addr) {
    asm volatile("ldmatrix.sync.aligned.m8n8.x4.shared.b16 {%0,%1,%2,%3}, [%4];"
                 : "=r"(r[0]), "=r"(r[1]), "=r"(r[2]), "=r"(r[3]) : "r"(addr));
}
__device__ __forceinline__ void ldsm_x4_t(uint32_t r[4], uint32_t addr) {
    asm volatile("ldmatrix.sync.aligned.m8n8.x4.trans.shared.b16 {%0,%1,%2,%3}, [%4];"
                 : "=r"(r[0]), "=r"(r[1]), "=r"(r[2]), "=r"(r[3]) : "r"(addr));
}

#define CP_A16(dst, src) \
    asm volatile("cp.async.cg.shared.global [%0], [%1], 16;" \
                 :: "r"(dst), "l"(src) : "memory")
#define CP_COMMIT() asm volatile("cp.async.commit_group;" ::: "memory")
#define CP_WAIT0()  asm volatile("cp.async.wait_group 0;" ::: "memory")

// fp16 hi/lo split of a scalar pair -> packed half2 words
__device__ __forceinline__ void pack2h(float x, float y, uint32_t& hi, uint32_t& lo) {
    __half2 h = __float22half2_rn(make_float2(x, y));
    __half2 l = __float22half2_rn(
        make_float2(x - __low2float(h), y - __high2float(h)));
    hi = *(uint32_t*)&h; lo = *(uint32_t*)&l;
}

__device__ __forceinline__ float exp2p(float y) {
    y = fmaxf(y, -125.0f);
    float t = y + 12582912.0f;
    float f = y - (t - 12582912.0f);
    float p = 0.0013333558f;
    p = fmaf(p, f, 0.0096181291f);
    p = fmaf(p, f, 0.055504109f);
    p = fmaf(p, f, 0.24022651f);
    p = fmaf(p, f, 0.69314718f);
    p = fmaf(p, f, 1.0f);
    return __int_as_float(__float_as_int(p) + (__float_as_int(t) << 23));
}

// Swizzle for 128-col 16-bit tiles (256B rows), 16B chunks (attention)
__device__ __forceinline__ uint32_t sw256(int row, int col) {
    int chunk = col >> 3;
    return (uint32_t)(row * 256 + (((chunk ^ (row & 7)) << 4) | ((col & 7) << 1)));
}
// Swizzle for 64-col fp16 tiles (128B rows), 8 chunks of 16B (GEMM)
__device__ __forceinline__ uint32_t sw128h(int row, int chunk) {
    return (uint32_t)(row * 128 + ((chunk ^ (row & 7)) << 4));
}

// ---------------------------------------------------------------------------
// split_x: x fp32 -> fp16 hi/lo
// ---------------------------------------------------------------------------
__global__ void split_x_kernel(const float* __restrict__ x)
{
    int i = blockIdx.x * blockDim.x + threadIdx.x;
    const int TOT = BT_MAX * DIM / 4;
    if (i >= TOT) return;
    float4 v = ((const float4*)x)[i];
    uint2 hi, lo;
    pack2h(v.x, v.y, hi.x, lo.x);
    pack2h(v.z, v.w, hi.y, lo.y);
    *(uint2*)(g_xh + i * 4) = hi;
    *(uint2*)(g_xl + i * 4) = lo;
}

// ---------------------------------------------------------------------------
// Weight concat + fp16 convert + trig table (one launch)
// ---------------------------------------------------------------------------
__global__ void prep_kernel(const float* __restrict__ Wq,
                            const float* __restrict__ Wk,
                            const float* __restrict__ Wv,
                            const float* __restrict__ Wo)
{
    int i = blockIdx.x * blockDim.x + threadIdx.x;
    const int WCAT4 = 512 * DIM / 4;
    const int WO4   = DIM * 256 / 4;
    const int TRIG  = T_SEQ * 64;
    if (i < WCAT4) {
        int row = i >> 8;
        float4 v;
        if (row < 256)       v = ((const float4*)Wq)[i];
        else if (row < 384)  v = ((const float4*)Wk)[i - 256 * 256];
        else                 v = ((const float4*)Wv)[i - 384 * 256];
        __half2 a = __float22half2_rn(make_float2(v.x, v.y));
        __half2 b = __float22half2_rn(make_float2(v.z, v.w));
        uint2 w; w.x = *(uint32_t*)&a; w.y = *(uint32_t*)&b;
        *(uint2*)(g_w16 + i * 4) = w;
    } else if (i < WCAT4 + WO4) {
        int j = i - WCAT4;
        float4 v = ((const float4*)Wo)[j];
        __half2 a = __float22half2_rn(make_float2(v.x, v.y));
        __half2 b = __float22half2_rn(make_float2(v.z, v.w));
        uint2 w; w.x = *(uint32_t*)&a; w.y = *(uint32_t*)&b;
        *(uint2*)(g_wo16 + j * 4) = w;
    } else if (i < WCAT4 + WO4 + TRIG) {
        int j = i - WCAT4 - WO4;
        int t = j >> 6, k = j & 63;
        float theta = exp2f(-(float)k * (13.287712379549449f / 32.0f));
        float s, c;
        sincosf((float)t * theta, &s, &c);
        g_trig[j] = make_float2(c, s);
    }
}

// ---------------------------------------------------------------------------
// HMMA GEMM NT (2xFP16): C[M,N] = (Ah+Al)[M,K] * B16[N,K]^T.
// 128x128 CTA tile, BK=64, 256 threads (8 warps, 32x64 warp tiles),
// cp.async double-buffered, SINGLE barrier per iteration:
//   wait_group 0 -> __syncthreads -> fill(kt+1) -> compute(kt)
// Stage s at s*49152: Ah +0, Al +16384, B +32768. 128B swizzled rows.
// epi=0: fp32 C. epi=1: fused rope+split epilogue.
// ---------------------------------------------------------------------------
#define GEMM_SMEM 98304

__device__ __forceinline__ void rope_epi_store(int r, int c, float x0, float x1)
{
    const float qscale = 0.08838834764831845f * 1.4426950408889634f;
    int t = r & (T_SEQ - 1);
    if (c < 384) {
        int i = (c & 127) >> 1;
        float2 cs = g_trig[t * 64 + i];
        float y0 = x0 * cs.x - x1 * cs.y;
        float y1 = x1 * cs.x + x0 * cs.y;
        if (c < 256) {
            y0 *= qscale; y1 *= qscale;
            uint32_t hi, lo;
            pack2h(y0, y1, hi, lo);
            *(uint32_t*)(g_q16h + (size_t)r * 256 + c) = hi;
            *(uint32_t*)(g_q16l + (size_t)r * 256 + c) = lo;
        } else {
            __half2 hh = __float22half2_rn(make_float2(y0, y1));
            *(uint32_t*)(g_k16 + (size_t)r * 128 + (c - 256)) = *(uint32_t*)&hh;
        }
    } else {
        __half2 hh = __float22half2_rn(make_float2(x0, x1));
        *(uint32_t*)(g_v16 + (size_t)r * 128 + (c - 384)) = *(uint32_t*)&hh;
    }
}

__global__ __launch_bounds__(256, 2)
void gemm_f16_kernel(const __half* __restrict__ Ah,
                     const __half* __restrict__ Al,
                     const __half* __restrict__ B16,
                     float* __restrict__ C, int M, int N, int K, int ldc,
                     int epi)
{
    extern __shared__ __align__(16) char smp[];
    const uint32_t sb = smem_u32(smp);

    const int tid = threadIdx.x;
    const int wid = tid >> 5;
    const int lane = tid & 31;
    const int m0 = blockIdx.x * 128;
    const int n0 = blockIdx.y * 128;
    const int wm = wid & 3;      // 4 warps over M (32 rows)
    const int wn = wid >> 2;     // 2 warps over N (64 cols)

    float acc[2][8][4];
#pragma unroll
    for (int mf = 0; mf < 2; mf++)
#pragma unroll
        for (int nf = 0; nf < 8; nf++)
#pragma unroll
            for (int q = 0; q < 4; q++) acc[mf][nf][q] = 0.f;

    const int KT = K >> 6;    // BK = 64

    auto fill = [&](int buf, int kt) {
        const uint32_t base = sb + buf * 49152;
#pragma unroll
        for (int i = 0; i < 4; i++) {
            int u = tid + i * 256;          // 0..1023
            int row = u >> 3, ch = u & 7;
            uint32_t off = sw128h(row, ch);
            size_t sA = (size_t)(m0 + row) * K + kt * 64 + ch * 8;
            size_t sB = (size_t)(n0 + row) * K + kt * 64 + ch * 8;
            CP_A16(base + off,         Ah  + sA);
            CP_A16(base + 16384 + off, Al  + sA);
            CP_A16(base + 32768 + off, B16 + sB);
        }
        CP_COMMIT();
    };

    fill(0, 0);

    for (int kt = 0; kt < KT; kt++) {
        const int buf = kt & 1;
        CP_WAIT0();          // fill(kt) locally complete
        __syncthreads();     // publish fill(kt); all warps done with buf^1
        if (kt + 1 < KT) fill(buf ^ 1, kt + 1);   // overlaps compute below

        const uint32_t ab = sb + buf * 49152;
        const uint32_t bb = ab + 32768;
#pragma unroll
        for (int ks = 0; ks < 4; ks++) {
            uint32_t ah[2][4], al[2][4];
#pragma unroll
            for (int mf = 0; mf < 2; mf++) {
                int row = wm * 32 + mf * 16 + (lane & 15);
                int chunk = ks * 2 + (lane >> 4);
                uint32_t ad = ab + sw128h(row, chunk);
                ldsm_x4(ah[mf], ad);
                ldsm_x4(al[mf], ad + 16384);
            }
            uint32_t bh[8][2];
#pragma unroll
            for (int np = 0; np < 4; np++) {
                int row = wn * 64 + np * 16 + ((lane >> 4) << 3) + (lane & 7);
                int chunk = ks * 2 + ((lane >> 3) & 1);
                uint32_t t[4];
                ldsm_x4(t, bb + sw128h(row, chunk));
                bh[np * 2][0] = t[0]; bh[np * 2][1] = t[1];
                bh[np * 2 + 1][0] = t[2]; bh[np * 2 + 1][1] = t[3];
            }
#pragma unroll
            for (int mf = 0; mf < 2; mf++)
#pragma unroll
                for (int nf = 0; nf < 8; nf++) {
                    mma_f16(acc[mf][nf], ah[mf], bh[nf]);
                    mma_f16(acc[mf][nf], al[mf], bh[nf]);
                }
        }
    }

    if (epi == 0) {
#pragma unroll
        for (int mf = 0; mf < 2; mf++)
#pragma unroll
            for (int nf = 0; nf < 8; nf++) {
                int row = m0 + wm * 32 + mf * 16 + (lane >> 2);
                int col = n0 + wn * 64 + nf * 8 + (lane & 3) * 2;
                *(float2*)(C + (size_t)row * ldc + col) =
                    make_float2(acc[mf][nf][0], acc[mf][nf][1]);
                *(float2*)(C + (size_t)(row + 8) * ldc + col) =
                    make_float2(acc[mf][nf][2], acc[mf][nf][3]);
            }
    } else {
#pragma unroll
        for (int mf = 0; mf < 2; mf++)
#pragma unroll
            for (int nf = 0; nf < 8; nf++) {
                int row = m0 + wm * 32 + mf * 16 + (lane >> 2);
                int col = n0 + wn * 64 + nf * 8 + (lane & 3) * 2;
                rope_epi_store(row,     col, acc[mf][nf][0], acc[mf][nf][1]);
                rope_epi_store(row + 8, col, acc[mf][nf][2], acc[mf][nf][3]);
            }
    }
}

// ---------------------------------------------------------------------------
// Flash attention, all-fp16 MMA, single barrier per tile:
//   wait_group 0 -> __syncthreads -> fillKV(j+1) -> compute(j)
// K buf b at b*16384; V buf b at 32768 + b*16384. Q staged in 0..32767.
// ---------------------------------------------------------------------------
#define ATT2_SMEM 65536

__global__ __launch_bounds__(128, 2)
void attn_reg_kernel(const __half* __restrict__ qh_g,
                     const __half* __restrict__ ql_g,
                     const __half* __restrict__ k_g,
                     const __half* __restrict__ v_g, int T)
{
    extern __shared__ __align__(16) char smp[];
    const uint32_t sb = smem_u32(smp);

    const int tid = threadIdx.x;
    const int wid = tid >> 5;
    const int lane = tid & 31;
    const int bh = blockIdx.y;
    const int b  = bh >> 1;
    const int h  = bh & 1;

    const int bx = blockIdx.x;
    const int oo = bx & 3;
    const int qq = bx >> 2;
    const int pp = (qq & 1) ? (qq ^ 4) : qq;
    const int mt = (pp & 1) ? (4 * oo + (pp >> 1)) : (31 - 4 * oo - (pp >> 1));
    const int m0 = mt * 64;

    const size_t rb = (size_t)b * T;

    // ---- stage Q (hi at 0, lo at 16384), extract frags ----
#pragma unroll
    for (int i = 0; i < 8; i++) {
        int u = tid + i * 128;
        int row = u >> 4, ch = u & 15;
        uint32_t off = sw256(row, ch * 8);
        size_t src = (rb + m0 + row) * 256 + h * 128 + ch * 8;
        CP_A16(sb + off,         qh_g + src);
        CP_A16(sb + 16384 + off, ql_g + src);
    }
    CP_COMMIT();
    CP_WAIT0();
    __syncthreads();

    uint32_t qfh[8][4], qfl[8][4];
#pragma unroll
    for (int ks = 0; ks < 8; ks++) {
        int row = wid * 16 + (lane & 15);
        int chunk = ks * 2 + (lane >> 4);
        uint32_t off = sw256(row, chunk * 8);
        ldsm_x4(qfh[ks], sb + off);
        ldsm_x4(qfl[ks], sb + 16384 + off);
    }
    __syncthreads();   // Q reads done before K0 overwrites

    auto fillKV = [&](int buf, int j) {
        const uint32_t kb = sb + buf * 16384;
        const uint32_t vb = sb + 32768 + buf * 16384;
        const int n0v = j * 64;
#pragma unroll
        for (int i = 0; i < 8; i++) {
            int u = tid + i * 128;
            int row = u >> 4, ch = u & 15;
            uint32_t off = sw256(row, ch * 8);
            size_t src = (size_t)(rb + n0v + row) * 128 + ch * 8;
            CP_A16(kb + off, k_g + src);
            CP_A16(vb + off, v_g + src);
        }
        CP_COMMIT();
    };

    fillKV(0, 0);

    float mr0 = -1e30f, mr1 = -1e30f, lr0 = 0.f, lr1 = 0.f;
    float oacc[16][4];
#pragma unroll
    for (int nf = 0; nf < 16; nf++)
#pragma unroll
        for (int q = 0; q < 4; q++) oacc[nf][q] = 0.f;

    for (int j = 0; j <= mt; j++) {
        const int cur = j & 1;
        const int n0v = j * 64;

        CP_WAIT0();         // fillKV(j) locally complete
        __syncthreads();    // publish; all warps done with buf cur^1
        if (j < mt) fillKV(cur ^ 1, j + 1);   // overlaps compute below

        const uint32_t kb = sb + cur * 16384;
        const uint32_t vb = sb + 32768 + cur * 16384;

        // ---- S = Q K^T (fp16) ----
        float sacc[8][4];
#pragma unroll
        for (int nf = 0; nf < 8; nf++)
#pragma unroll
            for (int q = 0; q < 4; q++) sacc[nf][q] = 0.f;

#pragma unroll
        for (int ks = 0; ks < 8; ks++) {
#pragma unroll
            for (int ng = 0; ng < 4; ng++) {
                int row = ng * 16 + ((lane >> 4) << 3) + (lane & 7);
                int chunk = ks * 2 + ((lane >> 3) & 1);
                uint32_t off = sw256(row, chunk * 8);
                uint32_t t[4];
                ldsm_x4(t, kb + off);
                uint32_t b0[2] = {t[0], t[1]}, b1[2] = {t[2], t[3]};
                mma_f16(sacc[ng * 2],     qfh[ks], b0);
                mma_f16(sacc[ng * 2],     qfl[ks], b0);
                mma_f16(sacc[ng * 2 + 1], qfh[ks], b1);
                mma_f16(sacc[ng * 2 + 1], qfl[ks], b1);
            }
        }

        // ---- causal mask (diagonal tile only) ----
        if (j == mt) {
            int grow0 = m0 + wid * 16 + (lane >> 2);
            int grow1 = grow0 + 8;
            int cbase = n0v + (lane & 3) * 2;
#pragma unroll
            for (int nf = 0; nf < 8; nf++) {
                int c = cbase + nf * 8;
                if (c     > grow0) sacc[nf][0] = -1e30f;
                if (c + 1 > grow0) sacc[nf][1] = -1e30f;
                if (c     > grow1) sacc[nf][2] = -1e30f;
                if (c + 1 > grow1) sacc[nf][3] = -1e30f;
            }
        }

        // ---- register softmax (exp2 domain) ----
        float mx0 = -1e30f, mx1 = -1e30f;
#pragma unroll
        for (int nf = 0; nf < 8; nf++) {
            mx0 = fmaxf(mx0, fmaxf(sacc[nf][0], sacc[nf][1]));
            mx1 = fmaxf(mx1, fmaxf(sacc[nf][2], sacc[nf][3]));
        }
        mx0 = fmaxf(mx0, __shfl_xor_sync(0xffffffffu, mx0, 1));
        mx0 = fmaxf(mx0, __shfl_xor_sync(0xffffffffu, mx0, 2));
        mx1 = fmaxf(mx1, __shfl_xor_sync(0xffffffffu, mx1, 1));
        mx1 = fmaxf(mx1, __shfl_xor_sync(0xffffffffu, mx1, 2));

        float mn0 = fmaxf(mr0, mx0), mn1 = fmaxf(mr1, mx1);
        float corr0 = exp2p(mr0 - mn0), corr1 = exp2p(mr1 - mn1);
        mr0 = mn0; mr1 = mn1;

        float sum0 = 0.f, sum1 = 0.f;
#pragma unroll
        for (int nf = 0; nf < 8; nf++) {
            sacc[nf][0] = exp2p(sacc[nf][0] - mn0);
            sacc[nf][1] = exp2p(sacc[nf][1] - mn0);
            sacc[nf][2] = exp2p(sacc[nf][2] - mn1);
            sacc[nf][3] = exp2p(sacc[nf][3] - mn1);
            sum0 += sacc[nf][0] + sacc[nf][1];
            sum1 += sacc[nf][2] + sacc[nf][3];
        }
        sum0 += __shfl_xor_sync(0xffffffffu, sum0, 1);
        sum0 += __shfl_xor_sync(0xffffffffu, sum0, 2);
        sum1 += __shfl_xor_sync(0xffffffffu, sum1, 1);
        sum1 += __shfl_xor_sync(0xffffffffu, sum1, 2);
        lr0 = lr0 * corr0 + sum0;
        lr1 = lr1 * corr1 + sum1;

        // ---- rescale O only when the running max actually moved ----
        if (__any_sync(0xffffffffu, (corr0 < 1.0f) | (corr1 < 1.0f))) {
#pragma unroll
            for (int nf = 0; nf < 16; nf++) {
                oacc[nf][0] *= corr0; oacc[nf][1] *= corr0;
                oacc[nf][2] *= corr1; oacc[nf][3] *= corr1;
            }
        }

        // ---- pack P into fp16 hi/lo A-frags ----
        uint32_t ph[4][4], pl[4][4];
#pragma unroll
        for (int kc = 0; kc < 4; kc++) {
            pack2h(sacc[2 * kc][0],     sacc[2 * kc][1],     ph[kc][0], pl[kc][0]);
            pack2h(sacc[2 * kc][2],     sacc[2 * kc][3],     ph[kc][1], pl[kc][1]);
            pack2h(sacc[2 * kc + 1][0], sacc[2 * kc + 1][1], ph[kc][2], pl[kc][2]);
            pack2h(sacc[2 * kc + 1][2], sacc[2 * kc + 1][3], ph[kc][3], pl[kc][3]);
        }

        // ---- O += P V ----
#pragma unroll
        for (int ks2 = 0; ks2 < 4; ks2++) {
            int vrow = ks2 * 16 + (lane & 15);
#pragma unroll
            for (int g = 0; g < 8; g++) {
                int chunk = g * 2 + (lane >> 4);
                uint32_t off = sw256(vrow, chunk * 8);
                uint32_t vh[4];
                ldsm_x4_t(vh, vb + off);
                uint32_t vh0[2] = {vh[0], vh[1]}, vh1[2] = {vh[2], vh[3]};
                mma_f16(oacc[g * 2],     ph[ks2], vh0);
                mma_f16(oacc[g * 2],     pl[ks2], vh0);
                mma_f16(oacc[g * 2 + 1], ph[ks2], vh1);
                mma_f16(oacc[g * 2 + 1], pl[ks2], vh1);
            }
        }
    }

    // ---- epilogue: normalize + fp16 hi/lo store ----
    float inv0 = 1.0f / lr0;
    float inv1 = 1.0f / lr1;
    size_t row0 = rb + m0 + wid * 16 + (lane >> 2);
#pragma unroll
    for (int nf = 0; nf < 16; nf++) {
        int col = h * 128 + nf * 8 + (lane & 3) * 2;
        uint32_t hi, lo;
        pack2h(oacc[nf][0] * inv0, oacc[nf][1] * inv0, hi, lo);
        *(uint32_t*)(g_ath + row0 * 256 + col) = hi;
        *(uint32_t*)(g_atl + row0 * 256 + col) = lo;
        pack2h(oacc[nf][2] * inv1, oacc[nf][3] * inv1, hi, lo);
        *(uint32_t*)(g_ath + (row0 + 8) * 256 + col) = hi;
        *(uint32_t*)(g_atl + (row0 + 8) * 256 + col) = lo;
    }
}

// ---------------------------------------------------------------------------
extern "C" void kernel_launch(void* const* d_in, const int* in_sizes, int n_in,
                              void* d_out, int out_size)
{
    const float* x  = (const float*)d_in[0];
    const float* Wq = (const float*)d_in[1];
    const float* Wk = (const float*)d_in[2];
    const float* Wv = (const float*)d_in[3];
    const float* Wo = (const float*)d_in[4];

    const int BT = in_sizes[0] / DIM;  // 8192
    const int T  = T_SEQ;
    const int B  = BT / T;

    __half *xh, *xl, *q16h, *q16l, *k16, *v16, *ath, *atl, *w16, *wo16;
    cudaGetSymbolAddress((void**)&xh,   g_xh);
    cudaGetSymbolAddress((void**)&xl,   g_xl);
    cudaGetSymbolAddress((void**)&q16h, g_q16h);
    cudaGetSymbolAddress((void**)&q16l, g_q16l);
    cudaGetSymbolAddress((void**)&k16,  g_k16);
    cudaGetSymbolAddress((void**)&v16,  g_v16);
    cudaGetSymbolAddress((void**)&ath,  g_ath);
    cudaGetSymbolAddress((void**)&atl,  g_atl);
    cudaGetSymbolAddress((void**)&w16,  g_w16);
    cudaGetSymbolAddress((void**)&wo16, g_wo16);

    cudaFuncSetAttribute(gemm_f16_kernel,
                         cudaFuncAttributeMaxDynamicSharedMemorySize, GEMM_SMEM);
    cudaFuncSetAttribute(attn_reg_kernel,
                         cudaFuncAttributeMaxDynamicSharedMemorySize, ATT2_SMEM);

    // 1) split x + (concat/convert weights + trig) — two small kernels
    {
        int tot = BT * DIM / 4;
        split_x_kernel<<<(tot + 255) / 256, 256>>>(x);
        int wt = 512 * DIM / 4 + DIM * 256 / 4 + T_SEQ * 64;
        prep_kernel<<<(wt + 255) / 256, 256>>>(Wq, Wk, Wv, Wo);
    }

    // 2) fused QKV projection + rope + split epilogue
    {
        dim3 grid(BT / 128, 512 / 128);
        gemm_f16_kernel<<<grid, 256, GEMM_SMEM>>>(xh, xl, w16, nullptr,
                                                  BT, 512, DIM, 512, 1);
    }

    // 3) flash attention (all-fp16)
    {
        dim3 grid(T / 64, B * NKV);
        attn_reg_kernel<<<grid, 128, ATT2_SMEM>>>(q16h, q16l, k16, v16, T);
    }

    // 4) output projection
    {
        dim3 grid(BT / 128, DIM / 128);
        gemm_f16_kernel<<<grid, 256, GEMM_SMEM>>>(ath, atl, wo16,
                                                  (float*)d_out, BT, DIM, 256,
                                                  DIM, 0);
    }
}

// round 10
// speedup vs baseline: 9.8467x; 1.0915x over previous
#include <cuda_runtime.h>
#include <cuda_bf16.h>
#include <cuda_fp16.h>
#include <math.h>
#include <float.h>
#include <stdint.h>

// Problem constants (fixed by reference setup_inputs)
#define DIM   1024
#define HS    128
#define NKV   2
#define T_SEQ 2048
#define BT_MAX 8192   // B*T = 4*2048

// ---------------- scratch (static device allocations; no cudaMalloc) -------
__device__ __half  g_xh   [BT_MAX * DIM];   // x fp16 hi
__device__ __half  g_xl   [BT_MAX * DIM];   // x fp16 lo residual
__device__ __half  g_q16  [BT_MAX * 256];   // rope'd+scaled Q, single fp16
__device__ __half  g_k16  [BT_MAX * 128];   // rope'd K, single fp16
__device__ __half  g_v16  [BT_MAX * 128];   // V, single fp16
__device__ __half  g_ath  [BT_MAX * 256];   // attention out fp16 hi
__device__ __half  g_atl  [BT_MAX * 256];   // attention out fp16 lo
__device__ __half  g_w16  [512 * DIM];      // Wcat single fp16
__device__ __half  g_wo16 [DIM * 256];      // Wo single fp16
__device__ float2  g_trig [T_SEQ * 64];     // (cos, sin) per (t, pair)

// ============================================================================
// helpers
// ============================================================================
__device__ __forceinline__ uint32_t smem_u32(const void* p) {
    uint32_t a;
    asm("{ .reg .u64 t; cvta.to.shared.u64 t, %1; cvt.u32.u64 %0, t; }"
        : "=r"(a) : "l"(p));
    return a;
}

__device__ __forceinline__ void mma_f16(float c[4], const uint32_t a[4],
                                        const uint32_t b[2]) {
    asm volatile(
        "mma.sync.aligned.m16n8k16.row.col.f32.f16.f16.f32 "
        "{%0,%1,%2,%3}, {%4,%5,%6,%7}, {%8,%9}, {%0,%1,%2,%3};"
        : "+f"(c[0]), "+f"(c[1]), "+f"(c[2]), "+f"(c[3])
        : "r"(a[0]), "r"(a[1]), "r"(a[2]), "r"(a[3]), "r"(b[0]), "r"(b[1]));
}

__device__ __forceinline__ void ldsm_x4(uint32_t r[4], uint32_t addr) {
    asm volatile("ldmatrix.sync.aligned.m8n8.x4.shared.b16 {%0,%1,%2,%3}, [%4];"
                 : "=r"(r[0]), "=r"(r[1]), "=r"(r[2]), "=r"(r[3]) : "r"(addr));
}
__device__ __forceinline__ void ldsm_x4_t(uint32_t r[4], uint32_t addr) {
    asm volatile("ldmatrix.sync.aligned.m8n8.x4.trans.shared.b16 {%0,%1,%2,%3}, [%4];"
                 : "=r"(r[0]), "=r"(r[1]), "=r"(r[2]), "=r"(r[3]) : "r"(addr));
}

#define CP_A16(dst, src) \
    asm volatile("cp.async.cg.shared.global [%0], [%1], 16;" \
                 :: "r"(dst), "l"(src) : "memory")
#define CP_COMMIT() asm volatile("cp.async.commit_group;" ::: "memory")
#define CP_WAIT0()  asm volatile("cp.async.wait_group 0;" ::: "memory")

// fp16 hi/lo split of a scalar pair -> packed half2 words
__device__ __forceinline__ void pack2h(float x, float y, uint32_t& hi, uint32_t& lo) {
    __half2 h = __float22half2_rn(make_float2(x, y));
    __half2 l = __float22half2_rn(
        make_float2(x - __low2float(h), y - __high2float(h)));
    hi = *(uint32_t*)&h; lo = *(uint32_t*)&l;
}

__device__ __forceinline__ float exp2p(float y) {
    y = fmaxf(y, -125.0f);
    float t = y + 12582912.0f;
    float f = y - (t - 12582912.0f);
    float p = 0.0013333558f;
    p = fmaf(p, f, 0.0096181291f);
    p = fmaf(p, f, 0.055504109f);
    p = fmaf(p, f, 0.24022651f);
    p = fmaf(p, f, 0.69314718f);
    p = fmaf(p, f, 1.0f);
    return __int_as_float(__float_as_int(p) + (__float_as_int(t) << 23));
}

// Swizzle for 128-col 16-bit tiles (256B rows), 16B chunks (attention)
__device__ __forceinline__ uint32_t sw256(int row, int col) {
    int chunk = col >> 3;
    return (uint32_t)(row * 256 + (((chunk ^ (row & 7)) << 4) | ((col & 7) << 1)));
}
// Swizzle for 64-col fp16 tiles (128B rows), 8 chunks of 16B (GEMM)
__device__ __forceinline__ uint32_t sw128h(int row, int chunk) {
    return (uint32_t)(row * 128 + ((chunk ^ (row & 7)) << 4));
}

// ---------------------------------------------------------------------------
// split_x: x fp32 -> fp16 hi/lo
// ---------------------------------------------------------------------------
__global__ void split_x_kernel(const float* __restrict__ x)
{
    int i = blockIdx.x * blockDim.x + threadIdx.x;
    const int TOT = BT_MAX * DIM / 4;
    if (i >= TOT) return;
    float4 v = ((const float4*)x)[i];
    uint2 hi, lo;
    pack2h(v.x, v.y, hi.x, lo.x);
    pack2h(v.z, v.w, hi.y, lo.y);
    *(uint2*)(g_xh + i * 4) = hi;
    *(uint2*)(g_xl + i * 4) = lo;
}

// ---------------------------------------------------------------------------
// Weight concat + fp16 convert + trig table (one launch)
// ---------------------------------------------------------------------------
__global__ void prep_kernel(const float* __restrict__ Wq,
                            const float* __restrict__ Wk,
                            const float* __restrict__ Wv,
                            const float* __restrict__ Wo)
{
    int i = blockIdx.x * blockDim.x + threadIdx.x;
    const int WCAT4 = 512 * DIM / 4;
    const int WO4   = DIM * 256 / 4;
    const int TRIG  = T_SEQ * 64;
    if (i < WCAT4) {
        int row = i >> 8;
        float4 v;
        if (row < 256)       v = ((const float4*)Wq)[i];
        else if (row < 384)  v = ((const float4*)Wk)[i - 256 * 256];
        else                 v = ((const float4*)Wv)[i - 384 * 256];
        __half2 a = __float22half2_rn(make_float2(v.x, v.y));
        __half2 b = __float22half2_rn(make_float2(v.z, v.w));
        uint2 w; w.x = *(uint32_t*)&a; w.y = *(uint32_t*)&b;
        *(uint2*)(g_w16 + i * 4) = w;
    } else if (i < WCAT4 + WO4) {
        int j = i - WCAT4;
        float4 v = ((const float4*)Wo)[j];
        __half2 a = __float22half2_rn(make_float2(v.x, v.y));
        __half2 b = __float22half2_rn(make_float2(v.z, v.w));
        uint2 w; w.x = *(uint32_t*)&a; w.y = *(uint32_t*)&b;
        *(uint2*)(g_wo16 + j * 4) = w;
    } else if (i < WCAT4 + WO4 + TRIG) {
        int j = i - WCAT4 - WO4;
        int t = j >> 6, k = j & 63;
        float theta = exp2f(-(float)k * (13.287712379549449f / 32.0f));
        float s, c;
        sincosf((float)t * theta, &s, &c);
        g_trig[j] = make_float2(c, s);
    }
}

// ---------------------------------------------------------------------------
// HMMA GEMM NT (2xFP16): C[M,N] = (Ah+Al)[M,K] * B16[N,K]^T.
// 128x128 CTA tile, BK=64, 256 threads, cp.async double-buffered,
// single barrier per iteration. epi=0: fp32 C. epi=1: rope+convert epilogue.
// ---------------------------------------------------------------------------
#define GEMM_SMEM 98304

__device__ __forceinline__ void rope_epi_store(int r, int c, float x0, float x1)
{
    const float qscale = 0.08838834764831845f * 1.4426950408889634f;
    int t = r & (T_SEQ - 1);
    if (c < 384) {
        int i = (c & 127) >> 1;
        float2 cs = g_trig[t * 64 + i];
        float y0 = x0 * cs.x - x1 * cs.y;
        float y1 = x1 * cs.x + x0 * cs.y;
        if (c < 256) {
            y0 *= qscale; y1 *= qscale;
            __half2 hh = __float22half2_rn(make_float2(y0, y1));
            *(uint32_t*)(g_q16 + (size_t)r * 256 + c) = *(uint32_t*)&hh;
        } else {
            __half2 hh = __float22half2_rn(make_float2(y0, y1));
            *(uint32_t*)(g_k16 + (size_t)r * 128 + (c - 256)) = *(uint32_t*)&hh;
        }
    } else {
        __half2 hh = __float22half2_rn(make_float2(x0, x1));
        *(uint32_t*)(g_v16 + (size_t)r * 128 + (c - 384)) = *(uint32_t*)&hh;
    }
}

__global__ __launch_bounds__(256, 2)
void gemm_f16_kernel(const __half* __restrict__ Ah,
                     const __half* __restrict__ Al,
                     const __half* __restrict__ B16,
                     float* __restrict__ C, int M, int N, int K, int ldc,
                     int epi)
{
    extern __shared__ __align__(16) char smp[];
    const uint32_t sb = smem_u32(smp);

    const int tid = threadIdx.x;
    const int wid = tid >> 5;
    const int lane = tid & 31;
    const int m0 = blockIdx.x * 128;
    const int n0 = blockIdx.y * 128;
    const int wm = wid & 3;
    const int wn = wid >> 2;

    float acc[2][8][4];
#pragma unroll
    for (int mf = 0; mf < 2; mf++)
#pragma unroll
        for (int nf = 0; nf < 8; nf++)
#pragma unroll
            for (int q = 0; q < 4; q++) acc[mf][nf][q] = 0.f;

    const int KT = K >> 6;    // BK = 64

    auto fill = [&](int buf, int kt) {
        const uint32_t base = sb + buf * 49152;
#pragma unroll
        for (int i = 0; i < 4; i++) {
            int u = tid + i * 256;
            int row = u >> 3, ch = u & 7;
            uint32_t off = sw128h(row, ch);
            size_t sA = (size_t)(m0 + row) * K + kt * 64 + ch * 8;
            size_t sB = (size_t)(n0 + row) * K + kt * 64 + ch * 8;
            CP_A16(base + off,         Ah  + sA);
            CP_A16(base + 16384 + off, Al  + sA);
            CP_A16(base + 32768 + off, B16 + sB);
        }
        CP_COMMIT();
    };

    fill(0, 0);

    for (int kt = 0; kt < KT; kt++) {
        const int buf = kt & 1;
        CP_WAIT0();
        __syncthreads();
        if (kt + 1 < KT) fill(buf ^ 1, kt + 1);

        const uint32_t ab = sb + buf * 49152;
        const uint32_t bb = ab + 32768;
#pragma unroll
        for (int ks = 0; ks < 4; ks++) {
            uint32_t ah[2][4], al[2][4];
#pragma unroll
            for (int mf = 0; mf < 2; mf++) {
                int row = wm * 32 + mf * 16 + (lane & 15);
                int chunk = ks * 2 + (lane >> 4);
                uint32_t ad = ab + sw128h(row, chunk);
                ldsm_x4(ah[mf], ad);
                ldsm_x4(al[mf], ad + 16384);
            }
            uint32_t bh[8][2];
#pragma unroll
            for (int np = 0; np < 4; np++) {
                int row = wn * 64 + np * 16 + ((lane >> 4) << 3) + (lane & 7);
                int chunk = ks * 2 + ((lane >> 3) & 1);
                uint32_t t[4];
                ldsm_x4(t, bb + sw128h(row, chunk));
                bh[np * 2][0] = t[0]; bh[np * 2][1] = t[1];
                bh[np * 2 + 1][0] = t[2]; bh[np * 2 + 1][1] = t[3];
            }
#pragma unroll
            for (int mf = 0; mf < 2; mf++)
#pragma unroll
                for (int nf = 0; nf < 8; nf++) {
                    mma_f16(acc[mf][nf], ah[mf], bh[nf]);
                    mma_f16(acc[mf][nf], al[mf], bh[nf]);
                }
        }
    }

    if (epi == 0) {
#pragma unroll
        for (int mf = 0; mf < 2; mf++)
#pragma unroll
            for (int nf = 0; nf < 8; nf++) {
                int row = m0 + wm * 32 + mf * 16 + (lane >> 2);
                int col = n0 + wn * 64 + nf * 8 + (lane & 3) * 2;
                *(float2*)(C + (size_t)row * ldc + col) =
                    make_float2(acc[mf][nf][0], acc[mf][nf][1]);
                *(float2*)(C + (size_t)(row + 8) * ldc + col) =
                    make_float2(acc[mf][nf][2], acc[mf][nf][3]);
            }
    } else {
#pragma unroll
        for (int mf = 0; mf < 2; mf++)
#pragma unroll
            for (int nf = 0; nf < 8; nf++) {
                int row = m0 + wm * 32 + mf * 16 + (lane >> 2);
                int col = n0 + wn * 64 + nf * 8 + (lane & 3) * 2;
                rope_epi_store(row,     col, acc[mf][nf][0], acc[mf][nf][1]);
                rope_epi_store(row + 8, col, acc[mf][nf][2], acc[mf][nf][3]);
            }
    }
}

// ---------------------------------------------------------------------------
// Flash attention: Q single fp16 frags in regs; K,V single fp16 double-buffered;
// P fp16 hi/lo. S: 64 mma/tile/warp. PV: 128. Single barrier per tile.
// K buf b at b*16384; V buf b at 32768 + b*16384. Q staged in 0..16383.
// ---------------------------------------------------------------------------
#define ATT2_SMEM 65536

__global__ __launch_bounds__(128, 2)
void attn_reg_kernel(const __half* __restrict__ q_g,
                     const __half* __restrict__ k_g,
                     const __half* __restrict__ v_g, int T)
{
    extern __shared__ __align__(16) char smp[];
    const uint32_t sb = smem_u32(smp);

    const int tid = threadIdx.x;
    const int wid = tid >> 5;
    const int lane = tid & 31;
    const int bh = blockIdx.y;
    const int b  = bh >> 1;
    const int h  = bh & 1;

    const int bx = blockIdx.x;
    const int oo = bx & 3;
    const int qq = bx >> 2;
    const int pp = (qq & 1) ? (qq ^ 4) : qq;
    const int mt = (pp & 1) ? (4 * oo + (pp >> 1)) : (31 - 4 * oo - (pp >> 1));
    const int m0 = mt * 64;

    const size_t rb = (size_t)b * T;

    // ---- stage Q, extract frags ----
#pragma unroll
    for (int i = 0; i < 8; i++) {
        int u = tid + i * 128;
        int row = u >> 4, ch = u & 15;
        uint32_t off = sw256(row, ch * 8);
        size_t src = (rb + m0 + row) * 256 + h * 128 + ch * 8;
        CP_A16(sb + off, q_g + src);
    }
    CP_COMMIT();
    CP_WAIT0();
    __syncthreads();

    uint32_t qf[8][4];
#pragma unroll
    for (int ks = 0; ks < 8; ks++) {
        int row = wid * 16 + (lane & 15);
        int chunk = ks * 2 + (lane >> 4);
        uint32_t off = sw256(row, chunk * 8);
        ldsm_x4(qf[ks], sb + off);
    }
    __syncthreads();   // Q reads done before K0 overwrites

    auto fillKV = [&](int buf, int j) {
        const uint32_t kb = sb + buf * 16384;
        const uint32_t vb = sb + 32768 + buf * 16384;
        const int n0v = j * 64;
#pragma unroll
        for (int i = 0; i < 8; i++) {
            int u = tid + i * 128;
            int row = u >> 4, ch = u & 15;
            uint32_t off = sw256(row, ch * 8);
            size_t src = (size_t)(rb + n0v + row) * 128 + ch * 8;
            CP_A16(kb + off, k_g + src);
            CP_A16(vb + off, v_g + src);
        }
        CP_COMMIT();
    };

    fillKV(0, 0);

    float mr0 = -1e30f, mr1 = -1e30f, lr0 = 0.f, lr1 = 0.f;
    float oacc[16][4];
#pragma unroll
    for (int nf = 0; nf < 16; nf++)
#pragma unroll
        for (int q = 0; q < 4; q++) oacc[nf][q] = 0.f;

    for (int j = 0; j <= mt; j++) {
        const int cur = j & 1;
        const int n0v = j * 64;

        CP_WAIT0();
        __syncthreads();
        if (j < mt) fillKV(cur ^ 1, j + 1);

        const uint32_t kb = sb + cur * 16384;
        const uint32_t vb = sb + 32768 + cur * 16384;

        // ---- S = Q K^T (single fp16 both sides) ----
        float sacc[8][4];
#pragma unroll
        for (int nf = 0; nf < 8; nf++)
#pragma unroll
            for (int q = 0; q < 4; q++) sacc[nf][q] = 0.f;

#pragma unroll
        for (int ks = 0; ks < 8; ks++) {
#pragma unroll
            for (int ng = 0; ng < 4; ng++) {
                int row = ng * 16 + ((lane >> 4) << 3) + (lane & 7);
                int chunk = ks * 2 + ((lane >> 3) & 1);
                uint32_t off = sw256(row, chunk * 8);
                uint32_t t[4];
                ldsm_x4(t, kb + off);
                uint32_t b0[2] = {t[0], t[1]}, b1[2] = {t[2], t[3]};
                mma_f16(sacc[ng * 2],     qf[ks], b0);
                mma_f16(sacc[ng * 2 + 1], qf[ks], b1);
            }
        }

        // ---- causal mask (diagonal tile only) ----
        if (j == mt) {
            int grow0 = m0 + wid * 16 + (lane >> 2);
            int grow1 = grow0 + 8;
            int cbase = n0v + (lane & 3) * 2;
#pragma unroll
            for (int nf = 0; nf < 8; nf++) {
                int c = cbase + nf * 8;
                if (c     > grow0) sacc[nf][0] = -1e30f;
                if (c + 1 > grow0) sacc[nf][1] = -1e30f;
                if (c     > grow1) sacc[nf][2] = -1e30f;
                if (c + 1 > grow1) sacc[nf][3] = -1e30f;
            }
        }

        // ---- register softmax (exp2 domain) ----
        float mx0 = -1e30f, mx1 = -1e30f;
#pragma unroll
        for (int nf = 0; nf < 8; nf++) {
            mx0 = fmaxf(mx0, fmaxf(sacc[nf][0], sacc[nf][1]));
            mx1 = fmaxf(mx1, fmaxf(sacc[nf][2], sacc[nf][3]));
        }
        mx0 = fmaxf(mx0, __shfl_xor_sync(0xffffffffu, mx0, 1));
        mx0 = fmaxf(mx0, __shfl_xor_sync(0xffffffffu, mx0, 2));
        mx1 = fmaxf(mx1, __shfl_xor_sync(0xffffffffu, mx1, 1));
        mx1 = fmaxf(mx1, __shfl_xor_sync(0xffffffffu, mx1, 2));

        float mn0 = fmaxf(mr0, mx0), mn1 = fmaxf(mr1, mx1);
        float corr0 = exp2p(mr0 - mn0), corr1 = exp2p(mr1 - mn1);
        mr0 = mn0; mr1 = mn1;

        float sum0 = 0.f, sum1 = 0.f;
#pragma unroll
        for (int nf = 0; nf < 8; nf++) {
            sacc[nf][0] = exp2p(sacc[nf][0] - mn0);
            sacc[nf][1] = exp2p(sacc[nf][1] - mn0);
            sacc[nf][2] = exp2p(sacc[nf][2] - mn1);
            sacc[nf][3] = exp2p(sacc[nf][3] - mn1);
            sum0 += sacc[nf][0] + sacc[nf][1];
            sum1 += sacc[nf][2] + sacc[nf][3];
        }
        sum0 += __shfl_xor_sync(0xffffffffu, sum0, 1);
        sum0 += __shfl_xor_sync(0xffffffffu, sum0, 2);
        sum1 += __shfl_xor_sync(0xffffffffu, sum1, 1);
        sum1 += __shfl_xor_sync(0xffffffffu, sum1, 2);
        lr0 = lr0 * corr0 + sum0;
        lr1 = lr1 * corr1 + sum1;

        // ---- rescale O only when running max moved ----
        if (__any_sync(0xffffffffu, (corr0 < 1.0f) | (corr1 < 1.0f))) {
#pragma unroll
            for (int nf = 0; nf < 16; nf++) {
                oacc[nf][0] *= corr0; oacc[nf][1] *= corr0;
                oacc[nf][2] *= corr1; oacc[nf][3] *= corr1;
            }
        }

        // ---- pack P into fp16 hi/lo A-frags ----
        uint32_t ph[4][4], pl[4][4];
#pragma unroll
        for (int kc = 0; kc < 4; kc++) {
            pack2h(sacc[2 * kc][0],     sacc[2 * kc][1],     ph[kc][0], pl[kc][0]);
            pack2h(sacc[2 * kc][2],     sacc[2 * kc][3],     ph[kc][1], pl[kc][1]);
            pack2h(sacc[2 * kc + 1][0], sacc[2 * kc + 1][1], ph[kc][2], pl[kc][2]);
            pack2h(sacc[2 * kc + 1][2], sacc[2 * kc + 1][3], ph[kc][3], pl[kc][3]);
        }

        // ---- O += P V ----
#pragma unroll
        for (int ks2 = 0; ks2 < 4; ks2++) {
            int vrow = ks2 * 16 + (lane & 15);
#pragma unroll
            for (int g = 0; g < 8; g++) {
                int chunk = g * 2 + (lane >> 4);
                uint32_t off = sw256(vrow, chunk * 8);
                uint32_t vh[4];
                ldsm_x4_t(vh, vb + off);
                uint32_t vh0[2] = {vh[0], vh[1]}, vh1[2] = {vh[2], vh[3]};
                mma_f16(oacc[g * 2],     ph[ks2], vh0);
                mma_f16(oacc[g * 2],     pl[ks2], vh0);
                mma_f16(oacc[g * 2 + 1], ph[ks2], vh1);
                mma_f16(oacc[g * 2 + 1], pl[ks2], vh1);
            }
        }
    }

    // ---- epilogue: normalize + fp16 hi/lo store ----
    float inv0 = 1.0f / lr0;
    float inv1 = 1.0f / lr1;
    size_t row0 = rb + m0 + wid * 16 + (lane >> 2);
#pragma unroll
    for (int nf = 0; nf < 16; nf++) {
        int col = h * 128 + nf * 8 + (lane & 3) * 2;
        uint32_t hi, lo;
        pack2h(oacc[nf][0] * inv0, oacc[nf][1] * inv0, hi, lo);
        *(uint32_t*)(g_ath + row0 * 256 + col) = hi;
        *(uint32_t*)(g_atl + row0 * 256 + col) = lo;
        pack2h(oacc[nf][2] * inv1, oacc[nf][3] * inv1, hi, lo);
        *(uint32_t*)(g_ath + (row0 + 8) * 256 + col) = hi;
        *(uint32_t*)(g_atl + (row0 + 8) * 256 + col) = lo;
    }
}

// ---------------------------------------------------------------------------
extern "C" void kernel_launch(void* const* d_in, const int* in_sizes, int n_in,
                              void* d_out, int out_size)
{
    const float* x  = (const float*)d_in[0];
    const float* Wq = (const float*)d_in[1];
    const float* Wk = (const float*)d_in[2];
    const float* Wv = (const float*)d_in[3];
    const float* Wo = (const float*)d_in[4];

    const int BT = in_sizes[0] / DIM;  // 8192
    const int T  = T_SEQ;
    const int B  = BT / T;

    __half *xh, *xl, *q16, *k16, *v16, *ath, *atl, *w16, *wo16;
    cudaGetSymbolAddress((void**)&xh,   g_xh);
    cudaGetSymbolAddress((void**)&xl,   g_xl);
    cudaGetSymbolAddress((void**)&q16,  g_q16);
    cudaGetSymbolAddress((void**)&k16,  g_k16);
    cudaGetSymbolAddress((void**)&v16,  g_v16);
    cudaGetSymbolAddress((void**)&ath,  g_ath);
    cudaGetSymbolAddress((void**)&atl,  g_atl);
    cudaGetSymbolAddress((void**)&w16,  g_w16);
    cudaGetSymbolAddress((void**)&wo16, g_wo16);

    cudaFuncSetAttribute(gemm_f16_kernel,
                         cudaFuncAttributeMaxDynamicSharedMemorySize, GEMM_SMEM);
    cudaFuncSetAttribute(attn_reg_kernel,
                         cudaFuncAttributeMaxDynamicSharedMemorySize, ATT2_SMEM);

    // 1) split x + (concat/convert weights + trig)
    {
        int tot = BT * DIM / 4;
        split_x_kernel<<<(tot + 255) / 256, 256>>>(x);
        int wt = 512 * DIM / 4 + DIM * 256 / 4 + T_SEQ * 64;
        prep_kernel<<<(wt + 255) / 256, 256>>>(Wq, Wk, Wv, Wo);
    }

    // 2) fused QKV projection + rope + convert epilogue
    {
        dim3 grid(BT / 128, 512 / 128);
        gemm_f16_kernel<<<grid, 256, GEMM_SMEM>>>(xh, xl, w16, nullptr,
                                                  BT, 512, DIM, 512, 1);
    }

    // 3) flash attention (Q/K/V single fp16, P hi/lo)
    {
        dim3 grid(T / 64, B * NKV);
        attn_reg_kernel<<<grid, 128, ATT2_SMEM>>>(q16, k16, v16, T);
    }

    // 4) output projection
    {
        dim3 grid(BT / 128, DIM / 128);
        gemm_f16_kernel<<<grid, 256, GEMM_SMEM>>>(ath, atl, wo16,
                                                  (float*)d_out, BT, DIM, 256,
                                                  DIM, 0);
    }
}

// round 11
// speedup vs baseline: 10.9340x; 1.1104x over previous
#include <cuda_runtime.h>
#include <cuda_bf16.h>
#include <cuda_fp16.h>
#include <math.h>
#include <float.h>
#include <stdint.h>

// Problem constants (fixed by reference setup_inputs)
#define DIM   1024
#define HS    128
#define NKV   2
#define T_SEQ 2048
#define BT_MAX 8192   // B*T = 4*2048

// ---------------- scratch (static device allocations; no cudaMalloc) -------
__device__ __half  g_xh   [BT_MAX * DIM];   // x fp16 hi
__device__ __half  g_xl   [BT_MAX * DIM];   // x fp16 lo residual
__device__ __half  g_q16  [BT_MAX * 256];   // rope'd+scaled Q, single fp16
__device__ __half  g_k16  [BT_MAX * 128];   // rope'd K, single fp16
__device__ __half  g_v16  [BT_MAX * 128];   // V, single fp16
__device__ __half  g_ath  [BT_MAX * 256];   // attention out fp16 hi
__device__ __half  g_atl  [BT_MAX * 256];   // attention out fp16 lo
__device__ __half  g_w16  [512 * DIM];      // Wcat single fp16
__device__ __half  g_wo16 [DIM * 256];      // Wo single fp16
__device__ float2  g_trig [T_SEQ * 64];     // (cos, sin) per (t, pair)

// ============================================================================
// helpers
// ============================================================================
__device__ __forceinline__ uint32_t smem_u32(const void* p) {
    uint32_t a;
    asm("{ .reg .u64 t; cvta.to.shared.u64 t, %1; cvt.u32.u64 %0, t; }"
        : "=r"(a) : "l"(p));
    return a;
}

__device__ __forceinline__ void mma_f16(float c[4], const uint32_t a[4],
                                        const uint32_t b[2]) {
    asm volatile(
        "mma.sync.aligned.m16n8k16.row.col.f32.f16.f16.f32 "
        "{%0,%1,%2,%3}, {%4,%5,%6,%7}, {%8,%9}, {%0,%1,%2,%3};"
        : "+f"(c[0]), "+f"(c[1]), "+f"(c[2]), "+f"(c[3])
        : "r"(a[0]), "r"(a[1]), "r"(a[2]), "r"(a[3]), "r"(b[0]), "r"(b[1]));
}

__device__ __forceinline__ void ldsm_x4(uint32_t r[4], uint32_t addr) {
    asm volatile("ldmatrix.sync.aligned.m8n8.x4.shared.b16 {%0,%1,%2,%3}, [%4];"
                 : "=r"(r[0]), "=r"(r[1]), "=r"(r[2]), "=r"(r[3]) : "r"(addr));
}
__device__ __forceinline__ void ldsm_x4_t(uint32_t r[4], uint32_t addr) {
    asm volatile("ldmatrix.sync.aligned.m8n8.x4.trans.shared.b16 {%0,%1,%2,%3}, [%4];"
                 : "=r"(r[0]), "=r"(r[1]), "=r"(r[2]), "=r"(r[3]) : "r"(addr));
}

#define CP_A16(dst, src) \
    asm volatile("cp.async.cg.shared.global [%0], [%1], 16;" \
                 :: "r"(dst), "l"(src) : "memory")
#define CP_COMMIT() asm volatile("cp.async.commit_group;" ::: "memory")
#define CP_WAIT0()  asm volatile("cp.async.wait_group 0;" ::: "memory")

// fp16 hi/lo split of a scalar pair -> packed half2 words
__device__ __forceinline__ void pack2h(float x, float y, uint32_t& hi, uint32_t& lo) {
    __half2 h = __float22half2_rn(make_float2(x, y));
    __half2 l = __float22half2_rn(
        make_float2(x - __low2float(h), y - __high2float(h)));
    hi = *(uint32_t*)&h; lo = *(uint32_t*)&l;
}
__device__ __forceinline__ uint32_t packh2(float x, float y) {
    __half2 h = __float22half2_rn(make_float2(x, y));
    return *(uint32_t*)&h;
}

__device__ __forceinline__ float exp2p(float y) {
    y = fmaxf(y, -125.0f);
    float t = y + 12582912.0f;
    float f = y - (t - 12582912.0f);
    float p = 0.0013333558f;
    p = fmaf(p, f, 0.0096181291f);
    p = fmaf(p, f, 0.055504109f);
    p = fmaf(p, f, 0.24022651f);
    p = fmaf(p, f, 0.69314718f);
    p = fmaf(p, f, 1.0f);
    return __int_as_float(__float_as_int(p) + (__float_as_int(t) << 23));
}

// Swizzle for 128-col 16-bit tiles (256B rows), 16B chunks (attention)
__device__ __forceinline__ uint32_t sw256(int row, int col) {
    int chunk = col >> 3;
    return (uint32_t)(row * 256 + (((chunk ^ (row & 7)) << 4) | ((col & 7) << 1)));
}
// Swizzle for 64-col fp16 tiles (128B rows), 8 chunks of 16B (GEMM)
__device__ __forceinline__ uint32_t sw128h(int row, int chunk) {
    return (uint32_t)(row * 128 + ((chunk ^ (row & 7)) << 4));
}

// ---------------------------------------------------------------------------
// split_x: x fp32 -> fp16 hi/lo
// ---------------------------------------------------------------------------
__global__ void split_x_kernel(const float* __restrict__ x)
{
    int i = blockIdx.x * blockDim.x + threadIdx.x;
    const int TOT = BT_MAX * DIM / 4;
    if (i >= TOT) return;
    float4 v = ((const float4*)x)[i];
    uint2 hi, lo;
    pack2h(v.x, v.y, hi.x, lo.x);
    pack2h(v.z, v.w, hi.y, lo.y);
    *(uint2*)(g_xh + i * 4) = hi;
    *(uint2*)(g_xl + i * 4) = lo;
}

// ---------------------------------------------------------------------------
// Weight concat + fp16 convert + trig table (one launch)
// ---------------------------------------------------------------------------
__global__ void prep_kernel(const float* __restrict__ Wq,
                            const float* __restrict__ Wk,
                            const float* __restrict__ Wv,
                            const float* __restrict__ Wo)
{
    int i = blockIdx.x * blockDim.x + threadIdx.x;
    const int WCAT4 = 512 * DIM / 4;
    const int WO4   = DIM * 256 / 4;
    const int TRIG  = T_SEQ * 64;
    if (i < WCAT4) {
        int row = i >> 8;
        float4 v;
        if (row < 256)       v = ((const float4*)Wq)[i];
        else if (row < 384)  v = ((const float4*)Wk)[i - 256 * 256];
        else                 v = ((const float4*)Wv)[i - 384 * 256];
        uint2 w;
        w.x = packh2(v.x, v.y);
        w.y = packh2(v.z, v.w);
        *(uint2*)(g_w16 + i * 4) = w;
    } else if (i < WCAT4 + WO4) {
        int j = i - WCAT4;
        float4 v = ((const float4*)Wo)[j];
        uint2 w;
        w.x = packh2(v.x, v.y);
        w.y = packh2(v.z, v.w);
        *(uint2*)(g_wo16 + j * 4) = w;
    } else if (i < WCAT4 + WO4 + TRIG) {
        int j = i - WCAT4 - WO4;
        int t = j >> 6, k = j & 63;
        float theta = exp2f(-(float)k * (13.287712379549449f / 32.0f));
        float s, c;
        sincosf((float)t * theta, &s, &c);
        g_trig[j] = make_float2(c, s);
    }
}

// ---------------------------------------------------------------------------
// HMMA GEMM NT (2xFP16): C[M,N] = (Ah+Al)[M,K] * B16[N,K]^T.
// (unchanged from R10: single-barrier cp.async double-buffered pipeline)
// ---------------------------------------------------------------------------
#define GEMM_SMEM 98304

__device__ __forceinline__ void rope_epi_store(int r, int c, float x0, float x1)
{
    const float qscale = 0.08838834764831845f * 1.4426950408889634f;
    int t = r & (T_SEQ - 1);
    if (c < 384) {
        int i = (c & 127) >> 1;
        float2 cs = g_trig[t * 64 + i];
        float y0 = x0 * cs.x - x1 * cs.y;
        float y1 = x1 * cs.x + x0 * cs.y;
        if (c < 256) {
            y0 *= qscale; y1 *= qscale;
            *(uint32_t*)(g_q16 + (size_t)r * 256 + c) = packh2(y0, y1);
        } else {
            *(uint32_t*)(g_k16 + (size_t)r * 128 + (c - 256)) = packh2(y0, y1);
        }
    } else {
        *(uint32_t*)(g_v16 + (size_t)r * 128 + (c - 384)) = packh2(x0, x1);
    }
}

__global__ __launch_bounds__(256, 2)
void gemm_f16_kernel(const __half* __restrict__ Ah,
                     const __half* __restrict__ Al,
                     const __half* __restrict__ B16,
                     float* __restrict__ C, int M, int N, int K, int ldc,
                     int epi)
{
    extern __shared__ __align__(16) char smp[];
    const uint32_t sb = smem_u32(smp);

    const int tid = threadIdx.x;
    const int wid = tid >> 5;
    const int lane = tid & 31;
    const int m0 = blockIdx.x * 128;
    const int n0 = blockIdx.y * 128;
    const int wm = wid & 3;
    const int wn = wid >> 2;

    float acc[2][8][4];
#pragma unroll
    for (int mf = 0; mf < 2; mf++)
#pragma unroll
        for (int nf = 0; nf < 8; nf++)
#pragma unroll
            for (int q = 0; q < 4; q++) acc[mf][nf][q] = 0.f;

    const int KT = K >> 6;    // BK = 64

    auto fill = [&](int buf, int kt) {
        const uint32_t base = sb + buf * 49152;
#pragma unroll
        for (int i = 0; i < 4; i++) {
            int u = tid + i * 256;
            int row = u >> 3, ch = u & 7;
            uint32_t off = sw128h(row, ch);
            size_t sA = (size_t)(m0 + row) * K + kt * 64 + ch * 8;
            size_t sB = (size_t)(n0 + row) * K + kt * 64 + ch * 8;
            CP_A16(base + off,         Ah  + sA);
            CP_A16(base + 16384 + off, Al  + sA);
            CP_A16(base + 32768 + off, B16 + sB);
        }
        CP_COMMIT();
    };

    fill(0, 0);

    for (int kt = 0; kt < KT; kt++) {
        const int buf = kt & 1;
        CP_WAIT0();
        __syncthreads();
        if (kt + 1 < KT) fill(buf ^ 1, kt + 1);

        const uint32_t ab = sb + buf * 49152;
        const uint32_t bb = ab + 32768;
#pragma unroll
        for (int ks = 0; ks < 4; ks++) {
            uint32_t ah[2][4], al[2][4];
#pragma unroll
            for (int mf = 0; mf < 2; mf++) {
                int row = wm * 32 + mf * 16 + (lane & 15);
                int chunk = ks * 2 + (lane >> 4);
                uint32_t ad = ab + sw128h(row, chunk);
                ldsm_x4(ah[mf], ad);
                ldsm_x4(al[mf], ad + 16384);
            }
            uint32_t bh[8][2];
#pragma unroll
            for (int np = 0; np < 4; np++) {
                int row = wn * 64 + np * 16 + ((lane >> 4) << 3) + (lane & 7);
                int chunk = ks * 2 + ((lane >> 3) & 1);
                uint32_t t[4];
                ldsm_x4(t, bb + sw128h(row, chunk));
                bh[np * 2][0] = t[0]; bh[np * 2][1] = t[1];
                bh[np * 2 + 1][0] = t[2]; bh[np * 2 + 1][1] = t[3];
            }
#pragma unroll
            for (int mf = 0; mf < 2; mf++)
#pragma unroll
                for (int nf = 0; nf < 8; nf++) {
                    mma_f16(acc[mf][nf], ah[mf], bh[nf]);
                    mma_f16(acc[mf][nf], al[mf], bh[nf]);
                }
        }
    }

    if (epi == 0) {
#pragma unroll
        for (int mf = 0; mf < 2; mf++)
#pragma unroll
            for (int nf = 0; nf < 8; nf++) {
                int row = m0 + wm * 32 + mf * 16 + (lane >> 2);
                int col = n0 + wn * 64 + nf * 8 + (lane & 3) * 2;
                *(float2*)(C + (size_t)row * ldc + col) =
                    make_float2(acc[mf][nf][0], acc[mf][nf][1]);
                *(float2*)(C + (size_t)(row + 8) * ldc + col) =
                    make_float2(acc[mf][nf][2], acc[mf][nf][3]);
            }
    } else {
#pragma unroll
        for (int mf = 0; mf < 2; mf++)
#pragma unroll
            for (int nf = 0; nf < 8; nf++) {
                int row = m0 + wm * 32 + mf * 16 + (lane >> 2);
                int col = n0 + wn * 64 + nf * 8 + (lane & 3) * 2;
                rope_epi_store(row,     col, acc[mf][nf][0], acc[mf][nf][1]);
                rope_epi_store(row + 8, col, acc[mf][nf][2], acc[mf][nf][3]);
            }
    }
}

// ---------------------------------------------------------------------------
// Flash attention, software-pipelined: per iteration, PV(j) and S(j+1) are
// two independent MMA chains issued back-to-back. Triple-buffered K/V.
// Q single fp16 frags in regs; P single fp16 (16 regs). 96 KB smem, 2 CTA/SM.
// Layout: K_b at b*16384 (b=0..2); V_b at 49152 + b*16384; Q staged in V_2.
// ---------------------------------------------------------------------------
#define ATT2_SMEM 98304

__global__ __launch_bounds__(128, 2)
void attn_reg_kernel(const __half* __restrict__ q_g,
                     const __half* __restrict__ k_g,
                     const __half* __restrict__ v_g, int T)
{
    extern __shared__ __align__(16) char smp[];
    const uint32_t sb = smem_u32(smp);

    const int tid = threadIdx.x;
    const int wid = tid >> 5;
    const int lane = tid & 31;
    const int bh = blockIdx.y;
    const int b  = bh >> 1;
    const int h  = bh & 1;

    // Orbit-balanced mt map (heavy/light pairing across co-resident bids)
    const int bx = blockIdx.x;
    const int oo = bx & 3;
    const int qq = bx >> 2;
    const int pp_ = (qq & 1) ? (qq ^ 4) : qq;
    const int mt = (pp_ & 1) ? (4 * oo + (pp_ >> 1)) : (31 - 4 * oo - (pp_ >> 1));
    const int m0 = mt * 64;

    const size_t rb = (size_t)b * T;

    auto KB = [&](int bf) { return sb + bf * 16384; };
    auto VB = [&](int bf) { return sb + 49152 + bf * 16384; };

    auto fillKV = [&](int bf, int j) {
        const uint32_t kb = KB(bf);
        const uint32_t vb = VB(bf);
        const int n0v = j * 64;
#pragma unroll
        for (int i = 0; i < 8; i++) {
            int u = tid + i * 128;
            int row = u >> 4, ch = u & 15;
            uint32_t off = sw256(row, ch * 8);
            size_t src = (size_t)(rb + n0v + row) * 128 + ch * 8;
            CP_A16(kb + off, k_g + src);
            CP_A16(vb + off, v_g + src);
        }
        CP_COMMIT();
    };

    // ---- prologue: stage Q (into V_2 slot) + fill KV tile 0, one group ----
    {
        const uint32_t qstage = VB(2);
#pragma unroll
        for (int i = 0; i < 8; i++) {
            int u = tid + i * 128;
            int row = u >> 4, ch = u & 15;
            uint32_t off = sw256(row, ch * 8);
            size_t src = (rb + m0 + row) * 256 + h * 128 + ch * 8;
            CP_A16(qstage + off, q_g + src);
        }
        const int n0v = 0;
#pragma unroll
        for (int i = 0; i < 8; i++) {
            int u = tid + i * 128;
            int row = u >> 4, ch = u & 15;
            uint32_t off = sw256(row, ch * 8);
            size_t src = (size_t)(rb + n0v + row) * 128 + ch * 8;
            CP_A16(KB(0) + off, k_g + src);
            CP_A16(VB(0) + off, v_g + src);
        }
        CP_COMMIT();
        CP_WAIT0();
        __syncthreads();
    }

    uint32_t qf[8][4];
#pragma unroll
    for (int ks = 0; ks < 8; ks++) {
        int row = wid * 16 + (lane & 15);
        int chunk = ks * 2 + (lane >> 4);
        ldsm_x4(qf[ks], VB(2) + sw256(row, chunk * 8));
    }
    // V_2 not refilled until fill(2) in iter j=0, which happens after a sync.

    if (mt >= 1) fillKV(1, 1);

    float mr0 = -1e30f, mr1 = -1e30f, lr0 = 0.f, lr1 = 0.f;
    float oacc[16][4];
#pragma unroll
    for (int nf = 0; nf < 16; nf++)
#pragma unroll
        for (int q = 0; q < 4; q++) oacc[nf][q] = 0.f;

    uint32_t pp[4][4];   // P fragments (single fp16) for the pending PV

    // S-compute into sacc from K buffer kb
    auto computeS = [&](uint32_t kb, float sacc[8][4]) {
#pragma unroll
        for (int nf = 0; nf < 8; nf++)
#pragma unroll
            for (int q = 0; q < 4; q++) sacc[nf][q] = 0.f;
#pragma unroll
        for (int ks = 0; ks < 8; ks++) {
#pragma unroll
            for (int ng = 0; ng < 4; ng++) {
                int row = ng * 16 + ((lane >> 4) << 3) + (lane & 7);
                int chunk = ks * 2 + ((lane >> 3) & 1);
                uint32_t t[4];
                ldsm_x4(t, kb + sw256(row, chunk * 8));
                uint32_t b0[2] = {t[0], t[1]}, b1[2] = {t[2], t[3]};
                mma_f16(sacc[ng * 2],     qf[ks], b0);
                mma_f16(sacc[ng * 2 + 1], qf[ks], b1);
            }
        }
    };

    // softmax on sacc for tile jj; updates m/l, rescales oacc, packs pp
    auto softmax_pack = [&](float sacc[8][4], int jj) {
        if (jj == mt) {
            int grow0 = m0 + wid * 16 + (lane >> 2);
            int grow1 = grow0 + 8;
            int cbase = jj * 64 + (lane & 3) * 2;
#pragma unroll
            for (int nf = 0; nf < 8; nf++) {
                int c = cbase + nf * 8;
                if (c     > grow0) sacc[nf][0] = -1e30f;
                if (c + 1 > grow0) sacc[nf][1] = -1e30f;
                if (c     > grow1) sacc[nf][2] = -1e30f;
                if (c + 1 > grow1) sacc[nf][3] = -1e30f;
            }
        }
        float mx0 = -1e30f, mx1 = -1e30f;
#pragma unroll
        for (int nf = 0; nf < 8; nf++) {
            mx0 = fmaxf(mx0, fmaxf(sacc[nf][0], sacc[nf][1]));
            mx1 = fmaxf(mx1, fmaxf(sacc[nf][2], sacc[nf][3]));
        }
        mx0 = fmaxf(mx0, __shfl_xor_sync(0xffffffffu, mx0, 1));
        mx0 = fmaxf(mx0, __shfl_xor_sync(0xffffffffu, mx0, 2));
        mx1 = fmaxf(mx1, __shfl_xor_sync(0xffffffffu, mx1, 1));
        mx1 = fmaxf(mx1, __shfl_xor_sync(0xffffffffu, mx1, 2));

        float mn0 = fmaxf(mr0, mx0), mn1 = fmaxf(mr1, mx1);
        float corr0 = exp2p(mr0 - mn0), corr1 = exp2p(mr1 - mn1);
        mr0 = mn0; mr1 = mn1;

        float sum0 = 0.f, sum1 = 0.f;
#pragma unroll
        for (int nf = 0; nf < 8; nf++) {
            sacc[nf][0] = exp2p(sacc[nf][0] - mn0);
            sacc[nf][1] = exp2p(sacc[nf][1] - mn0);
            sacc[nf][2] = exp2p(sacc[nf][2] - mn1);
            sacc[nf][3] = exp2p(sacc[nf][3] - mn1);
            sum0 += sacc[nf][0] + sacc[nf][1];
            sum1 += sacc[nf][2] + sacc[nf][3];
        }
        sum0 += __shfl_xor_sync(0xffffffffu, sum0, 1);
        sum0 += __shfl_xor_sync(0xffffffffu, sum0, 2);
        sum1 += __shfl_xor_sync(0xffffffffu, sum1, 1);
        sum1 += __shfl_xor_sync(0xffffffffu, sum1, 2);
        lr0 = lr0 * corr0 + sum0;
        lr1 = lr1 * corr1 + sum1;

        if (__any_sync(0xffffffffu, (corr0 < 1.0f) | (corr1 < 1.0f))) {
#pragma unroll
            for (int nf = 0; nf < 16; nf++) {
                oacc[nf][0] *= corr0; oacc[nf][1] *= corr0;
                oacc[nf][2] *= corr1; oacc[nf][3] *= corr1;
            }
        }
#pragma unroll
        for (int kc = 0; kc < 4; kc++) {
            pp[kc][0] = packh2(sacc[2 * kc][0],     sacc[2 * kc][1]);
            pp[kc][1] = packh2(sacc[2 * kc][2],     sacc[2 * kc][3]);
            pp[kc][2] = packh2(sacc[2 * kc + 1][0], sacc[2 * kc + 1][1]);
            pp[kc][3] = packh2(sacc[2 * kc + 1][2], sacc[2 * kc + 1][3]);
        }
    };

    auto computePV = [&](uint32_t vb) {
#pragma unroll
        for (int ks2 = 0; ks2 < 4; ks2++) {
            int vrow = ks2 * 16 + (lane & 15);
#pragma unroll
            for (int g = 0; g < 8; g++) {
                int chunk = g * 2 + (lane >> 4);
                uint32_t vh[4];
                ldsm_x4_t(vh, vb + sw256(vrow, chunk * 8));
                uint32_t vh0[2] = {vh[0], vh[1]}, vh1[2] = {vh[2], vh[3]};
                mma_f16(oacc[g * 2],     pp[ks2], vh0);
                mma_f16(oacc[g * 2 + 1], pp[ks2], vh1);
            }
        }
    };

    // ---- prologue compute: S(0) -> P(0) ----
    {
        float sacc[8][4];
        computeS(KB(0), sacc);
        softmax_pack(sacc, 0);
    }

    // ---- pipelined main loop: PV(j) + S(j+1) ----
    for (int j = 0; j < mt; j++) {
        const int bufc = j % 3;          // V(j)
        const int bufn = (j + 1) % 3;    // K(j+1)

        CP_WAIT0();        // fill(j+1) locally complete
        __syncthreads();   // publish; all warps past reads of buf (j+2)%3
        if (j + 2 <= mt) fillKV((j + 2) % 3, j + 2);

        // Two independent MMA chains: S(j+1) then PV(j) (ptxas interleaves)
        float sacc[8][4];
        computeS(KB(bufn), sacc);
        computePV(VB(bufc));

        softmax_pack(sacc, j + 1);
    }

    // ---- final PV(mt) ----
    computePV(VB(mt % 3));

    // ---- epilogue: normalize + fp16 hi/lo store ----
    float inv0 = 1.0f / lr0;
    float inv1 = 1.0f / lr1;
    size_t row0 = rb + m0 + wid * 16 + (lane >> 2);
#pragma unroll
    for (int nf = 0; nf < 16; nf++) {
        int col = h * 128 + nf * 8 + (lane & 3) * 2;
        uint32_t hi, lo;
        pack2h(oacc[nf][0] * inv0, oacc[nf][1] * inv0, hi, lo);
        *(uint32_t*)(g_ath + row0 * 256 + col) = hi;
        *(uint32_t*)(g_atl + row0 * 256 + col) = lo;
        pack2h(oacc[nf][2] * inv1, oacc[nf][3] * inv1, hi, lo);
        *(uint32_t*)(g_ath + (row0 + 8) * 256 + col) = hi;
        *(uint32_t*)(g_atl + (row0 + 8) * 256 + col) = lo;
    }
}

// ---------------------------------------------------------------------------
extern "C" void kernel_launch(void* const* d_in, const int* in_sizes, int n_in,
                              void* d_out, int out_size)
{
    const float* x  = (const float*)d_in[0];
    const float* Wq = (const float*)d_in[1];
    const float* Wk = (const float*)d_in[2];
    const float* Wv = (const float*)d_in[3];
    const float* Wo = (const float*)d_in[4];

    const int BT = in_sizes[0] / DIM;  // 8192
    const int T  = T_SEQ;
    const int B  = BT / T;

    __half *xh, *xl, *q16, *k16, *v16, *ath, *atl, *w16, *wo16;
    cudaGetSymbolAddress((void**)&xh,   g_xh);
    cudaGetSymbolAddress((void**)&xl,   g_xl);
    cudaGetSymbolAddress((void**)&q16,  g_q16);
    cudaGetSymbolAddress((void**)&k16,  g_k16);
    cudaGetSymbolAddress((void**)&v16,  g_v16);
    cudaGetSymbolAddress((void**)&ath,  g_ath);
    cudaGetSymbolAddress((void**)&atl,  g_atl);
    cudaGetSymbolAddress((void**)&w16,  g_w16);
    cudaGetSymbolAddress((void**)&wo16, g_wo16);

    cudaFuncSetAttribute(gemm_f16_kernel,
                         cudaFuncAttributeMaxDynamicSharedMemorySize, GEMM_SMEM);
    cudaFuncSetAttribute(attn_reg_kernel,
                         cudaFuncAttributeMaxDynamicSharedMemorySize, ATT2_SMEM);

    // 1) split x + (concat/convert weights + trig)
    {
        int tot = BT * DIM / 4;
        split_x_kernel<<<(tot + 255) / 256, 256>>>(x);
        int wt = 512 * DIM / 4 + DIM * 256 / 4 + T_SEQ * 64;
        prep_kernel<<<(wt + 255) / 256, 256>>>(Wq, Wk, Wv, Wo);
    }

    // 2) fused QKV projection + rope + convert epilogue
    {
        dim3 grid(BT / 128, 512 / 128);
        gemm_f16_kernel<<<grid, 256, GEMM_SMEM>>>(xh, xl, w16, nullptr,
                                                  BT, 512, DIM, 512, 1);
    }

    // 3) flash attention (pipelined, Q/K/V/P single fp16)
    {
        dim3 grid(T / 64, B * NKV);
        attn_reg_kernel<<<grid, 128, ATT2_SMEM>>>(q16, k16, v16, T);
    }

    // 4) output projection
    {
        dim3 grid(BT / 128, DIM / 128);
        gemm_f16_kernel<<<grid, 256, GEMM_SMEM>>>(ath, atl, wo16,
                                                  (float*)d_out, BT, DIM, 256,
                                                  DIM, 0);
    }
}

// round 12
// speedup vs baseline: 11.9791x; 1.0956x over previous
#include <cuda_runtime.h>
#include <cuda_bf16.h>
#include <cuda_fp16.h>
#include <math.h>
#include <float.h>
#include <stdint.h>

// Problem constants (fixed by reference setup_inputs)
#define DIM   1024
#define HS    128
#define NKV   2
#define T_SEQ 2048
#define BT_MAX 8192   // B*T = 4*2048

// ---------------- scratch (static device allocations; no cudaMalloc) -------
__device__ __half  g_xh   [BT_MAX * DIM];   // x fp16 hi
__device__ __half  g_xl   [BT_MAX * DIM];   // x fp16 lo residual
__device__ __half  g_q16  [BT_MAX * 256];   // rope'd+scaled Q, single fp16
__device__ __half  g_k16  [BT_MAX * 128];   // rope'd K, single fp16
__device__ __half  g_v16  [BT_MAX * 128];   // V, single fp16
__device__ __half  g_ath  [BT_MAX * 256];   // attention out fp16 hi
__device__ __half  g_atl  [BT_MAX * 256];   // attention out fp16 lo
__device__ __half  g_w16  [512 * DIM];      // Wcat single fp16
__device__ __half  g_wo16 [DIM * 256];      // Wo single fp16
__device__ float2  g_trig [T_SEQ * 64];     // (cos, sin) per (t, pair)

// ============================================================================
// helpers
// ============================================================================
__device__ __forceinline__ uint32_t smem_u32(const void* p) {
    uint32_t a;
    asm("{ .reg .u64 t; cvta.to.shared.u64 t, %1; cvt.u32.u64 %0, t; }"
        : "=r"(a) : "l"(p));
    return a;
}

__device__ __forceinline__ void mma_f16(float c[4], const uint32_t a[4],
                                        const uint32_t b[2]) {
    asm volatile(
        "mma.sync.aligned.m16n8k16.row.col.f32.f16.f16.f32 "
        "{%0,%1,%2,%3}, {%4,%5,%6,%7}, {%8,%9}, {%0,%1,%2,%3};"
        : "+f"(c[0]), "+f"(c[1]), "+f"(c[2]), "+f"(c[3])
        : "r"(a[0]), "r"(a[1]), "r"(a[2]), "r"(a[3]), "r"(b[0]), "r"(b[1]));
}

__device__ __forceinline__ void ldsm_x4(uint32_t r[4], uint32_t addr) {
    asm volatile("ldmatrix.sync.aligned.m8n8.x4.shared.b16 {%0,%1,%2,%3}, [%4];"
                 : "=r"(r[0]), "=r"(r[1]), "=r"(r[2]), "=r"(r[3]) : "r"(addr));
}
__device__ __forceinline__ void ldsm_x4_t(uint32_t r[4], uint32_t addr) {
    asm volatile("ldmatrix.sync.aligned.m8n8.x4.trans.shared.b16 {%0,%1,%2,%3}, [%4];"
                 : "=r"(r[0]), "=r"(r[1]), "=r"(r[2]), "=r"(r[3]) : "r"(addr));
}

#define CP_A16(dst, src) \
    asm volatile("cp.async.cg.shared.global [%0], [%1], 16;" \
                 :: "r"(dst), "l"(src) : "memory")
#define CP_COMMIT() asm volatile("cp.async.commit_group;" ::: "memory")
#define CP_WAIT0()  asm volatile("cp.async.wait_group 0;" ::: "memory")

// fp16 hi/lo split of a scalar pair -> packed half2 words
__device__ __forceinline__ void pack2h(float x, float y, uint32_t& hi, uint32_t& lo) {
    __half2 h = __float22half2_rn(make_float2(x, y));
    __half2 l = __float22half2_rn(
        make_float2(x - __low2float(h), y - __high2float(h)));
    hi = *(uint32_t*)&h; lo = *(uint32_t*)&l;
}
__device__ __forceinline__ uint32_t packh2(float x, float y) {
    __half2 h = __float22half2_rn(make_float2(x, y));
    return *(uint32_t*)&h;
}

// MUFU exp2: 1 instruction/value, rel err ~2^-21. ex2(-huge) -> 0 exactly.
__device__ __forceinline__ float ex2(float y) {
    float r;
    asm("ex2.approx.ftz.f32 %0, %1;" : "=f"(r) : "f"(y));
    return r;
}

// Swizzle for 128-col 16-bit tiles (256B rows), 16B chunks (attention)
__device__ __forceinline__ uint32_t sw256(int row, int col) {
    int chunk = col >> 3;
    return (uint32_t)(row * 256 + (((chunk ^ (row & 7)) << 4) | ((col & 7) << 1)));
}
// Swizzle for 64-col fp16 tiles (128B rows), 8 chunks of 16B (GEMM)
__device__ __forceinline__ uint32_t sw128h(int row, int chunk) {
    return (uint32_t)(row * 128 + ((chunk ^ (row & 7)) << 4));
}

// ---------------------------------------------------------------------------
// split_x: x fp32 -> fp16 hi/lo
// ---------------------------------------------------------------------------
__global__ void split_x_kernel(const float* __restrict__ x)
{
    int i = blockIdx.x * blockDim.x + threadIdx.x;
    const int TOT = BT_MAX * DIM / 4;
    if (i >= TOT) return;
    float4 v = ((const float4*)x)[i];
    uint2 hi, lo;
    pack2h(v.x, v.y, hi.x, lo.x);
    pack2h(v.z, v.w, hi.y, lo.y);
    *(uint2*)(g_xh + i * 4) = hi;
    *(uint2*)(g_xl + i * 4) = lo;
}

// ---------------------------------------------------------------------------
// Weight concat + fp16 convert + trig table (one launch)
// ---------------------------------------------------------------------------
__global__ void prep_kernel(const float* __restrict__ Wq,
                            const float* __restrict__ Wk,
                            const float* __restrict__ Wv,
                            const float* __restrict__ Wo)
{
    int i = blockIdx.x * blockDim.x + threadIdx.x;
    const int WCAT4 = 512 * DIM / 4;
    const int WO4   = DIM * 256 / 4;
    const int TRIG  = T_SEQ * 64;
    if (i < WCAT4) {
        int row = i >> 8;
        float4 v;
        if (row < 256)       v = ((const float4*)Wq)[i];
        else if (row < 384)  v = ((const float4*)Wk)[i - 256 * 256];
        else                 v = ((const float4*)Wv)[i - 384 * 256];
        uint2 w;
        w.x = packh2(v.x, v.y);
        w.y = packh2(v.z, v.w);
        *(uint2*)(g_w16 + i * 4) = w;
    } else if (i < WCAT4 + WO4) {
        int j = i - WCAT4;
        float4 v = ((const float4*)Wo)[j];
        uint2 w;
        w.x = packh2(v.x, v.y);
        w.y = packh2(v.z, v.w);
        *(uint2*)(g_wo16 + j * 4) = w;
    } else if (i < WCAT4 + WO4 + TRIG) {
        int j = i - WCAT4 - WO4;
        int t = j >> 6, k = j & 63;
        float theta = exp2f(-(float)k * (13.287712379549449f / 32.0f));
        float s, c;
        sincosf((float)t * theta, &s, &c);
        g_trig[j] = make_float2(c, s);
    }
}

// ---------------------------------------------------------------------------
// HMMA GEMM NT (2xFP16): C[M,N] = (Ah+Al)[M,K] * B16[N,K]^T.
// Single-barrier cp.async double-buffered pipeline (R11 WIN state).
// ---------------------------------------------------------------------------
#define GEMM_SMEM 98304

__device__ __forceinline__ void rope_epi_store(int r, int c, float x0, float x1)
{
    const float qscale = 0.08838834764831845f * 1.4426950408889634f;
    int t = r & (T_SEQ - 1);
    if (c < 384) {
        int i = (c & 127) >> 1;
        float2 cs = g_trig[t * 64 + i];
        float y0 = x0 * cs.x - x1 * cs.y;
        float y1 = x1 * cs.x + x0 * cs.y;
        if (c < 256) {
            y0 *= qscale; y1 *= qscale;
            *(uint32_t*)(g_q16 + (size_t)r * 256 + c) = packh2(y0, y1);
        } else {
            *(uint32_t*)(g_k16 + (size_t)r * 128 + (c - 256)) = packh2(y0, y1);
        }
    } else {
        *(uint32_t*)(g_v16 + (size_t)r * 128 + (c - 384)) = packh2(x0, x1);
    }
}

__global__ __launch_bounds__(256, 2)
void gemm_f16_kernel(const __half* __restrict__ Ah,
                     const __half* __restrict__ Al,
                     const __half* __restrict__ B16,
                     float* __restrict__ C, int M, int N, int K, int ldc,
                     int epi)
{
    extern __shared__ __align__(16) char smp[];
    const uint32_t sb = smem_u32(smp);

    const int tid = threadIdx.x;
    const int wid = tid >> 5;
    const int lane = tid & 31;
    const int m0 = blockIdx.x * 128;
    const int n0 = blockIdx.y * 128;
    const int wm = wid & 3;
    const int wn = wid >> 2;

    float acc[2][8][4];
#pragma unroll
    for (int mf = 0; mf < 2; mf++)
#pragma unroll
        for (int nf = 0; nf < 8; nf++)
#pragma unroll
            for (int q = 0; q < 4; q++) acc[mf][nf][q] = 0.f;

    const int KT = K >> 6;    // BK = 64

    auto fill = [&](int buf, int kt) {
        const uint32_t base = sb + buf * 49152;
#pragma unroll
        for (int i = 0; i < 4; i++) {
            int u = tid + i * 256;
            int row = u >> 3, ch = u & 7;
            uint32_t off = sw128h(row, ch);
            size_t sA = (size_t)(m0 + row) * K + kt * 64 + ch * 8;
            size_t sB = (size_t)(n0 + row) * K + kt * 64 + ch * 8;
            CP_A16(base + off,         Ah  + sA);
            CP_A16(base + 16384 + off, Al  + sA);
            CP_A16(base + 32768 + off, B16 + sB);
        }
        CP_COMMIT();
    };

    fill(0, 0);

    for (int kt = 0; kt < KT; kt++) {
        const int buf = kt & 1;
        CP_WAIT0();
        __syncthreads();
        if (kt + 1 < KT) fill(buf ^ 1, kt + 1);

        const uint32_t ab = sb + buf * 49152;
        const uint32_t bb = ab + 32768;
#pragma unroll
        for (int ks = 0; ks < 4; ks++) {
            uint32_t ah[2][4], al[2][4];
#pragma unroll
            for (int mf = 0; mf < 2; mf++) {
                int row = wm * 32 + mf * 16 + (lane & 15);
                int chunk = ks * 2 + (lane >> 4);
                uint32_t ad = ab + sw128h(row, chunk);
                ldsm_x4(ah[mf], ad);
                ldsm_x4(al[mf], ad + 16384);
            }
            uint32_t bh[8][2];
#pragma unroll
            for (int np = 0; np < 4; np++) {
                int row = wn * 64 + np * 16 + ((lane >> 4) << 3) + (lane & 7);
                int chunk = ks * 2 + ((lane >> 3) & 1);
                uint32_t t[4];
                ldsm_x4(t, bb + sw128h(row, chunk));
                bh[np * 2][0] = t[0]; bh[np * 2][1] = t[1];
                bh[np * 2 + 1][0] = t[2]; bh[np * 2 + 1][1] = t[3];
            }
#pragma unroll
            for (int mf = 0; mf < 2; mf++)
#pragma unroll
                for (int nf = 0; nf < 8; nf++) {
                    mma_f16(acc[mf][nf], ah[mf], bh[nf]);
                    mma_f16(acc[mf][nf], al[mf], bh[nf]);
                }
        }
    }

    if (epi == 0) {
#pragma unroll
        for (int mf = 0; mf < 2; mf++)
#pragma unroll
            for (int nf = 0; nf < 8; nf++) {
                int row = m0 + wm * 32 + mf * 16 + (lane >> 2);
                int col = n0 + wn * 64 + nf * 8 + (lane & 3) * 2;
                *(float2*)(C + (size_t)row * ldc + col) =
                    make_float2(acc[mf][nf][0], acc[mf][nf][1]);
                *(float2*)(C + (size_t)(row + 8) * ldc + col) =
                    make_float2(acc[mf][nf][2], acc[mf][nf][3]);
            }
    } else {
#pragma unroll
        for (int mf = 0; mf < 2; mf++)
#pragma unroll
            for (int nf = 0; nf < 8; nf++) {
                int row = m0 + wm * 32 + mf * 16 + (lane >> 2);
                int col = n0 + wn * 64 + nf * 8 + (lane & 3) * 2;
                rope_epi_store(row,     col, acc[mf][nf][0], acc[mf][nf][1]);
                rope_epi_store(row + 8, col, acc[mf][nf][2], acc[mf][nf][3]);
            }
    }
}

// ---------------------------------------------------------------------------
// Flash attention, software-pipelined (R11 WIN structure), MUFU ex2 softmax.
// Triple-buffered K/V; Q single fp16 frags in regs; P single fp16.
// Layout: K_b at b*16384 (b=0..2); V_b at 49152 + b*16384; Q staged in V_2.
// ---------------------------------------------------------------------------
#define ATT2_SMEM 98304

__global__ __launch_bounds__(128, 2)
void attn_reg_kernel(const __half* __restrict__ q_g,
                     const __half* __restrict__ k_g,
                     const __half* __restrict__ v_g, int T)
{
    extern __shared__ __align__(16) char smp[];
    const uint32_t sb = smem_u32(smp);

    const int tid = threadIdx.x;
    const int wid = tid >> 5;
    const int lane = tid & 31;
    const int bh = blockIdx.y;
    const int b  = bh >> 1;
    const int h  = bh & 1;

    // Orbit-balanced mt map (heavy/light pairing across co-resident bids)
    const int bx = blockIdx.x;
    const int oo = bx & 3;
    const int qq = bx >> 2;
    const int pp_ = (qq & 1) ? (qq ^ 4) : qq;
    const int mt = (pp_ & 1) ? (4 * oo + (pp_ >> 1)) : (31 - 4 * oo - (pp_ >> 1));
    const int m0 = mt * 64;

    const size_t rb = (size_t)b * T;

    auto KB = [&](int bf) { return sb + bf * 16384; };
    auto VB = [&](int bf) { return sb + 49152 + bf * 16384; };

    auto fillKV = [&](int bf, int j) {
        const uint32_t kb = KB(bf);
        const uint32_t vb = VB(bf);
        const int n0v = j * 64;
#pragma unroll
        for (int i = 0; i < 8; i++) {
            int u = tid + i * 128;
            int row = u >> 4, ch = u & 15;
            uint32_t off = sw256(row, ch * 8);
            size_t src = (size_t)(rb + n0v + row) * 128 + ch * 8;
            CP_A16(kb + off, k_g + src);
            CP_A16(vb + off, v_g + src);
        }
        CP_COMMIT();
    };

    // ---- prologue: stage Q (into V_2 slot) + fill KV tile 0, one group ----
    {
        const uint32_t qstage = VB(2);
#pragma unroll
        for (int i = 0; i < 8; i++) {
            int u = tid + i * 128;
            int row = u >> 4, ch = u & 15;
            uint32_t off = sw256(row, ch * 8);
            size_t src = (rb + m0 + row) * 256 + h * 128 + ch * 8;
            CP_A16(qstage + off, q_g + src);
        }
        const int n0v = 0;
#pragma unroll
        for (int i = 0; i < 8; i++) {
            int u = tid + i * 128;
            int row = u >> 4, ch = u & 15;
            uint32_t off = sw256(row, ch * 8);
            size_t src = (size_t)(rb + n0v + row) * 128 + ch * 8;
            CP_A16(KB(0) + off, k_g + src);
            CP_A16(VB(0) + off, v_g + src);
        }
        CP_COMMIT();
        CP_WAIT0();
        __syncthreads();
    }

    uint32_t qf[8][4];
#pragma unroll
    for (int ks = 0; ks < 8; ks++) {
        int row = wid * 16 + (lane & 15);
        int chunk = ks * 2 + (lane >> 4);
        ldsm_x4(qf[ks], VB(2) + sw256(row, chunk * 8));
    }

    if (mt >= 1) fillKV(1, 1);

    float mr0 = -1e30f, mr1 = -1e30f, lr0 = 0.f, lr1 = 0.f;
    float oacc[16][4];
#pragma unroll
    for (int nf = 0; nf < 16; nf++)
#pragma unroll
        for (int q = 0; q < 4; q++) oacc[nf][q] = 0.f;

    uint32_t pp[4][4];   // P fragments (single fp16) for the pending PV

    auto computeS = [&](uint32_t kb, float sacc[8][4]) {
#pragma unroll
        for (int nf = 0; nf < 8; nf++)
#pragma unroll
            for (int q = 0; q < 4; q++) sacc[nf][q] = 0.f;
#pragma unroll
        for (int ks = 0; ks < 8; ks++) {
#pragma unroll
            for (int ng = 0; ng < 4; ng++) {
                int row = ng * 16 + ((lane >> 4) << 3) + (lane & 7);
                int chunk = ks * 2 + ((lane >> 3) & 1);
                uint32_t t[4];
                ldsm_x4(t, kb + sw256(row, chunk * 8));
                uint32_t b0[2] = {t[0], t[1]}, b1[2] = {t[2], t[3]};
                mma_f16(sacc[ng * 2],     qf[ks], b0);
                mma_f16(sacc[ng * 2 + 1], qf[ks], b1);
            }
        }
    };

    auto softmax_pack = [&](float sacc[8][4], int jj) {
        if (jj == mt) {
            int grow0 = m0 + wid * 16 + (lane >> 2);
            int grow1 = grow0 + 8;
            int cbase = jj * 64 + (lane & 3) * 2;
#pragma unroll
            for (int nf = 0; nf < 8; nf++) {
                int c = cbase + nf * 8;
                if (c     > grow0) sacc[nf][0] = -1e30f;
                if (c + 1 > grow0) sacc[nf][1] = -1e30f;
                if (c     > grow1) sacc[nf][2] = -1e30f;
                if (c + 1 > grow1) sacc[nf][3] = -1e30f;
            }
        }
        float mx0 = -1e30f, mx1 = -1e30f;
#pragma unroll
        for (int nf = 0; nf < 8; nf++) {
            mx0 = fmaxf(mx0, fmaxf(sacc[nf][0], sacc[nf][1]));
            mx1 = fmaxf(mx1, fmaxf(sacc[nf][2], sacc[nf][3]));
        }
        mx0 = fmaxf(mx0, __shfl_xor_sync(0xffffffffu, mx0, 1));
        mx0 = fmaxf(mx0, __shfl_xor_sync(0xffffffffu, mx0, 2));
        mx1 = fmaxf(mx1, __shfl_xor_sync(0xffffffffu, mx1, 1));
        mx1 = fmaxf(mx1, __shfl_xor_sync(0xffffffffu, mx1, 2));

        float mn0 = fmaxf(mr0, mx0), mn1 = fmaxf(mr1, mx1);
        float corr0 = ex2(mr0 - mn0), corr1 = ex2(mr1 - mn1);
        mr0 = mn0; mr1 = mn1;

        float sum0 = 0.f, sum1 = 0.f;
#pragma unroll
        for (int nf = 0; nf < 8; nf++) {
            sacc[nf][0] = ex2(sacc[nf][0] - mn0);
            sacc[nf][1] = ex2(sacc[nf][1] - mn0);
            sacc[nf][2] = ex2(sacc[nf][2] - mn1);
            sacc[nf][3] = ex2(sacc[nf][3] - mn1);
            sum0 += sacc[nf][0] + sacc[nf][1];
            sum1 += sacc[nf][2] + sacc[nf][3];
        }
        sum0 += __shfl_xor_sync(0xffffffffu, sum0, 1);
        sum0 += __shfl_xor_sync(0xffffffffu, sum0, 2);
        sum1 += __shfl_xor_sync(0xffffffffu, sum1, 1);
        sum1 += __shfl_xor_sync(0xffffffffu, sum1, 2);
        lr0 = lr0 * corr0 + sum0;
        lr1 = lr1 * corr1 + sum1;

        if (__any_sync(0xffffffffu, (corr0 < 1.0f) | (corr1 < 1.0f))) {
#pragma unroll
            for (int nf = 0; nf < 16; nf++) {
                oacc[nf][0] *= corr0; oacc[nf][1] *= corr0;
                oacc[nf][2] *= corr1; oacc[nf][3] *= corr1;
            }
        }
#pragma unroll
        for (int kc = 0; kc < 4; kc++) {
            pp[kc][0] = packh2(sacc[2 * kc][0],     sacc[2 * kc][1]);
            pp[kc][1] = packh2(sacc[2 * kc][2],     sacc[2 * kc][3]);
            pp[kc][2] = packh2(sacc[2 * kc + 1][0], sacc[2 * kc + 1][1]);
            pp[kc][3] = packh2(sacc[2 * kc + 1][2], sacc[2 * kc + 1][3]);
        }
    };

    auto computePV = [&](uint32_t vb) {
#pragma unroll
        for (int ks2 = 0; ks2 < 4; ks2++) {
            int vrow = ks2 * 16 + (lane & 15);
#pragma unroll
            for (int g = 0; g < 8; g++) {
                int chunk = g * 2 + (lane >> 4);
                uint32_t vh[4];
                ldsm_x4_t(vh, vb + sw256(vrow, chunk * 8));
                uint32_t vh0[2] = {vh[0], vh[1]}, vh1[2] = {vh[2], vh[3]};
                mma_f16(oacc[g * 2],     pp[ks2], vh0);
                mma_f16(oacc[g * 2 + 1], pp[ks2], vh1);
            }
        }
    };

    // ---- prologue compute: S(0) -> P(0) ----
    {
        float sacc[8][4];
        computeS(KB(0), sacc);
        softmax_pack(sacc, 0);
    }

    // ---- pipelined main loop: PV(j) + S(j+1) ----
    for (int j = 0; j < mt; j++) {
        const int bufc = j % 3;          // V(j)
        const int bufn = (j + 1) % 3;    // K(j+1)

        CP_WAIT0();
        __syncthreads();
        if (j + 2 <= mt) fillKV((j + 2) % 3, j + 2);

        float sacc[8][4];
        computeS(KB(bufn), sacc);
        computePV(VB(bufc));

        softmax_pack(sacc, j + 1);
    }

    // ---- final PV(mt) ----
    computePV(VB(mt % 3));

    // ---- epilogue: normalize + fp16 hi/lo store ----
    float inv0 = 1.0f / lr0;
    float inv1 = 1.0f / lr1;
    size_t row0 = rb + m0 + wid * 16 + (lane >> 2);
#pragma unroll
    for (int nf = 0; nf < 16; nf++) {
        int col = h * 128 + nf * 8 + (lane & 3) * 2;
        uint32_t hi, lo;
        pack2h(oacc[nf][0] * inv0, oacc[nf][1] * inv0, hi, lo);
        *(uint32_t*)(g_ath + row0 * 256 + col) = hi;
        *(uint32_t*)(g_atl + row0 * 256 + col) = lo;
        pack2h(oacc[nf][2] * inv1, oacc[nf][3] * inv1, hi, lo);
        *(uint32_t*)(g_ath + (row0 + 8) * 256 + col) = hi;
        *(uint32_t*)(g_atl + (row0 + 8) * 256 + col) = lo;
    }
}

// ---------------------------------------------------------------------------
extern "C" void kernel_launch(void* const* d_in, const int* in_sizes, int n_in,
                              void* d_out, int out_size)
{
    const float* x  = (const float*)d_in[0];
    const float* Wq = (const float*)d_in[1];
    const float* Wk = (const float*)d_in[2];
    const float* Wv = (const float*)d_in[3];
    const float* Wo = (const float*)d_in[4];

    const int BT = in_sizes[0] / DIM;  // 8192
    const int T  = T_SEQ;
    const int B  = BT / T;

    __half *xh, *xl, *q16, *k16, *v16, *ath, *atl, *w16, *wo16;
    cudaGetSymbolAddress((void**)&xh,   g_xh);
    cudaGetSymbolAddress((void**)&xl,   g_xl);
    cudaGetSymbolAddress((void**)&q16,  g_q16);
    cudaGetSymbolAddress((void**)&k16,  g_k16);
    cudaGetSymbolAddress((void**)&v16,  g_v16);
    cudaGetSymbolAddress((void**)&ath,  g_ath);
    cudaGetSymbolAddress((void**)&atl,  g_atl);
    cudaGetSymbolAddress((void**)&w16,  g_w16);
    cudaGetSymbolAddress((void**)&wo16, g_wo16);

    cudaFuncSetAttribute(gemm_f16_kernel,
                         cudaFuncAttributeMaxDynamicSharedMemorySize, GEMM_SMEM);
    cudaFuncSetAttribute(attn_reg_kernel,
                         cudaFuncAttributeMaxDynamicSharedMemorySize, ATT2_SMEM);

    // 1) split x + (concat/convert weights + trig)
    {
        int tot = BT * DIM / 4;
        split_x_kernel<<<(tot + 255) / 256, 256>>>(x);
        int wt = 512 * DIM / 4 + DIM * 256 / 4 + T_SEQ * 64;
        prep_kernel<<<(wt + 255) / 256, 256>>>(Wq, Wk, Wv, Wo);
    }

    // 2) fused QKV projection + rope + convert epilogue
    {
        dim3 grid(BT / 128, 512 / 128);
        gemm_f16_kernel<<<grid, 256, GEMM_SMEM>>>(xh, xl, w16, nullptr,
                                                  BT, 512, DIM, 512, 1);
    }

    // 3) flash attention (pipelined, MUFU softmax)
    {
        dim3 grid(T / 64, B * NKV);
        attn_reg_kernel<<<grid, 128, ATT2_SMEM>>>(q16, k16, v16, T);
    }

    // 4) output projection
    {
        dim3 grid(BT / 128, DIM / 128);
        gemm_f16_kernel<<<grid, 256, GEMM_SMEM>>>(ath, atl, wo16,
                                                  (float*)d_out, BT, DIM, 256,
                                                  DIM, 0);
    }
}